// round 1
// baseline (speedup 1.0000x reference)
#include <cuda_runtime.h>
#include <cuda_bf16.h>
#include <cstdio>

// Problem constants
#define NB   16
#define TT   512
#define VV   10000
#define DIN  2048
#define DD   1024
#define HH   16
#define LL   4
#define FFD  2048
#define DHD  64
#define ROWS (NB*TT)          // 8192
#define NEGF (-1e8f)

// ---------------- device scratch (no allocations allowed) ----------------
__device__ float g_x[ROWS * DD];       // running activations
__device__ float g_q[ROWS * DD];
__device__ float g_k[ROWS * DD];
__device__ float g_v[ROWS * DD];
__device__ float g_t[ROWS * DD];       // temp (proj outputs)
__device__ float g_attn[ROWS * DD];    // attention output (quirk layout = natural [n][h][s][dh])
__device__ float g_h[ROWS * FFD];      // FF hidden
__device__ float g_fe[NB * DD];        // projected features
__device__ float g_fev[NB * DD];       // fe @ Wv
__device__ float g_ztile[NB * 16 * DD];// tiled rows for cross out-proj
__device__ float g_z[NB * 16 * DD];    // cross-attn contribution (16 distinct rows per n)

// ---------------- SGEMM: C = A(MxK) * B(KxN) [+bias] [ReLU] -------------
// 128x128 block tile, BK=8, 256 threads, 8x8 per-thread microtile.
#define BM 128
#define BN 128
#define BK 8
#define TM 8
#define TN 8

template<bool RELU, bool BIAS>
__global__ void sgemm(const float* __restrict__ A, const float* __restrict__ B,
                      const float* __restrict__ bias, float* __restrict__ C,
                      int M, int Nn, int K)
{
    __shared__ float As[BK][BM];
    __shared__ float Bs[BK][BN];
    const int tid = threadIdx.x;
    const int row0 = blockIdx.y * BM;
    const int col0 = blockIdx.x * BN;
    const int tx = tid % 16;   // 16x16 thread grid
    const int ty = tid / 16;

    float acc[TM][TN];
#pragma unroll
    for (int i = 0; i < TM; i++)
#pragma unroll
        for (int j = 0; j < TN; j++) acc[i][j] = 0.f;

    const int aRow = tid >> 1;           // 0..127
    const int aCol = (tid & 1) * 4;      // 0 or 4
    const int bRow = tid >> 5;           // 0..7
    const int bCol = (tid & 31) * 4;     // 0..124

    for (int k0 = 0; k0 < K; k0 += BK) {
        int gr = row0 + aRow;
        float4 av = make_float4(0.f, 0.f, 0.f, 0.f);
        if (gr < M) av = *(const float4*)(A + (size_t)gr * K + k0 + aCol);
        As[aCol + 0][aRow] = av.x;
        As[aCol + 1][aRow] = av.y;
        As[aCol + 2][aRow] = av.z;
        As[aCol + 3][aRow] = av.w;

        int gc = col0 + bCol;
        float4 bv = make_float4(0.f, 0.f, 0.f, 0.f);
        if (gc < Nn) bv = *(const float4*)(B + (size_t)(k0 + bRow) * Nn + gc);
        *(float4*)&Bs[bRow][bCol] = bv;
        __syncthreads();

#pragma unroll
        for (int kk = 0; kk < BK; kk++) {
            float ar[TM], br[TN];
#pragma unroll
            for (int i = 0; i < TM; i++) ar[i] = As[kk][ty * TM + i];
#pragma unroll
            for (int j = 0; j < TN; j++) br[j] = Bs[kk][tx * TN + j];
#pragma unroll
            for (int i = 0; i < TM; i++)
#pragma unroll
                for (int j = 0; j < TN; j++)
                    acc[i][j] = fmaf(ar[i], br[j], acc[i][j]);
        }
        __syncthreads();
    }

#pragma unroll
    for (int i = 0; i < TM; i++) {
        int r = row0 + ty * TM + i;
        if (r >= M) continue;
#pragma unroll
        for (int j = 0; j < TN; j++) {
            int c = col0 + tx * TN + j;
            if (c >= Nn) continue;
            float v = acc[i][j];
            if (BIAS) v += bias[c];
            if (RELU) v = fmaxf(v, 0.f);
            C[(size_t)r * Nn + c] = v;
        }
    }
}

// ---------------- embedding: x = cap_emb[captions] + pos_emb ------------
__global__ void embed_kernel(const int* __restrict__ cap, const float* __restrict__ emb,
                             const float* __restrict__ pos, float* __restrict__ X)
{
    int r = blockIdx.x;            // n*512 + t
    int t = r & (TT - 1);
    int c = cap[r];
    int d = threadIdx.x * 4;       // 256 threads * 4 = 1024
    float4 e = *(const float4*)(emb + (size_t)c * DD + d);
    float4 p = *(const float4*)(pos + (size_t)t * DD + d);
    e.x += p.x; e.y += p.y; e.z += p.z; e.w += p.w;
    *(float4*)(X + (size_t)r * DD + d) = e;
}

// ---------------- causal self-attention, one block per (n,h,s) ---------
__global__ void attn_kernel(const float* __restrict__ Q, const float* __restrict__ Km,
                            const float* __restrict__ Vm, float* __restrict__ O)
{
    const int idx = blockIdx.x;
    const int s = idx & (TT - 1);
    const int h = (idx >> 9) & (HH - 1);
    const int n = idx >> 13;
    const int tid = threadIdx.x;          // 128 threads

    __shared__ float qs[DHD];
    __shared__ float p[TT];
    __shared__ float red[128];
    __shared__ float ysh[DHD];

    const float* qrow = Q + ((size_t)(n * TT + s)) * DD + h * DHD;
    if (tid < DHD) qs[tid] = qrow[tid];
    __syncthreads();

    float sc[4];
    float lmax = -1e30f;
#pragma unroll
    for (int r = 0; r < 4; r++) {
        int j = tid + r * 128;
        float v = NEGF;
        if (j <= s) {
            const float* krow = Km + ((size_t)(n * TT + j)) * DD + h * DHD;
            float acc = 0.f;
#pragma unroll
            for (int d = 0; d < DHD; d++) acc = fmaf(qs[d], krow[d], acc);
            v = acc * 0.125f;   // 1/sqrt(64)
        }
        sc[r] = v;
        lmax = fmaxf(lmax, v);
    }
    red[tid] = lmax; __syncthreads();
    for (int st = 64; st > 0; st >>= 1) {
        if (tid < st) red[tid] = fmaxf(red[tid], red[tid + st]);
        __syncthreads();
    }
    const float mx = red[0];
    __syncthreads();

    float lsum = 0.f;
#pragma unroll
    for (int r = 0; r < 4; r++) {
        int j = tid + r * 128;
        float e = (j <= s) ? __expf(sc[r] - mx) : 0.f;
        p[j] = e;
        lsum += e;
    }
    red[tid] = lsum; __syncthreads();
    for (int st = 64; st > 0; st >>= 1) {
        if (tid < st) red[tid] += red[tid + st];
        __syncthreads();
    }
    const float inv = 1.f / red[0];
    __syncthreads();

    // weighted sum over values: 128 threads = 64 dims x 2 j-partitions
    const int dh = tid & 63;
    const int part = tid >> 6;
    const int jend = s + 1;
    const int half = (jend + 1) >> 1;
    const int j0 = part ? half : 0;
    const int j1 = part ? jend : half;
    float acc = 0.f;
    const float* vbase = Vm + ((size_t)(n * TT)) * DD + h * DHD + dh;
    for (int j = j0; j < j1; j++)
        acc = fmaf(p[j], vbase[(size_t)j * DD], acc);
    if (part == 0) ysh[dh] = acc;
    __syncthreads();
    if (part == 1) ysh[dh] += acc;
    __syncthreads();
    if (tid < DHD)
        O[((size_t)((n * HH + h) * TT + s)) * DHD + tid] = ysh[tid] * inv;
}

// ---------------- residual + LayerNorm ----------------------------------
// mode 0: resid row = r   | mode 1: resid row = n*16 + (s>>5)  (cross-attn bcast)
__global__ void ln_kernel(const float* __restrict__ X, const float* __restrict__ Rsd,
                          const float* __restrict__ g, const float* __restrict__ b,
                          float* __restrict__ out, int mode)
{
    const int r = blockIdx.x;
    const int tid = threadIdx.x;    // 256
    size_t rr;
    if (mode == 0) rr = (size_t)r;
    else {
        int n = r >> 9;
        int s = r & (TT - 1);
        rr = (size_t)(n * 16 + (s >> 5));
    }
    const float* xr = X + (size_t)r * DD;
    const float* dr = Rsd + rr * DD;
    const int d = tid * 4;
    float4 xv = *(const float4*)(xr + d);
    float4 dv = *(const float4*)(dr + d);
    float v0 = xv.x + dv.x, v1 = xv.y + dv.y, v2 = xv.z + dv.z, v3 = xv.w + dv.w;

    __shared__ float s1[256], s2[256];
    s1[tid] = v0 + v1 + v2 + v3;
    s2[tid] = v0 * v0 + v1 * v1 + v2 * v2 + v3 * v3;
    __syncthreads();
    for (int st = 128; st > 0; st >>= 1) {
        if (tid < st) { s1[tid] += s1[tid + st]; s2[tid] += s2[tid + st]; }
        __syncthreads();
    }
    const float mean = s1[0] * (1.f / DD);
    const float var = s2[0] * (1.f / DD) - mean * mean;
    const float rstd = rsqrtf(var + 1e-5f);

    float4 ov;
    ov.x = g[d + 0] * (v0 - mean) * rstd + b[d + 0];
    ov.y = g[d + 1] * (v1 - mean) * rstd + b[d + 1];
    ov.z = g[d + 2] * (v2 - mean) * rstd + b[d + 2];
    ov.w = g[d + 3] * (v3 - mean) * rstd + b[d + 3];
    *(float4*)(out + (size_t)r * DD + d) = ov;
}

// ------------- build tiled rows for cross-attn out-projection ----------
// A[n*16+g][d] = fev[n][g*64 + (d & 63)]
__global__ void tilefe_kernel(const float* __restrict__ fev, float* __restrict__ A)
{
    const int r = blockIdx.x;        // 0..255
    const int n = r >> 4;
    const int g = r & 15;
    const int d = threadIdx.x * 4;   // 256 threads
    const float* src = fev + (size_t)n * DD + g * 64;
    float4 v = *(const float4*)(src + (d & 63));
    *(float4*)(A + (size_t)r * DD + d) = v;
}

// ---------------- launch --------------------------------------------------
extern "C" void kernel_launch(void* const* d_in, const int* in_sizes, int n_in,
                              void* d_out, int out_size)
{
    const float* features = (const float*)d_in[0];
    const int*   captions = (const int*)d_in[1];
    const float* feat_W   = (const float*)d_in[2];
    const float* feat_b   = (const float*)d_in[3];
    const float* cap_emb  = (const float*)d_in[4];
    const float* pos_emb  = (const float*)d_in[5];
    const float* sa_Wq = (const float*)d_in[6];
    const float* sa_Wk = (const float*)d_in[7];
    const float* sa_Wv = (const float*)d_in[8];
    const float* sa_Wo = (const float*)d_in[9];
    const float* sa_bo = (const float*)d_in[10];
    const float* sa_g  = (const float*)d_in[11];
    const float* sa_b  = (const float*)d_in[12];
    const float* ca_Wv = (const float*)d_in[15];
    const float* ca_Wo = (const float*)d_in[16];
    const float* ca_bo = (const float*)d_in[17];
    const float* ca_g  = (const float*)d_in[18];
    const float* ca_b  = (const float*)d_in[19];
    const float* ff_W1 = (const float*)d_in[20];
    const float* ff_b1 = (const float*)d_in[21];
    const float* ff_W2 = (const float*)d_in[22];
    const float* ff_b2 = (const float*)d_in[23];
    const float* ff_g  = (const float*)d_in[24];
    const float* ff_b  = (const float*)d_in[25];
    const float* score_W = (const float*)d_in[26];
    const float* score_b = (const float*)d_in[27];
    float* out = (float*)d_out;

    float *px, *pq, *pk, *pv, *pt, *pattn, *ph, *pfe, *pfev, *pzt, *pz;
    cudaGetSymbolAddress((void**)&px,    g_x);
    cudaGetSymbolAddress((void**)&pq,    g_q);
    cudaGetSymbolAddress((void**)&pk,    g_k);
    cudaGetSymbolAddress((void**)&pv,    g_v);
    cudaGetSymbolAddress((void**)&pt,    g_t);
    cudaGetSymbolAddress((void**)&pattn, g_attn);
    cudaGetSymbolAddress((void**)&ph,    g_h);
    cudaGetSymbolAddress((void**)&pfe,   g_fe);
    cudaGetSymbolAddress((void**)&pfev,  g_fev);
    cudaGetSymbolAddress((void**)&pzt,   g_ztile);
    cudaGetSymbolAddress((void**)&pz,    g_z);

    // features -> fe   (16 x 2048) @ (2048 x 1024) + feat_b
    sgemm<false, true><<<dim3(DD / BN, 1), 256>>>(features, feat_W, feat_b, pfe, NB, DD, DIN);

    // embedding
    embed_kernel<<<ROWS, 256>>>(captions, cap_emb, pos_emb, px);

    const dim3 gP(DD / BN, ROWS / BM);       // 8 x 64   (D-wide projections)
    const dim3 gF(FFD / BN, ROWS / BM);      // 16 x 64  (FF1)

    for (int i = 0; i < LL; i++) {
        const float* Wq = sa_Wq + (size_t)i * DD * DD;
        const float* Wk = sa_Wk + (size_t)i * DD * DD;
        const float* Wv = sa_Wv + (size_t)i * DD * DD;
        const float* Wo = sa_Wo + (size_t)i * DD * DD;

        // --- self attention ---
        sgemm<false, false><<<gP, 256>>>(px, Wq, nullptr, pq, ROWS, DD, DD);
        sgemm<false, false><<<gP, 256>>>(px, Wk, nullptr, pk, ROWS, DD, DD);
        sgemm<false, false><<<gP, 256>>>(px, Wv, nullptr, pv, ROWS, DD, DD);
        attn_kernel<<<NB * HH * TT, 128>>>(pq, pk, pv, pattn);
        sgemm<false, true><<<gP, 256>>>(pattn, Wo, sa_bo + (size_t)i * DD, pt, ROWS, DD, DD);
        ln_kernel<<<ROWS, 256>>>(px, pt, sa_g + (size_t)i * DD, sa_b + (size_t)i * DD, px, 0);

        // --- cross attention (T_kv = 1 => softmax == 1; Q/K projections dead) ---
        sgemm<false, false><<<dim3(DD / BN, 1), 256>>>(pfe, ca_Wv + (size_t)i * DD * DD, nullptr, pfev, NB, DD, DD);
        tilefe_kernel<<<NB * 16, 256>>>(pfev, pzt);
        sgemm<false, true><<<dim3(DD / BN, 2), 256>>>(pzt, ca_Wo + (size_t)i * DD * DD,
                                                      ca_bo + (size_t)i * DD, pz, NB * 16, DD, DD);
        ln_kernel<<<ROWS, 256>>>(px, pz, ca_g + (size_t)i * DD, ca_b + (size_t)i * DD, px, 1);

        // --- feed forward ---
        sgemm<true, true><<<gF, 256>>>(px, ff_W1 + (size_t)i * DD * FFD,
                                       ff_b1 + (size_t)i * FFD, ph, ROWS, FFD, DD);
        sgemm<false, true><<<gP, 256>>>(ph, ff_W2 + (size_t)i * FFD * DD,
                                        ff_b2 + (size_t)i * DD, pt, ROWS, DD, FFD);
        ln_kernel<<<ROWS, 256>>>(px, pt, ff_g + (size_t)i * DD, ff_b + (size_t)i * DD, px, 0);
    }

    // final vocab projection (N = 10000, bounds-checked tiles)
    sgemm<false, true><<<dim3((VV + BN - 1) / BN, ROWS / BM), 256>>>(px, score_W, score_b, out, ROWS, VV, DD);
}

// round 2
// speedup vs baseline: 2.4605x; 2.4605x over previous
#include <cuda_runtime.h>
#include <cuda_bf16.h>
#include <cstdio>

// Problem constants
#define NB   16
#define TT   512
#define VV   10000
#define DIN  2048
#define DD   1024
#define HH   16
#define LL   4
#define FFD  2048
#define DHD  64
#define ROWS (NB*TT)          // 8192
#define NEGF (-1e8f)

// ---------------- device scratch (no allocations allowed) ----------------
__device__ float g_x[ROWS * DD];       // running activations
__device__ float g_q[ROWS * DD];
__device__ float g_k[ROWS * DD];
__device__ float g_v[ROWS * DD];
__device__ float g_t[ROWS * DD];       // temp (proj outputs)
__device__ float g_attn[ROWS * DD];    // attention output (quirk layout = natural [n][h][s][dh])
__device__ float g_h[ROWS * FFD];      // FF hidden
__device__ float g_fe[NB * DD];        // projected features
__device__ float g_fev[LL * NB * DD];  // fe @ Wv  (all layers)
__device__ float g_ztile[LL * NB * 16 * DD]; // tiled rows for cross out-proj (all layers)
__device__ float g_z[LL * NB * 16 * DD];     // cross-attn contribution (all layers)

// ---------------- SGEMM: C = A(MxK) * B(KxN) [+bias] [ReLU] -------------
#define BM 128
#define BN 128
#define BK 8
#define TM 8
#define TN 8

template<bool RELU, bool BIAS>
__global__ void sgemm(const float* __restrict__ A, const float* __restrict__ B,
                      const float* __restrict__ bias, float* __restrict__ C,
                      int M, int Nn, int K)
{
    __shared__ float As[BK][BM];
    __shared__ float Bs[BK][BN];
    const int tid = threadIdx.x;
    const int row0 = blockIdx.y * BM;
    const int col0 = blockIdx.x * BN;
    const int tx = tid % 16;
    const int ty = tid / 16;

    float acc[TM][TN];
#pragma unroll
    for (int i = 0; i < TM; i++)
#pragma unroll
        for (int j = 0; j < TN; j++) acc[i][j] = 0.f;

    const int aRow = tid >> 1;
    const int aCol = (tid & 1) * 4;
    const int bRow = tid >> 5;
    const int bCol = (tid & 31) * 4;

    for (int k0 = 0; k0 < K; k0 += BK) {
        int gr = row0 + aRow;
        float4 av = make_float4(0.f, 0.f, 0.f, 0.f);
        if (gr < M) av = *(const float4*)(A + (size_t)gr * K + k0 + aCol);
        As[aCol + 0][aRow] = av.x;
        As[aCol + 1][aRow] = av.y;
        As[aCol + 2][aRow] = av.z;
        As[aCol + 3][aRow] = av.w;

        int gc = col0 + bCol;
        float4 bv = make_float4(0.f, 0.f, 0.f, 0.f);
        if (gc < Nn) bv = *(const float4*)(B + (size_t)(k0 + bRow) * Nn + gc);
        *(float4*)&Bs[bRow][bCol] = bv;
        __syncthreads();

#pragma unroll
        for (int kk = 0; kk < BK; kk++) {
            float ar[TM], br[TN];
#pragma unroll
            for (int i = 0; i < TM; i++) ar[i] = As[kk][ty * TM + i];
#pragma unroll
            for (int j = 0; j < TN; j++) br[j] = Bs[kk][tx * TN + j];
#pragma unroll
            for (int i = 0; i < TM; i++)
#pragma unroll
                for (int j = 0; j < TN; j++)
                    acc[i][j] = fmaf(ar[i], br[j], acc[i][j]);
        }
        __syncthreads();
    }

#pragma unroll
    for (int i = 0; i < TM; i++) {
        int r = row0 + ty * TM + i;
        if (r >= M) continue;
#pragma unroll
        for (int j = 0; j < TN; j++) {
            int c = col0 + tx * TN + j;
            if (c >= Nn) continue;
            float v = acc[i][j];
            if (BIAS) v += bias[c];
            if (RELU) v = fmaxf(v, 0.f);
            C[(size_t)r * Nn + c] = v;
        }
    }
}

// Batched (blockIdx.z) variant: per-z offsets on A,B,bias,C.
template<bool BIAS>
__global__ void sgemm_bz(const float* __restrict__ A0, const float* __restrict__ B0,
                         const float* __restrict__ bias0, float* __restrict__ C0,
                         int M, int Nn, int K,
                         size_t sA, size_t sB, size_t sBias, size_t sC)
{
    const int z = blockIdx.z;
    const float* A = A0 + sA * z;
    const float* B = B0 + sB * z;
    const float* bias = BIAS ? (bias0 + sBias * z) : nullptr;
    float* C = C0 + sC * z;

    __shared__ float As[BK][BM];
    __shared__ float Bs[BK][BN];
    const int tid = threadIdx.x;
    const int row0 = blockIdx.y * BM;
    const int col0 = blockIdx.x * BN;
    const int tx = tid % 16;
    const int ty = tid / 16;

    float acc[TM][TN];
#pragma unroll
    for (int i = 0; i < TM; i++)
#pragma unroll
        for (int j = 0; j < TN; j++) acc[i][j] = 0.f;

    const int aRow = tid >> 1;
    const int aCol = (tid & 1) * 4;
    const int bRow = tid >> 5;
    const int bCol = (tid & 31) * 4;

    for (int k0 = 0; k0 < K; k0 += BK) {
        int gr = row0 + aRow;
        float4 av = make_float4(0.f, 0.f, 0.f, 0.f);
        if (gr < M) av = *(const float4*)(A + (size_t)gr * K + k0 + aCol);
        As[aCol + 0][aRow] = av.x;
        As[aCol + 1][aRow] = av.y;
        As[aCol + 2][aRow] = av.z;
        As[aCol + 3][aRow] = av.w;

        int gc = col0 + bCol;
        float4 bv = make_float4(0.f, 0.f, 0.f, 0.f);
        if (gc < Nn) bv = *(const float4*)(B + (size_t)(k0 + bRow) * Nn + gc);
        *(float4*)&Bs[bRow][bCol] = bv;
        __syncthreads();

#pragma unroll
        for (int kk = 0; kk < BK; kk++) {
            float ar[TM], br[TN];
#pragma unroll
            for (int i = 0; i < TM; i++) ar[i] = As[kk][ty * TM + i];
#pragma unroll
            for (int j = 0; j < TN; j++) br[j] = Bs[kk][tx * TN + j];
#pragma unroll
            for (int i = 0; i < TM; i++)
#pragma unroll
                for (int j = 0; j < TN; j++)
                    acc[i][j] = fmaf(ar[i], br[j], acc[i][j]);
        }
        __syncthreads();
    }

#pragma unroll
    for (int i = 0; i < TM; i++) {
        int r = row0 + ty * TM + i;
        if (r >= M) continue;
#pragma unroll
        for (int j = 0; j < TN; j++) {
            int c = col0 + tx * TN + j;
            if (c >= Nn) continue;
            float v = acc[i][j];
            if (BIAS) v += bias[c];
            C[(size_t)r * Nn + c] = v;
        }
    }
}

// ---------------- embedding ------------
__global__ void embed_kernel(const int* __restrict__ cap, const float* __restrict__ emb,
                             const float* __restrict__ pos, float* __restrict__ X)
{
    int r = blockIdx.x;
    int t = r & (TT - 1);
    int c = cap[r];
    int d = threadIdx.x * 4;
    float4 e = *(const float4*)(emb + (size_t)c * DD + d);
    float4 p = *(const float4*)(pos + (size_t)t * DD + d);
    e.x += p.x; e.y += p.y; e.z += p.z; e.w += p.w;
    *(float4*)(X + (size_t)r * DD + d) = e;
}

// ---------------- flash attention -----------------------------------------
// block = 256 threads, per (n, h, q-tile of 128). Online softmax, causal.
#define QS_STRIDE 132
#define KS_STRIDE 68
#define PS_STRIDE 132
#define FA_SMEM ((64*QS_STRIDE + 64*KS_STRIDE + 64*64 + 64*PS_STRIDE) * sizeof(float))

__global__ __launch_bounds__(256) void flash_attn(
    const float* __restrict__ Q, const float* __restrict__ K,
    const float* __restrict__ V, float* __restrict__ O)
{
    extern __shared__ float sh[];
    float* Qs = sh;                       // [64][QS_STRIDE]  d-major
    float* Ks = Qs + 64 * QS_STRIDE;      // [64][KS_STRIDE]  d-major
    float* Vs = Ks + 64 * KS_STRIDE;      // [64][64]         k-major
    float* Ps = Vs + 64 * 64;             // [64][PS_STRIDE]  k-major

    const int bid = blockIdx.x;
    const int qt = bid & 3;
    const int h  = (bid >> 2) & 15;
    const int n  = bid >> 6;
    const int q0 = qt * 128;

    const int tid = threadIdx.x;
    const int tx = tid & 15;
    const int ty = tid >> 4;

    // load Q tile transposed: Qs[d][r]
    {
        const int d4 = (tid & 15) * 4;
        const int r0 = tid >> 4;
#pragma unroll
        for (int rr = 0; rr < 8; rr++) {
            const int r = r0 + rr * 16;
            const float4 v = *(const float4*)(Q + ((size_t)(n * TT + q0 + r)) * DD + h * DHD + d4);
            Qs[(d4 + 0) * QS_STRIDE + r] = v.x;
            Qs[(d4 + 1) * QS_STRIDE + r] = v.y;
            Qs[(d4 + 2) * QS_STRIDE + r] = v.z;
            Qs[(d4 + 3) * QS_STRIDE + r] = v.w;
        }
    }

    float o[8][4];
    float m[8], l[8];
#pragma unroll
    for (int i = 0; i < 8; i++) {
        m[i] = -1e30f; l[i] = 0.f;
#pragma unroll
        for (int j = 0; j < 4; j++) o[i][j] = 0.f;
    }

    const int ntiles = (q0 + 128) / 64;    // 2*(qt+1)
    for (int t = 0; t < ntiles; t++) {
        const int j0 = t * 64;
        __syncthreads();   // previous iter's Ps/Vs reads complete
        // load K transposed, V natural
        {
            const int d4 = (tid & 15) * 4;
            const int c0 = tid >> 4;
#pragma unroll
            for (int cc = 0; cc < 4; cc++) {
                const int c = c0 + cc * 16;
                const size_t grow = ((size_t)(n * TT + j0 + c)) * DD + h * DHD + d4;
                const float4 kv = *(const float4*)(K + grow);
                Ks[(d4 + 0) * KS_STRIDE + c] = kv.x;
                Ks[(d4 + 1) * KS_STRIDE + c] = kv.y;
                Ks[(d4 + 2) * KS_STRIDE + c] = kv.z;
                Ks[(d4 + 3) * KS_STRIDE + c] = kv.w;
                const float4 vv = *(const float4*)(V + grow);
                *(float4*)(Vs + c * 64 + d4) = vv;
            }
        }
        __syncthreads();

        // S = Q @ K^T   (microtile 8 rows x 4 cols)
        float s[8][4];
#pragma unroll
        for (int i = 0; i < 8; i++)
#pragma unroll
            for (int j = 0; j < 4; j++) s[i][j] = 0.f;
#pragma unroll 4
        for (int kk = 0; kk < 64; kk++) {
            float ar[8], br[4];
            *(float4*)ar       = *(const float4*)(Qs + kk * QS_STRIDE + ty * 8);
            *(float4*)(ar + 4) = *(const float4*)(Qs + kk * QS_STRIDE + ty * 8 + 4);
            *(float4*)br       = *(const float4*)(Ks + kk * KS_STRIDE + tx * 4);
#pragma unroll
            for (int i = 0; i < 8; i++)
#pragma unroll
                for (int j = 0; j < 4; j++) s[i][j] = fmaf(ar[i], br[j], s[i][j]);
        }

        // scale + causal mask + tile row max
        float tmax[8];
#pragma unroll
        for (int i = 0; i < 8; i++) {
            const int q = q0 + ty * 8 + i;
            tmax[i] = -1e30f;
#pragma unroll
            for (int j = 0; j < 4; j++) {
                const int kidx = j0 + tx * 4 + j;
                float v = (kidx <= q) ? s[i][j] * 0.125f : -1e30f;
                s[i][j] = v;
                tmax[i] = fmaxf(tmax[i], v);
            }
        }
#pragma unroll
        for (int st = 1; st < 16; st <<= 1)
#pragma unroll
            for (int i = 0; i < 8; i++)
                tmax[i] = fmaxf(tmax[i], __shfl_xor_sync(0xffffffffu, tmax[i], st));

        // online softmax update
        float psum[8];
#pragma unroll
        for (int i = 0; i < 8; i++) {
            const float mn = fmaxf(m[i], tmax[i]);
            const float sc = __expf(m[i] - mn);
            m[i] = mn;
            l[i] *= sc;
#pragma unroll
            for (int j = 0; j < 4; j++) o[i][j] *= sc;
            float ps = 0.f;
#pragma unroll
            for (int j = 0; j < 4; j++) {
                const float p = __expf(s[i][j] - mn);
                s[i][j] = p;
                ps += p;
            }
            psum[i] = ps;
        }
#pragma unroll
        for (int st = 1; st < 16; st <<= 1)
#pragma unroll
            for (int i = 0; i < 8; i++)
                psum[i] += __shfl_xor_sync(0xffffffffu, psum[i], st);
#pragma unroll
        for (int i = 0; i < 8; i++) l[i] += psum[i];

        // stage P into shared (k-major)
#pragma unroll
        for (int j = 0; j < 4; j++) {
            const int k = tx * 4 + j;
#pragma unroll
            for (int i = 0; i < 8; i++)
                Ps[k * PS_STRIDE + ty * 8 + i] = s[i][j];
        }
        __syncthreads();

        // O += P @ V
#pragma unroll 4
        for (int k = 0; k < 64; k++) {
            float ar[8], bv[4];
            *(float4*)ar       = *(const float4*)(Ps + k * PS_STRIDE + ty * 8);
            *(float4*)(ar + 4) = *(const float4*)(Ps + k * PS_STRIDE + ty * 8 + 4);
            *(float4*)bv       = *(const float4*)(Vs + k * 64 + tx * 4);
#pragma unroll
            for (int i = 0; i < 8; i++)
#pragma unroll
                for (int j = 0; j < 4; j++) o[i][j] = fmaf(ar[i], bv[j], o[i][j]);
        }
    }

    // write output in quirk layout [(n*H+h)*T + q][dh]
#pragma unroll
    for (int i = 0; i < 8; i++) {
        const int q = q0 + ty * 8 + i;
        const float inv = 1.f / l[i];
        float4 ov;
        ov.x = o[i][0] * inv; ov.y = o[i][1] * inv;
        ov.z = o[i][2] * inv; ov.w = o[i][3] * inv;
        *(float4*)(O + ((size_t)((n * HH + h) * TT + q)) * DHD + tx * 4) = ov;
    }
}

// ---------------- residual + LayerNorm ----------------------------------
__global__ void ln_kernel(const float* __restrict__ X, const float* __restrict__ Rsd,
                          const float* __restrict__ g, const float* __restrict__ b,
                          float* __restrict__ out, int mode)
{
    const int r = blockIdx.x;
    const int tid = threadIdx.x;
    size_t rr;
    if (mode == 0) rr = (size_t)r;
    else {
        int n = r >> 9;
        int s = r & (TT - 1);
        rr = (size_t)(n * 16 + (s >> 5));
    }
    const float* xr = X + (size_t)r * DD;
    const float* dr = Rsd + rr * DD;
    const int d = tid * 4;
    float4 xv = *(const float4*)(xr + d);
    float4 dv = *(const float4*)(dr + d);
    float v0 = xv.x + dv.x, v1 = xv.y + dv.y, v2 = xv.z + dv.z, v3 = xv.w + dv.w;

    __shared__ float s1[256], s2[256];
    s1[tid] = v0 + v1 + v2 + v3;
    s2[tid] = v0 * v0 + v1 * v1 + v2 * v2 + v3 * v3;
    __syncthreads();
    for (int st = 128; st > 0; st >>= 1) {
        if (tid < st) { s1[tid] += s1[tid + st]; s2[tid] += s2[tid + st]; }
        __syncthreads();
    }
    const float mean = s1[0] * (1.f / DD);
    const float var = s2[0] * (1.f / DD) - mean * mean;
    const float rstd = rsqrtf(var + 1e-5f);

    float4 ov;
    ov.x = g[d + 0] * (v0 - mean) * rstd + b[d + 0];
    ov.y = g[d + 1] * (v1 - mean) * rstd + b[d + 1];
    ov.z = g[d + 2] * (v2 - mean) * rstd + b[d + 2];
    ov.w = g[d + 3] * (v3 - mean) * rstd + b[d + 3];
    *(float4*)(out + (size_t)r * DD + d) = ov;
}

// ------------- build tiled rows for cross-attn out-projection (batched) --
// A[z][n*16+g][d] = fev[z][n][g*64 + (d & 63)]
__global__ void tilefe_kernel(const float* __restrict__ fev, float* __restrict__ A)
{
    const int bx = blockIdx.x;       // z*256 + local row
    const int z = bx >> 8;
    const int rl = bx & 255;
    const int n = rl >> 4;
    const int g = rl & 15;
    const int d = threadIdx.x * 4;
    const float* src = fev + (size_t)z * NB * DD + (size_t)n * DD + g * 64;
    float4 v = *(const float4*)(src + (d & 63));
    *(float4*)(A + (size_t)z * NB * 16 * DD + (size_t)rl * DD + d) = v;
}

// ---------------- launch --------------------------------------------------
extern "C" void kernel_launch(void* const* d_in, const int* in_sizes, int n_in,
                              void* d_out, int out_size)
{
    const float* features = (const float*)d_in[0];
    const int*   captions = (const int*)d_in[1];
    const float* feat_W   = (const float*)d_in[2];
    const float* feat_b   = (const float*)d_in[3];
    const float* cap_emb  = (const float*)d_in[4];
    const float* pos_emb  = (const float*)d_in[5];
    const float* sa_Wq = (const float*)d_in[6];
    const float* sa_Wk = (const float*)d_in[7];
    const float* sa_Wv = (const float*)d_in[8];
    const float* sa_Wo = (const float*)d_in[9];
    const float* sa_bo = (const float*)d_in[10];
    const float* sa_g  = (const float*)d_in[11];
    const float* sa_b  = (const float*)d_in[12];
    const float* ca_Wv = (const float*)d_in[15];
    const float* ca_Wo = (const float*)d_in[16];
    const float* ca_bo = (const float*)d_in[17];
    const float* ca_g  = (const float*)d_in[18];
    const float* ca_b  = (const float*)d_in[19];
    const float* ff_W1 = (const float*)d_in[20];
    const float* ff_b1 = (const float*)d_in[21];
    const float* ff_W2 = (const float*)d_in[22];
    const float* ff_b2 = (const float*)d_in[23];
    const float* ff_g  = (const float*)d_in[24];
    const float* ff_b  = (const float*)d_in[25];
    const float* score_W = (const float*)d_in[26];
    const float* score_b = (const float*)d_in[27];
    float* out = (float*)d_out;

    float *px, *pq, *pk, *pv, *pt, *pattn, *ph, *pfe, *pfev, *pzt, *pz;
    cudaGetSymbolAddress((void**)&px,    g_x);
    cudaGetSymbolAddress((void**)&pq,    g_q);
    cudaGetSymbolAddress((void**)&pk,    g_k);
    cudaGetSymbolAddress((void**)&pv,    g_v);
    cudaGetSymbolAddress((void**)&pt,    g_t);
    cudaGetSymbolAddress((void**)&pattn, g_attn);
    cudaGetSymbolAddress((void**)&ph,    g_h);
    cudaGetSymbolAddress((void**)&pfe,   g_fe);
    cudaGetSymbolAddress((void**)&pfev,  g_fev);
    cudaGetSymbolAddress((void**)&pzt,   g_ztile);
    cudaGetSymbolAddress((void**)&pz,    g_z);

    static bool attr_set = false;
    if (!attr_set) {
        cudaFuncSetAttribute(flash_attn, cudaFuncAttributeMaxDynamicSharedMemorySize, FA_SMEM);
        attr_set = true;
    }

    // features -> fe
    sgemm<false, true><<<dim3(DD / BN, 1), 256>>>(features, feat_W, feat_b, pfe, NB, DD, DIN);

    // embedding
    embed_kernel<<<ROWS, 256>>>(captions, cap_emb, pos_emb, px);

    // ---- cross-attention contributions for ALL layers (independent of x) ----
    // fev[z] = fe @ ca_Wv[z]
    sgemm_bz<false><<<dim3(DD / BN, 1, LL), 256>>>(pfe, ca_Wv, nullptr, pfev,
                                                   NB, DD, DD,
                                                   0, (size_t)DD * DD, 0, (size_t)NB * DD);
    // tiled rows
    tilefe_kernel<<<LL * NB * 16, 256>>>(pfev, pzt);
    // z[z] = ztile[z] @ ca_Wo[z] + ca_bo[z]
    sgemm_bz<true><<<dim3(DD / BN, 2, LL), 256>>>(pzt, ca_Wo, ca_bo, pz,
                                                  NB * 16, DD, DD,
                                                  (size_t)NB * 16 * DD, (size_t)DD * DD,
                                                  DD, (size_t)NB * 16 * DD);

    const dim3 gP(DD / BN, ROWS / BM);
    const dim3 gF(FFD / BN, ROWS / BM);

    for (int i = 0; i < LL; i++) {
        const float* Wq = sa_Wq + (size_t)i * DD * DD;
        const float* Wk = sa_Wk + (size_t)i * DD * DD;
        const float* Wv = sa_Wv + (size_t)i * DD * DD;
        const float* Wo = sa_Wo + (size_t)i * DD * DD;

        // --- self attention ---
        sgemm<false, false><<<gP, 256>>>(px, Wq, nullptr, pq, ROWS, DD, DD);
        sgemm<false, false><<<gP, 256>>>(px, Wk, nullptr, pk, ROWS, DD, DD);
        sgemm<false, false><<<gP, 256>>>(px, Wv, nullptr, pv, ROWS, DD, DD);
        flash_attn<<<NB * HH * 4, 256, FA_SMEM>>>(pq, pk, pv, pattn);
        sgemm<false, true><<<gP, 256>>>(pattn, Wo, sa_bo + (size_t)i * DD, pt, ROWS, DD, DD);
        ln_kernel<<<ROWS, 256>>>(px, pt, sa_g + (size_t)i * DD, sa_b + (size_t)i * DD, px, 0);

        // --- cross attention (precomputed z) ---
        ln_kernel<<<ROWS, 256>>>(px, pz + (size_t)i * NB * 16 * DD,
                                 ca_g + (size_t)i * DD, ca_b + (size_t)i * DD, px, 1);

        // --- feed forward ---
        sgemm<true, true><<<gF, 256>>>(px, ff_W1 + (size_t)i * DD * FFD,
                                       ff_b1 + (size_t)i * FFD, ph, ROWS, FFD, DD);
        sgemm<false, true><<<gP, 256>>>(ph, ff_W2 + (size_t)i * FFD * DD,
                                        ff_b2 + (size_t)i * DD, pt, ROWS, DD, FFD);
        ln_kernel<<<ROWS, 256>>>(px, pt, ff_g + (size_t)i * DD, ff_b + (size_t)i * DD, px, 0);
    }

    // final vocab projection
    sgemm<false, true><<<dim3((VV + BN - 1) / BN, ROWS / BM), 256>>>(px, score_W, score_b, out, ROWS, VV, DD);
}

// round 3
// speedup vs baseline: 2.6242x; 1.0666x over previous
#include <cuda_runtime.h>
#include <cuda_bf16.h>
#include <cstdio>

// Problem constants
#define NB   16
#define TT   512
#define VV   10000
#define DIN  2048
#define DD   1024
#define HH   16
#define LL   4
#define FFD  2048
#define DHD  64
#define ROWS (NB*TT)          // 8192
#define NEGF (-1e8f)

// ---------------- device scratch ----------------
__device__ float g_x[ROWS * DD];
__device__ float g_q[ROWS * DD];
__device__ float g_k[ROWS * DD];
__device__ float g_v[ROWS * DD];
__device__ float g_t[ROWS * DD];
__device__ float g_attn[ROWS * DD];
__device__ float g_h[ROWS * FFD];
__device__ float g_fe[NB * DD];
__device__ float g_fev[LL * NB * DD];
__device__ float g_ztile[LL * NB * 16 * DD];
__device__ float g_z[LL * NB * 16 * DD];

// ======================= tf32 tensor-core GEMM ===========================
// C = A(MxK) * B(KxN) [+bias] [ReLU].  Requires M%128==0, K%8==0. N predicated.
// 256 threads = 8 warps (2x4), warp tile 64x32, mma m16n8k8 tf32.
__device__ __forceinline__ unsigned f2tf32(float x) {
    unsigned u;
    asm("cvt.rna.tf32.f32 %0, %1;" : "=r"(u) : "f"(x));
    return u;
}

template<bool RELU, bool BIAS>
__global__ __launch_bounds__(256) void tgemm(
    const float* __restrict__ A, const float* __restrict__ B,
    const float* __restrict__ bias, float* __restrict__ C,
    int M, int Nn, int K)
{
    // smem layout: per row of 8 tf32 values, word = ((k%4)^(row&3))*2 + k/4
    __shared__ unsigned As[2][128 * 8];
    __shared__ unsigned Bs[2][128 * 8];

    const int tid  = threadIdx.x;
    const int lane = tid & 31;
    const int warp = tid >> 5;
    const int row0 = blockIdx.y * 128;
    const int col0 = blockIdx.x * 128;
    const int wm = (warp >> 2) * 64;       // 0 or 64
    const int wn = (warp & 3) * 32;        // 0..96
    const int g  = lane >> 2;              // 0..7
    const int tq = lane & 3;               // 0..3

    // global load indexing
    const int arow = tid >> 1;             // 0..127
    const int ah   = (tid & 1) * 4;        // 0 or 4
    const int brow = tid >> 5;             // 0..7 (k within tile)
    const int bcol = lane * 4;             // 0..124

    const float* aptr = A + (size_t)(row0 + arow) * K + ah;
    const float* bptr = B + (size_t)brow * Nn + col0 + bcol;
    const bool bvalid = (col0 + bcol + 3) < Nn;

    float acc[4][4][4];
#pragma unroll
    for (int i = 0; i < 4; i++)
#pragma unroll
        for (int j = 0; j < 4; j++)
#pragma unroll
            for (int c = 0; c < 4; c++) acc[i][j][c] = 0.f;

    const int nk = K >> 3;

    // prologue: tile 0
    {
        float4 av = *(const float4*)aptr;
        float4 bv = make_float4(0.f, 0.f, 0.f, 0.f);
        if (bvalid) bv = *(const float4*)bptr;
        const int ac = arow & 3;
        const int hb = ah >> 2;
        unsigned* ar = &As[0][arow * 8];
        ar[((0 ^ ac) << 1) + hb] = f2tf32(av.x);
        ar[((1 ^ ac) << 1) + hb] = f2tf32(av.y);
        ar[((2 ^ ac) << 1) + hb] = f2tf32(av.z);
        ar[((3 ^ ac) << 1) + hb] = f2tf32(av.w);
        const int km = brow & 3, kh = brow >> 2;
        const float bb[4] = {bv.x, bv.y, bv.z, bv.w};
#pragma unroll
        for (int c = 0; c < 4; c++) {
            const int col = bcol + c;
            Bs[0][col * 8 + ((km ^ (col & 3)) << 1) + kh] = f2tf32(bb[c]);
        }
    }
    __syncthreads();

    for (int it = 0; it < nk; it++) {
        const int buf = it & 1;
        float4 av, bv;
        const bool more = (it + 1) < nk;
        if (more) {
            av = *(const float4*)(aptr + (it + 1) * 8);
            bv = make_float4(0.f, 0.f, 0.f, 0.f);
            if (bvalid) bv = *(const float4*)(bptr + (size_t)((it + 1) * 8) * Nn);
        }

        // fragments
        unsigned a[4][4], b[4][2];
#pragma unroll
        for (int i = 0; i < 4; i++) {
            const int ra = wm + i * 16 + g;
            const int rb = ra + 8;
            const uint2 p0 = *(const uint2*)&As[buf][ra * 8 + ((tq ^ (ra & 3)) << 1)];
            const uint2 p1 = *(const uint2*)&As[buf][rb * 8 + ((tq ^ (rb & 3)) << 1)];
            a[i][0] = p0.x; a[i][2] = p0.y;
            a[i][1] = p1.x; a[i][3] = p1.y;
        }
#pragma unroll
        for (int j = 0; j < 4; j++) {
            const int cb = wn + j * 8 + g;
            const uint2 p = *(const uint2*)&Bs[buf][cb * 8 + ((tq ^ (cb & 3)) << 1)];
            b[j][0] = p.x; b[j][1] = p.y;
        }
#pragma unroll
        for (int i = 0; i < 4; i++)
#pragma unroll
            for (int j = 0; j < 4; j++) {
                asm volatile(
                    "mma.sync.aligned.m16n8k8.row.col.f32.tf32.tf32.f32 "
                    "{%0,%1,%2,%3}, {%4,%5,%6,%7}, {%8,%9}, {%0,%1,%2,%3};"
                    : "+f"(acc[i][j][0]), "+f"(acc[i][j][1]),
                      "+f"(acc[i][j][2]), "+f"(acc[i][j][3])
                    : "r"(a[i][0]), "r"(a[i][1]), "r"(a[i][2]), "r"(a[i][3]),
                      "r"(b[j][0]), "r"(b[j][1]));
            }

        if (more) {
            const int nbuf = buf ^ 1;
            const int ac = arow & 3;
            const int hb = ah >> 2;
            unsigned* ar = &As[nbuf][arow * 8];
            ar[((0 ^ ac) << 1) + hb] = f2tf32(av.x);
            ar[((1 ^ ac) << 1) + hb] = f2tf32(av.y);
            ar[((2 ^ ac) << 1) + hb] = f2tf32(av.z);
            ar[((3 ^ ac) << 1) + hb] = f2tf32(av.w);
            const int km = brow & 3, kh = brow >> 2;
            const float bb[4] = {bv.x, bv.y, bv.z, bv.w};
#pragma unroll
            for (int c = 0; c < 4; c++) {
                const int col = bcol + c;
                Bs[nbuf][col * 8 + ((km ^ (col & 3)) << 1) + kh] = f2tf32(bb[c]);
            }
            __syncthreads();
        }
    }

    // epilogue
#pragma unroll
    for (int i = 0; i < 4; i++) {
        const int r0 = row0 + wm + i * 16 + g;
#pragma unroll
        for (int j = 0; j < 4; j++) {
            const int col = col0 + wn + j * 8 + tq * 2;
            if (col >= Nn) continue;
            float2 bsv = make_float2(0.f, 0.f);
            if (BIAS) bsv = *(const float2*)(bias + col);
            float2 v0, v1;
            v0.x = acc[i][j][0] + (BIAS ? bsv.x : 0.f);
            v0.y = acc[i][j][1] + (BIAS ? bsv.y : 0.f);
            v1.x = acc[i][j][2] + (BIAS ? bsv.x : 0.f);
            v1.y = acc[i][j][3] + (BIAS ? bsv.y : 0.f);
            if (RELU) {
                v0.x = fmaxf(v0.x, 0.f); v0.y = fmaxf(v0.y, 0.f);
                v1.x = fmaxf(v1.x, 0.f); v1.y = fmaxf(v1.y, 0.f);
            }
            *(float2*)(C + (size_t)r0 * Nn + col) = v0;
            *(float2*)(C + (size_t)(r0 + 8) * Nn + col) = v1;
        }
    }
}

// ---------------- SIMT SGEMM (small M cases only) -------------------------
#define BM 128
#define BN 128
#define BK 8
#define TM 8
#define TN 8

template<bool RELU, bool BIAS>
__global__ void sgemm(const float* __restrict__ A, const float* __restrict__ B,
                      const float* __restrict__ bias, float* __restrict__ C,
                      int M, int Nn, int K)
{
    __shared__ float As[BK][BM];
    __shared__ float Bs[BK][BN];
    const int tid = threadIdx.x;
    const int row0 = blockIdx.y * BM;
    const int col0 = blockIdx.x * BN;
    const int tx = tid % 16;
    const int ty = tid / 16;

    float acc[TM][TN];
#pragma unroll
    for (int i = 0; i < TM; i++)
#pragma unroll
        for (int j = 0; j < TN; j++) acc[i][j] = 0.f;

    const int aRow = tid >> 1;
    const int aCol = (tid & 1) * 4;
    const int bRow = tid >> 5;
    const int bCol = (tid & 31) * 4;

    for (int k0 = 0; k0 < K; k0 += BK) {
        int gr = row0 + aRow;
        float4 av = make_float4(0.f, 0.f, 0.f, 0.f);
        if (gr < M) av = *(const float4*)(A + (size_t)gr * K + k0 + aCol);
        As[aCol + 0][aRow] = av.x;
        As[aCol + 1][aRow] = av.y;
        As[aCol + 2][aRow] = av.z;
        As[aCol + 3][aRow] = av.w;

        int gc = col0 + bCol;
        float4 bv = make_float4(0.f, 0.f, 0.f, 0.f);
        if (gc < Nn) bv = *(const float4*)(B + (size_t)(k0 + bRow) * Nn + gc);
        *(float4*)&Bs[bRow][bCol] = bv;
        __syncthreads();

#pragma unroll
        for (int kk = 0; kk < BK; kk++) {
            float ar[TM], br[TN];
#pragma unroll
            for (int i = 0; i < TM; i++) ar[i] = As[kk][ty * TM + i];
#pragma unroll
            for (int j = 0; j < TN; j++) br[j] = Bs[kk][tx * TN + j];
#pragma unroll
            for (int i = 0; i < TM; i++)
#pragma unroll
                for (int j = 0; j < TN; j++)
                    acc[i][j] = fmaf(ar[i], br[j], acc[i][j]);
        }
        __syncthreads();
    }

#pragma unroll
    for (int i = 0; i < TM; i++) {
        int r = row0 + ty * TM + i;
        if (r >= M) continue;
#pragma unroll
        for (int j = 0; j < TN; j++) {
            int c = col0 + tx * TN + j;
            if (c >= Nn) continue;
            float v = acc[i][j];
            if (BIAS) v += bias[c];
            if (RELU) v = fmaxf(v, 0.f);
            C[(size_t)r * Nn + c] = v;
        }
    }
}

template<bool BIAS>
__global__ void sgemm_bz(const float* __restrict__ A0, const float* __restrict__ B0,
                         const float* __restrict__ bias0, float* __restrict__ C0,
                         int M, int Nn, int K,
                         size_t sA, size_t sB, size_t sBias, size_t sC)
{
    const int z = blockIdx.z;
    const float* A = A0 + sA * z;
    const float* B = B0 + sB * z;
    const float* bias = BIAS ? (bias0 + sBias * z) : nullptr;
    float* C = C0 + sC * z;

    __shared__ float As[BK][BM];
    __shared__ float Bs[BK][BN];
    const int tid = threadIdx.x;
    const int row0 = blockIdx.y * BM;
    const int col0 = blockIdx.x * BN;
    const int tx = tid % 16;
    const int ty = tid / 16;

    float acc[TM][TN];
#pragma unroll
    for (int i = 0; i < TM; i++)
#pragma unroll
        for (int j = 0; j < TN; j++) acc[i][j] = 0.f;

    const int aRow = tid >> 1;
    const int aCol = (tid & 1) * 4;
    const int bRow = tid >> 5;
    const int bCol = (tid & 31) * 4;

    for (int k0 = 0; k0 < K; k0 += BK) {
        int gr = row0 + aRow;
        float4 av = make_float4(0.f, 0.f, 0.f, 0.f);
        if (gr < M) av = *(const float4*)(A + (size_t)gr * K + k0 + aCol);
        As[aCol + 0][aRow] = av.x;
        As[aCol + 1][aRow] = av.y;
        As[aCol + 2][aRow] = av.z;
        As[aCol + 3][aRow] = av.w;

        int gc = col0 + bCol;
        float4 bv = make_float4(0.f, 0.f, 0.f, 0.f);
        if (gc < Nn) bv = *(const float4*)(B + (size_t)(k0 + bRow) * Nn + gc);
        *(float4*)&Bs[bRow][bCol] = bv;
        __syncthreads();

#pragma unroll
        for (int kk = 0; kk < BK; kk++) {
            float ar[TM], br[TN];
#pragma unroll
            for (int i = 0; i < TM; i++) ar[i] = As[kk][ty * TM + i];
#pragma unroll
            for (int j = 0; j < TN; j++) br[j] = Bs[kk][tx * TN + j];
#pragma unroll
            for (int i = 0; i < TM; i++)
#pragma unroll
                for (int j = 0; j < TN; j++)
                    acc[i][j] = fmaf(ar[i], br[j], acc[i][j]);
        }
        __syncthreads();
    }

#pragma unroll
    for (int i = 0; i < TM; i++) {
        int r = row0 + ty * TM + i;
        if (r >= M) continue;
#pragma unroll
        for (int j = 0; j < TN; j++) {
            int c = col0 + tx * TN + j;
            if (c >= Nn) continue;
            float v = acc[i][j];
            if (BIAS) v += bias[c];
            C[(size_t)r * Nn + c] = v;
        }
    }
}

// ---------------- embedding ------------
__global__ void embed_kernel(const int* __restrict__ cap, const float* __restrict__ emb,
                             const float* __restrict__ pos, float* __restrict__ X)
{
    int r = blockIdx.x;
    int t = r & (TT - 1);
    int c = cap[r];
    int d = threadIdx.x * 4;
    float4 e = *(const float4*)(emb + (size_t)c * DD + d);
    float4 p = *(const float4*)(pos + (size_t)t * DD + d);
    e.x += p.x; e.y += p.y; e.z += p.z; e.w += p.w;
    *(float4*)(X + (size_t)r * DD + d) = e;
}

// ---------------- flash attention -----------------------------------------
#define QS_STRIDE 132
#define KS_STRIDE 68
#define PS_STRIDE 132
#define FA_SMEM ((64*QS_STRIDE + 64*KS_STRIDE + 64*64 + 64*PS_STRIDE) * sizeof(float))

__global__ __launch_bounds__(256) void flash_attn(
    const float* __restrict__ Q, const float* __restrict__ K,
    const float* __restrict__ V, float* __restrict__ O)
{
    extern __shared__ float sh[];
    float* Qs = sh;
    float* Ks = Qs + 64 * QS_STRIDE;
    float* Vs = Ks + 64 * KS_STRIDE;
    float* Ps = Vs + 64 * 64;

    const int bid = blockIdx.x;
    const int qt = bid & 3;
    const int h  = (bid >> 2) & 15;
    const int n  = bid >> 6;
    const int q0 = qt * 128;

    const int tid = threadIdx.x;
    const int tx = tid & 15;
    const int ty = tid >> 4;

    {
        const int d4 = (tid & 15) * 4;
        const int r0 = tid >> 4;
#pragma unroll
        for (int rr = 0; rr < 8; rr++) {
            const int r = r0 + rr * 16;
            const float4 v = *(const float4*)(Q + ((size_t)(n * TT + q0 + r)) * DD + h * DHD + d4);
            Qs[(d4 + 0) * QS_STRIDE + r] = v.x;
            Qs[(d4 + 1) * QS_STRIDE + r] = v.y;
            Qs[(d4 + 2) * QS_STRIDE + r] = v.z;
            Qs[(d4 + 3) * QS_STRIDE + r] = v.w;
        }
    }

    float o[8][4];
    float m[8], l[8];
#pragma unroll
    for (int i = 0; i < 8; i++) {
        m[i] = -1e30f; l[i] = 0.f;
#pragma unroll
        for (int j = 0; j < 4; j++) o[i][j] = 0.f;
    }

    const int ntiles = (q0 + 128) / 64;
    for (int t = 0; t < ntiles; t++) {
        const int j0 = t * 64;
        __syncthreads();
        {
            const int d4 = (tid & 15) * 4;
            const int c0 = tid >> 4;
#pragma unroll
            for (int cc = 0; cc < 4; cc++) {
                const int c = c0 + cc * 16;
                const size_t grow = ((size_t)(n * TT + j0 + c)) * DD + h * DHD + d4;
                const float4 kv = *(const float4*)(K + grow);
                Ks[(d4 + 0) * KS_STRIDE + c] = kv.x;
                Ks[(d4 + 1) * KS_STRIDE + c] = kv.y;
                Ks[(d4 + 2) * KS_STRIDE + c] = kv.z;
                Ks[(d4 + 3) * KS_STRIDE + c] = kv.w;
                const float4 vv = *(const float4*)(V + grow);
                *(float4*)(Vs + c * 64 + d4) = vv;
            }
        }
        __syncthreads();

        float s[8][4];
#pragma unroll
        for (int i = 0; i < 8; i++)
#pragma unroll
            for (int j = 0; j < 4; j++) s[i][j] = 0.f;
#pragma unroll 4
        for (int kk = 0; kk < 64; kk++) {
            float ar[8], br[4];
            *(float4*)ar       = *(const float4*)(Qs + kk * QS_STRIDE + ty * 8);
            *(float4*)(ar + 4) = *(const float4*)(Qs + kk * QS_STRIDE + ty * 8 + 4);
            *(float4*)br       = *(const float4*)(Ks + kk * KS_STRIDE + tx * 4);
#pragma unroll
            for (int i = 0; i < 8; i++)
#pragma unroll
                for (int j = 0; j < 4; j++) s[i][j] = fmaf(ar[i], br[j], s[i][j]);
        }

        float tmax[8];
#pragma unroll
        for (int i = 0; i < 8; i++) {
            const int q = q0 + ty * 8 + i;
            tmax[i] = -1e30f;
#pragma unroll
            for (int j = 0; j < 4; j++) {
                const int kidx = j0 + tx * 4 + j;
                float v = (kidx <= q) ? s[i][j] * 0.125f : -1e30f;
                s[i][j] = v;
                tmax[i] = fmaxf(tmax[i], v);
            }
        }
#pragma unroll
        for (int st = 1; st < 16; st <<= 1)
#pragma unroll
            for (int i = 0; i < 8; i++)
                tmax[i] = fmaxf(tmax[i], __shfl_xor_sync(0xffffffffu, tmax[i], st));

        float psum[8];
#pragma unroll
        for (int i = 0; i < 8; i++) {
            const float mn = fmaxf(m[i], tmax[i]);
            const float sc = __expf(m[i] - mn);
            m[i] = mn;
            l[i] *= sc;
#pragma unroll
            for (int j = 0; j < 4; j++) o[i][j] *= sc;
            float ps = 0.f;
#pragma unroll
            for (int j = 0; j < 4; j++) {
                const float p = __expf(s[i][j] - mn);
                s[i][j] = p;
                ps += p;
            }
            psum[i] = ps;
        }
#pragma unroll
        for (int st = 1; st < 16; st <<= 1)
#pragma unroll
            for (int i = 0; i < 8; i++)
                psum[i] += __shfl_xor_sync(0xffffffffu, psum[i], st);
#pragma unroll
        for (int i = 0; i < 8; i++) l[i] += psum[i];

#pragma unroll
        for (int j = 0; j < 4; j++) {
            const int k = tx * 4 + j;
#pragma unroll
            for (int i = 0; i < 8; i++)
                Ps[k * PS_STRIDE + ty * 8 + i] = s[i][j];
        }
        __syncthreads();

#pragma unroll 4
        for (int k = 0; k < 64; k++) {
            float ar[8], bv[4];
            *(float4*)ar       = *(const float4*)(Ps + k * PS_STRIDE + ty * 8);
            *(float4*)(ar + 4) = *(const float4*)(Ps + k * PS_STRIDE + ty * 8 + 4);
            *(float4*)bv       = *(const float4*)(Vs + k * 64 + tx * 4);
#pragma unroll
            for (int i = 0; i < 8; i++)
#pragma unroll
                for (int j = 0; j < 4; j++) o[i][j] = fmaf(ar[i], bv[j], o[i][j]);
        }
    }

#pragma unroll
    for (int i = 0; i < 8; i++) {
        const int q = q0 + ty * 8 + i;
        const float inv = 1.f / l[i];
        float4 ov;
        ov.x = o[i][0] * inv; ov.y = o[i][1] * inv;
        ov.z = o[i][2] * inv; ov.w = o[i][3] * inv;
        *(float4*)(O + ((size_t)((n * HH + h) * TT + q)) * DHD + tx * 4) = ov;
    }
}

// ---------------- residual + LayerNorm ----------------------------------
__global__ void ln_kernel(const float* __restrict__ X, const float* __restrict__ Rsd,
                          const float* __restrict__ g, const float* __restrict__ b,
                          float* __restrict__ out, int mode)
{
    const int r = blockIdx.x;
    const int tid = threadIdx.x;
    size_t rr;
    if (mode == 0) rr = (size_t)r;
    else {
        int n = r >> 9;
        int s = r & (TT - 1);
        rr = (size_t)(n * 16 + (s >> 5));
    }
    const float* xr = X + (size_t)r * DD;
    const float* dr = Rsd + rr * DD;
    const int d = tid * 4;
    float4 xv = *(const float4*)(xr + d);
    float4 dv = *(const float4*)(dr + d);
    float v0 = xv.x + dv.x, v1 = xv.y + dv.y, v2 = xv.z + dv.z, v3 = xv.w + dv.w;

    __shared__ float s1[256], s2[256];
    s1[tid] = v0 + v1 + v2 + v3;
    s2[tid] = v0 * v0 + v1 * v1 + v2 * v2 + v3 * v3;
    __syncthreads();
    for (int st = 128; st > 0; st >>= 1) {
        if (tid < st) { s1[tid] += s1[tid + st]; s2[tid] += s2[tid + st]; }
        __syncthreads();
    }
    const float mean = s1[0] * (1.f / DD);
    const float var = s2[0] * (1.f / DD) - mean * mean;
    const float rstd = rsqrtf(var + 1e-5f);

    float4 ov;
    ov.x = g[d + 0] * (v0 - mean) * rstd + b[d + 0];
    ov.y = g[d + 1] * (v1 - mean) * rstd + b[d + 1];
    ov.z = g[d + 2] * (v2 - mean) * rstd + b[d + 2];
    ov.w = g[d + 3] * (v3 - mean) * rstd + b[d + 3];
    *(float4*)(out + (size_t)r * DD + d) = ov;
}

// ------------- tiled rows for cross-attn out-projection (batched) --------
__global__ void tilefe_kernel(const float* __restrict__ fev, float* __restrict__ A)
{
    const int bx = blockIdx.x;
    const int z = bx >> 8;
    const int rl = bx & 255;
    const int n = rl >> 4;
    const int g = rl & 15;
    const int d = threadIdx.x * 4;
    const float* src = fev + (size_t)z * NB * DD + (size_t)n * DD + g * 64;
    float4 v = *(const float4*)(src + (d & 63));
    *(float4*)(A + (size_t)z * NB * 16 * DD + (size_t)rl * DD + d) = v;
}

// ---------------- launch --------------------------------------------------
extern "C" void kernel_launch(void* const* d_in, const int* in_sizes, int n_in,
                              void* d_out, int out_size)
{
    const float* features = (const float*)d_in[0];
    const int*   captions = (const int*)d_in[1];
    const float* feat_W   = (const float*)d_in[2];
    const float* feat_b   = (const float*)d_in[3];
    const float* cap_emb  = (const float*)d_in[4];
    const float* pos_emb  = (const float*)d_in[5];
    const float* sa_Wq = (const float*)d_in[6];
    const float* sa_Wk = (const float*)d_in[7];
    const float* sa_Wv = (const float*)d_in[8];
    const float* sa_Wo = (const float*)d_in[9];
    const float* sa_bo = (const float*)d_in[10];
    const float* sa_g  = (const float*)d_in[11];
    const float* sa_b  = (const float*)d_in[12];
    const float* ca_Wv = (const float*)d_in[15];
    const float* ca_Wo = (const float*)d_in[16];
    const float* ca_bo = (const float*)d_in[17];
    const float* ca_g  = (const float*)d_in[18];
    const float* ca_b  = (const float*)d_in[19];
    const float* ff_W1 = (const float*)d_in[20];
    const float* ff_b1 = (const float*)d_in[21];
    const float* ff_W2 = (const float*)d_in[22];
    const float* ff_b2 = (const float*)d_in[23];
    const float* ff_g  = (const float*)d_in[24];
    const float* ff_b  = (const float*)d_in[25];
    const float* score_W = (const float*)d_in[26];
    const float* score_b = (const float*)d_in[27];
    float* out = (float*)d_out;

    float *px, *pq, *pk, *pv, *pt, *pattn, *ph, *pfe, *pfev, *pzt, *pz;
    cudaGetSymbolAddress((void**)&px,    g_x);
    cudaGetSymbolAddress((void**)&pq,    g_q);
    cudaGetSymbolAddress((void**)&pk,    g_k);
    cudaGetSymbolAddress((void**)&pv,    g_v);
    cudaGetSymbolAddress((void**)&pt,    g_t);
    cudaGetSymbolAddress((void**)&pattn, g_attn);
    cudaGetSymbolAddress((void**)&ph,    g_h);
    cudaGetSymbolAddress((void**)&pfe,   g_fe);
    cudaGetSymbolAddress((void**)&pfev,  g_fev);
    cudaGetSymbolAddress((void**)&pzt,   g_ztile);
    cudaGetSymbolAddress((void**)&pz,    g_z);

    static bool attr_set = false;
    if (!attr_set) {
        cudaFuncSetAttribute(flash_attn, cudaFuncAttributeMaxDynamicSharedMemorySize, FA_SMEM);
        attr_set = true;
    }

    // features -> fe  (M=16, SIMT path)
    sgemm<false, true><<<dim3(DD / BN, 1), 256>>>(features, feat_W, feat_b, pfe, NB, DD, DIN);

    // embedding
    embed_kernel<<<ROWS, 256>>>(captions, cap_emb, pos_emb, px);

    // cross-attention contributions for all layers
    sgemm_bz<false><<<dim3(DD / BN, 1, LL), 256>>>(pfe, ca_Wv, nullptr, pfev,
                                                   NB, DD, DD,
                                                   0, (size_t)DD * DD, 0, (size_t)NB * DD);
    tilefe_kernel<<<LL * NB * 16, 256>>>(pfev, pzt);
    sgemm_bz<true><<<dim3(DD / BN, 2, LL), 256>>>(pzt, ca_Wo, ca_bo, pz,
                                                  NB * 16, DD, DD,
                                                  (size_t)NB * 16 * DD, (size_t)DD * DD,
                                                  DD, (size_t)NB * 16 * DD);

    const dim3 gP(DD / 128, ROWS / 128);     // 8 x 64
    const dim3 gF(FFD / 128, ROWS / 128);    // 16 x 64

    for (int i = 0; i < LL; i++) {
        const float* Wq = sa_Wq + (size_t)i * DD * DD;
        const float* Wk = sa_Wk + (size_t)i * DD * DD;
        const float* Wv = sa_Wv + (size_t)i * DD * DD;
        const float* Wo = sa_Wo + (size_t)i * DD * DD;

        tgemm<false, false><<<gP, 256>>>(px, Wq, nullptr, pq, ROWS, DD, DD);
        tgemm<false, false><<<gP, 256>>>(px, Wk, nullptr, pk, ROWS, DD, DD);
        tgemm<false, false><<<gP, 256>>>(px, Wv, nullptr, pv, ROWS, DD, DD);
        flash_attn<<<NB * HH * 4, 256, FA_SMEM>>>(pq, pk, pv, pattn);
        tgemm<false, true><<<gP, 256>>>(pattn, Wo, sa_bo + (size_t)i * DD, pt, ROWS, DD, DD);
        ln_kernel<<<ROWS, 256>>>(px, pt, sa_g + (size_t)i * DD, sa_b + (size_t)i * DD, px, 0);

        ln_kernel<<<ROWS, 256>>>(px, pz + (size_t)i * NB * 16 * DD,
                                 ca_g + (size_t)i * DD, ca_b + (size_t)i * DD, px, 1);

        tgemm<true, true><<<gF, 256>>>(px, ff_W1 + (size_t)i * DD * FFD,
                                       ff_b1 + (size_t)i * FFD, ph, ROWS, FFD, DD);
        tgemm<false, true><<<gP, 256>>>(ph, ff_W2 + (size_t)i * FFD * DD,
                                        ff_b2 + (size_t)i * DD, pt, ROWS, DD, FFD);
        ln_kernel<<<ROWS, 256>>>(px, pt, ff_g + (size_t)i * DD, ff_b + (size_t)i * DD, px, 0);
    }

    // final vocab projection
    tgemm<false, true><<<dim3((VV + 127) / 128, ROWS / 128), 256>>>(px, score_W, score_b, out, ROWS, VV, DD);
}

// round 6
// speedup vs baseline: 4.2602x; 1.6234x over previous
#include <cuda_runtime.h>
#include <cuda_bf16.h>
#include <cuda_fp16.h>
#include <cstdio>
#include <cstdint>

// Problem constants
#define NB   16
#define TT   512
#define VV   10000
#define DIN  2048
#define DD   1024
#define HH   16
#define LL   4
#define FFD  2048
#define DHD  64
#define ROWS (NB*TT)          // 8192
#define NEGF (-1e8f)

// ---------------- device scratch ----------------
__device__ float g_x[ROWS * DD];
__device__ float g_q[ROWS * DD];
__device__ float g_k[ROWS * DD];
__device__ float g_v[ROWS * DD];
__device__ float g_t[ROWS * DD];
__device__ float g_attn[ROWS * DD];
__device__ float g_h[ROWS * FFD];
__device__ float g_fe[NB * DD];
__device__ float g_fev[LL * NB * DD];
__device__ float g_ztile[LL * NB * 16 * DD];
__device__ float g_z[LL * NB * 16 * DD];

// ---------------- small helpers ----------------
__device__ __forceinline__ unsigned h2_as_u32(__half2 h) {
    return *(unsigned*)&h;
}

// ==================== fp16 tensor-core GEMM (mma.sync m16n8k16) ==========
// C = A(MxK) * B(KxN) [+bias] [ReLU]. M%128==0, K%16==0. N predicated.
// 256 threads = 8 warps (2x4), warp tile 64x32, K-chunk = 16, double buffer.
// smem rows hold 16 halves as 8 half2 words; physical word index
// p(w,row) = ((w&3)^(row&3))*2 + (w>>2)  -> LDS.64 yields (k, k+8) reg pairs.

template<bool RELU, bool BIAS>
__global__ __launch_bounds__(256) void hgemm(
    const float* __restrict__ A, const float* __restrict__ B,
    const float* __restrict__ bias, float* __restrict__ C,
    int M, int Nn, int K)
{
    __shared__ unsigned As[2][128 * 8];   // 4KB each
    __shared__ unsigned Bs[2][128 * 8];

    const int tid  = threadIdx.x;
    const int lane = tid & 31;
    const int warp = tid >> 5;
    const int row0 = blockIdx.y * 128;
    const int col0 = blockIdx.x * 128;
    const int wm = (warp >> 2) * 64;       // 0 or 64
    const int wn = (warp & 3) * 32;        // 0..96
    const int g  = lane >> 2;              // 0..7
    const int tq = lane & 3;               // 0..3

    // A global-load mapping: row = tid>>1, k-half h = tid&1 (k offset 8h)
    const int arow = tid >> 1;
    const int ah   = tid & 1;
    // B global-load mapping: k = tid>>4 (0..15), n base = (tid&15)*8
    const int bk  = tid >> 4;
    const int bn0 = (tid & 15) * 8;

    const float* aptr = A + (size_t)(row0 + arow) * K + ah * 8;
    const float* bptr = B + (size_t)bk * Nn + col0 + bn0;

    float acc[4][4][4];
#pragma unroll
    for (int i = 0; i < 4; i++)
#pragma unroll
        for (int j = 0; j < 4; j++)
#pragma unroll
            for (int c = 0; c < 4; c++) acc[i][j][c] = 0.f;

    const int nk = K >> 4;

    // prologue: load chunk 0
    float4 a0 = *(const float4*)aptr;
    float4 a1 = *(const float4*)(aptr + 4);
    float4 b0, b1;
    {
        const int gc0 = col0 + bn0;
        b0 = make_float4(0.f, 0.f, 0.f, 0.f);
        b1 = make_float4(0.f, 0.f, 0.f, 0.f);
        if (gc0 + 3 < Nn)      b0 = *(const float4*)bptr;
        else { if (gc0+0 < Nn) b0.x = bptr[0]; if (gc0+1 < Nn) b0.y = bptr[1];
               if (gc0+2 < Nn) b0.z = bptr[2]; if (gc0+3 < Nn) b0.w = bptr[3]; }
        if (gc0 + 7 < Nn)      b1 = *(const float4*)(bptr + 4);
        else { if (gc0+4 < Nn) b1.x = bptr[4]; if (gc0+5 < Nn) b1.y = bptr[5];
               if (gc0+6 < Nn) b1.z = bptr[6]; if (gc0+7 < Nn) b1.w = bptr[7]; }
    }

#define STASH(BUF)                                                              \
    do {                                                                        \
        /* A: row arow, words w = ah*4 + c */                                   \
        unsigned hww[4];                                                        \
        hww[0] = h2_as_u32(__floats2half2_rn(a0.x, a0.y));                      \
        hww[1] = h2_as_u32(__floats2half2_rn(a0.z, a0.w));                      \
        hww[2] = h2_as_u32(__floats2half2_rn(a1.x, a1.y));                      \
        hww[3] = h2_as_u32(__floats2half2_rn(a1.z, a1.w));                      \
        const int rm = arow & 3;                                                \
        unsigned* ar = &As[BUF][arow * 8];                                      \
        _Pragma("unroll")                                                       \
        for (int c = 0; c < 4; c++)                                             \
            ar[((c ^ rm) << 1) + ah] = hww[c];                                  \
        /* B: 8 halves at (n = bn0+e, k = bk) */                                \
        const int w = bk >> 1;                                                  \
        const int klo = bk & 1;                                                 \
        const float bbv[8] = {b0.x, b0.y, b0.z, b0.w, b1.x, b1.y, b1.z, b1.w};  \
        _Pragma("unroll")                                                       \
        for (int e = 0; e < 8; e++) {                                           \
            const int n = bn0 + e;                                              \
            const int p = (((w & 3) ^ (n & 3)) << 1) + (w >> 2);                \
            __half* dst = (__half*)&Bs[BUF][n * 8 + p];                         \
            dst[klo] = __float2half_rn(bbv[e]);                                 \
        }                                                                       \
    } while (0)

    STASH(0);
    __syncthreads();

    for (int it = 0; it < nk; it++) {
        const int buf = it & 1;
        const bool more = (it + 1) < nk;
        if (more) {
            a0 = *(const float4*)(aptr + (size_t)(it + 1) * 16);
            a1 = *(const float4*)(aptr + (size_t)(it + 1) * 16 + 4);
            const float* bp = bptr + (size_t)(it + 1) * 16 * Nn;
            const int gc0 = col0 + bn0;
            b0 = make_float4(0.f, 0.f, 0.f, 0.f);
            b1 = make_float4(0.f, 0.f, 0.f, 0.f);
            if (gc0 + 3 < Nn)      b0 = *(const float4*)bp;
            else { if (gc0+0 < Nn) b0.x = bp[0]; if (gc0+1 < Nn) b0.y = bp[1];
                   if (gc0+2 < Nn) b0.z = bp[2]; if (gc0+3 < Nn) b0.w = bp[3]; }
            if (gc0 + 7 < Nn)      b1 = *(const float4*)(bp + 4);
            else { if (gc0+4 < Nn) b1.x = bp[4]; if (gc0+5 < Nn) b1.y = bp[5];
                   if (gc0+6 < Nn) b1.z = bp[6]; if (gc0+7 < Nn) b1.w = bp[7]; }
        }

        // fragments + MMA
        unsigned af[4][4], bf[4][2];
#pragma unroll
        for (int i = 0; i < 4; i++) {
            const int ra = wm + i * 16 + g;
            const int rb = ra + 8;
            const uint2 pA = *(const uint2*)&As[buf][ra * 8 + ((tq ^ (ra & 3)) << 1)];
            const uint2 pB = *(const uint2*)&As[buf][rb * 8 + ((tq ^ (rb & 3)) << 1)];
            af[i][0] = pA.x; af[i][2] = pA.y;
            af[i][1] = pB.x; af[i][3] = pB.y;
        }
#pragma unroll
        for (int j = 0; j < 4; j++) {
            const int nr = wn + j * 8 + g;
            const uint2 p = *(const uint2*)&Bs[buf][nr * 8 + ((tq ^ (nr & 3)) << 1)];
            bf[j][0] = p.x; bf[j][1] = p.y;
        }
#pragma unroll
        for (int i = 0; i < 4; i++)
#pragma unroll
            for (int j = 0; j < 4; j++) {
                asm volatile(
                    "mma.sync.aligned.m16n8k16.row.col.f32.f16.f16.f32 "
                    "{%0,%1,%2,%3}, {%4,%5,%6,%7}, {%8,%9}, {%0,%1,%2,%3};"
                    : "+f"(acc[i][j][0]), "+f"(acc[i][j][1]),
                      "+f"(acc[i][j][2]), "+f"(acc[i][j][3])
                    : "r"(af[i][0]), "r"(af[i][1]), "r"(af[i][2]), "r"(af[i][3]),
                      "r"(bf[j][0]), "r"(bf[j][1]));
            }

        if (more) {
            const int nbuf = buf ^ 1;
            STASH(nbuf);
            __syncthreads();
        }
    }
#undef STASH

    // epilogue (same accumulator layout as m16n8k8 f32)
#pragma unroll
    for (int i = 0; i < 4; i++) {
        const int r0 = row0 + wm + i * 16 + g;
#pragma unroll
        for (int j = 0; j < 4; j++) {
            const int col = col0 + wn + j * 8 + tq * 2;
            if (col >= Nn) continue;
            float2 bsv = make_float2(0.f, 0.f);
            if (BIAS) bsv = *(const float2*)(bias + col);
            float2 v0, v1;
            v0.x = acc[i][j][0] + (BIAS ? bsv.x : 0.f);
            v0.y = acc[i][j][1] + (BIAS ? bsv.y : 0.f);
            v1.x = acc[i][j][2] + (BIAS ? bsv.x : 0.f);
            v1.y = acc[i][j][3] + (BIAS ? bsv.y : 0.f);
            if (RELU) {
                v0.x = fmaxf(v0.x, 0.f); v0.y = fmaxf(v0.y, 0.f);
                v1.x = fmaxf(v1.x, 0.f); v1.y = fmaxf(v1.y, 0.f);
            }
            *(float2*)(C + (size_t)r0 * Nn + col) = v0;
            *(float2*)(C + (size_t)(r0 + 8) * Nn + col) = v1;
        }
    }
}

// ---------------- SIMT SGEMM (small M cases only) -------------------------
#define BM 128
#define BN 128
#define BK 8
#define TM 8
#define TN 8

template<bool RELU, bool BIAS>
__global__ void sgemm(const float* __restrict__ A, const float* __restrict__ B,
                      const float* __restrict__ bias, float* __restrict__ C,
                      int M, int Nn, int K)
{
    __shared__ float As[BK][BM];
    __shared__ float Bs[BK][BN];
    const int tid = threadIdx.x;
    const int row0 = blockIdx.y * BM;
    const int col0 = blockIdx.x * BN;
    const int tx = tid % 16;
    const int ty = tid / 16;

    float acc[TM][TN];
#pragma unroll
    for (int i = 0; i < TM; i++)
#pragma unroll
        for (int j = 0; j < TN; j++) acc[i][j] = 0.f;

    const int aRow = tid >> 1;
    const int aCol = (tid & 1) * 4;
    const int bRow = tid >> 5;
    const int bCol = (tid & 31) * 4;

    for (int k0 = 0; k0 < K; k0 += BK) {
        int gr = row0 + aRow;
        float4 av = make_float4(0.f, 0.f, 0.f, 0.f);
        if (gr < M) av = *(const float4*)(A + (size_t)gr * K + k0 + aCol);
        As[aCol + 0][aRow] = av.x;
        As[aCol + 1][aRow] = av.y;
        As[aCol + 2][aRow] = av.z;
        As[aCol + 3][aRow] = av.w;

        int gc = col0 + bCol;
        float4 bv = make_float4(0.f, 0.f, 0.f, 0.f);
        if (gc < Nn) bv = *(const float4*)(B + (size_t)(k0 + bRow) * Nn + gc);
        *(float4*)&Bs[bRow][bCol] = bv;
        __syncthreads();

#pragma unroll
        for (int kk = 0; kk < BK; kk++) {
            float ar[TM], br[TN];
#pragma unroll
            for (int i = 0; i < TM; i++) ar[i] = As[kk][ty * TM + i];
#pragma unroll
            for (int j = 0; j < TN; j++) br[j] = Bs[kk][tx * TN + j];
#pragma unroll
            for (int i = 0; i < TM; i++)
#pragma unroll
                for (int j = 0; j < TN; j++)
                    acc[i][j] = fmaf(ar[i], br[j], acc[i][j]);
        }
        __syncthreads();
    }

#pragma unroll
    for (int i = 0; i < TM; i++) {
        int r = row0 + ty * TM + i;
        if (r >= M) continue;
#pragma unroll
        for (int j = 0; j < TN; j++) {
            int c = col0 + tx * TN + j;
            if (c >= Nn) continue;
            float v = acc[i][j];
            if (BIAS) v += bias[c];
            if (RELU) v = fmaxf(v, 0.f);
            C[(size_t)r * Nn + c] = v;
        }
    }
}

template<bool BIAS>
__global__ void sgemm_bz(const float* __restrict__ A0, const float* __restrict__ B0,
                         const float* __restrict__ bias0, float* __restrict__ C0,
                         int M, int Nn, int K,
                         size_t sA, size_t sB, size_t sBias, size_t sC)
{
    const int z = blockIdx.z;
    const float* A = A0 + sA * z;
    const float* B = B0 + sB * z;
    const float* bias = BIAS ? (bias0 + sBias * z) : nullptr;
    float* C = C0 + sC * z;

    __shared__ float As[BK][BM];
    __shared__ float Bs[BK][BN];
    const int tid = threadIdx.x;
    const int row0 = blockIdx.y * BM;
    const int col0 = blockIdx.x * BN;
    const int tx = tid % 16;
    const int ty = tid / 16;

    float acc[TM][TN];
#pragma unroll
    for (int i = 0; i < TM; i++)
#pragma unroll
        for (int j = 0; j < TN; j++) acc[i][j] = 0.f;

    const int aRow = tid >> 1;
    const int aCol = (tid & 1) * 4;
    const int bRow = tid >> 5;
    const int bCol = (tid & 31) * 4;

    for (int k0 = 0; k0 < K; k0 += BK) {
        int gr = row0 + aRow;
        float4 av = make_float4(0.f, 0.f, 0.f, 0.f);
        if (gr < M) av = *(const float4*)(A + (size_t)gr * K + k0 + aCol);
        As[aCol + 0][aRow] = av.x;
        As[aCol + 1][aRow] = av.y;
        As[aCol + 2][aRow] = av.z;
        As[aCol + 3][aRow] = av.w;

        int gc = col0 + bCol;
        float4 bv = make_float4(0.f, 0.f, 0.f, 0.f);
        if (gc < Nn) bv = *(const float4*)(B + (size_t)(k0 + bRow) * Nn + gc);
        *(float4*)&Bs[bRow][bCol] = bv;
        __syncthreads();

#pragma unroll
        for (int kk = 0; kk < BK; kk++) {
            float ar[TM], br[TN];
#pragma unroll
            for (int i = 0; i < TM; i++) ar[i] = As[kk][ty * TM + i];
#pragma unroll
            for (int j = 0; j < TN; j++) br[j] = Bs[kk][tx * TN + j];
#pragma unroll
            for (int i = 0; i < TM; i++)
#pragma unroll
                for (int j = 0; j < TN; j++)
                    acc[i][j] = fmaf(ar[i], br[j], acc[i][j]);
        }
        __syncthreads();
    }

#pragma unroll
    for (int i = 0; i < TM; i++) {
        int r = row0 + ty * TM + i;
        if (r >= M) continue;
#pragma unroll
        for (int j = 0; j < TN; j++) {
            int c = col0 + tx * TN + j;
            if (c >= Nn) continue;
            float v = acc[i][j];
            if (BIAS) v += bias[c];
            C[(size_t)r * Nn + c] = v;
        }
    }
}

// ---------------- embedding ------------
__global__ void embed_kernel(const int* __restrict__ cap, const float* __restrict__ emb,
                             const float* __restrict__ pos, float* __restrict__ X)
{
    int r = blockIdx.x;
    int t = r & (TT - 1);
    int c = cap[r];
    int d = threadIdx.x * 4;
    float4 e = *(const float4*)(emb + (size_t)c * DD + d);
    float4 p = *(const float4*)(pos + (size_t)t * DD + d);
    e.x += p.x; e.y += p.y; e.z += p.z; e.w += p.w;
    *(float4*)(X + (size_t)r * DD + d) = e;
}

// ---------------- flash attention -----------------------------------------
#define QS_STRIDE 132
#define KS_STRIDE 68
#define PS_STRIDE 132
#define FA_SMEM ((64*QS_STRIDE + 64*KS_STRIDE + 64*64 + 64*PS_STRIDE) * sizeof(float))

__global__ __launch_bounds__(256) void flash_attn(
    const float* __restrict__ Q, const float* __restrict__ K,
    const float* __restrict__ V, float* __restrict__ O)
{
    extern __shared__ float sh[];
    float* Qs = sh;
    float* Ks = Qs + 64 * QS_STRIDE;
    float* Vs = Ks + 64 * KS_STRIDE;
    float* Ps = Vs + 64 * 64;

    const int bid = blockIdx.x;
    const int qt = bid & 3;
    const int h  = (bid >> 2) & 15;
    const int n  = bid >> 6;
    const int q0 = qt * 128;

    const int tid = threadIdx.x;
    const int tx = tid & 15;
    const int ty = tid >> 4;

    {
        const int d4 = (tid & 15) * 4;
        const int r0 = tid >> 4;
#pragma unroll
        for (int rr = 0; rr < 8; rr++) {
            const int r = r0 + rr * 16;
            const float4 v = *(const float4*)(Q + ((size_t)(n * TT + q0 + r)) * DD + h * DHD + d4);
            Qs[(d4 + 0) * QS_STRIDE + r] = v.x;
            Qs[(d4 + 1) * QS_STRIDE + r] = v.y;
            Qs[(d4 + 2) * QS_STRIDE + r] = v.z;
            Qs[(d4 + 3) * QS_STRIDE + r] = v.w;
        }
    }

    float o[8][4];
    float m[8], l[8];
#pragma unroll
    for (int i = 0; i < 8; i++) {
        m[i] = -1e30f; l[i] = 0.f;
#pragma unroll
        for (int j = 0; j < 4; j++) o[i][j] = 0.f;
    }

    const int ntiles = (q0 + 128) / 64;
    for (int t = 0; t < ntiles; t++) {
        const int j0 = t * 64;
        __syncthreads();
        {
            const int d4 = (tid & 15) * 4;
            const int c0 = tid >> 4;
#pragma unroll
            for (int cc = 0; cc < 4; cc++) {
                const int c = c0 + cc * 16;
                const size_t grow = ((size_t)(n * TT + j0 + c)) * DD + h * DHD + d4;
                const float4 kv = *(const float4*)(K + grow);
                Ks[(d4 + 0) * KS_STRIDE + c] = kv.x;
                Ks[(d4 + 1) * KS_STRIDE + c] = kv.y;
                Ks[(d4 + 2) * KS_STRIDE + c] = kv.z;
                Ks[(d4 + 3) * KS_STRIDE + c] = kv.w;
                const float4 vv = *(const float4*)(V + grow);
                *(float4*)(Vs + c * 64 + d4) = vv;
            }
        }
        __syncthreads();

        float s[8][4];
#pragma unroll
        for (int i = 0; i < 8; i++)
#pragma unroll
            for (int j = 0; j < 4; j++) s[i][j] = 0.f;
#pragma unroll 4
        for (int kk = 0; kk < 64; kk++) {
            float ar[8], br[4];
            *(float4*)ar       = *(const float4*)(Qs + kk * QS_STRIDE + ty * 8);
            *(float4*)(ar + 4) = *(const float4*)(Qs + kk * QS_STRIDE + ty * 8 + 4);
            *(float4*)br       = *(const float4*)(Ks + kk * KS_STRIDE + tx * 4);
#pragma unroll
            for (int i = 0; i < 8; i++)
#pragma unroll
                for (int j = 0; j < 4; j++) s[i][j] = fmaf(ar[i], br[j], s[i][j]);
        }

        float tmax[8];
#pragma unroll
        for (int i = 0; i < 8; i++) {
            const int q = q0 + ty * 8 + i;
            tmax[i] = -1e30f;
#pragma unroll
            for (int j = 0; j < 4; j++) {
                const int kidx = j0 + tx * 4 + j;
                float v = (kidx <= q) ? s[i][j] * 0.125f : -1e30f;
                s[i][j] = v;
                tmax[i] = fmaxf(tmax[i], v);
            }
        }
#pragma unroll
        for (int st = 1; st < 16; st <<= 1)
#pragma unroll
            for (int i = 0; i < 8; i++)
                tmax[i] = fmaxf(tmax[i], __shfl_xor_sync(0xffffffffu, tmax[i], st));

        float psum[8];
#pragma unroll
        for (int i = 0; i < 8; i++) {
            const float mn = fmaxf(m[i], tmax[i]);
            const float sc = __expf(m[i] - mn);
            m[i] = mn;
            l[i] *= sc;
#pragma unroll
            for (int j = 0; j < 4; j++) o[i][j] *= sc;
            float ps = 0.f;
#pragma unroll
            for (int j = 0; j < 4; j++) {
                const float p = __expf(s[i][j] - mn);
                s[i][j] = p;
                ps += p;
            }
            psum[i] = ps;
        }
#pragma unroll
        for (int st = 1; st < 16; st <<= 1)
#pragma unroll
            for (int i = 0; i < 8; i++)
                psum[i] += __shfl_xor_sync(0xffffffffu, psum[i], st);
#pragma unroll
        for (int i = 0; i < 8; i++) l[i] += psum[i];

#pragma unroll
        for (int j = 0; j < 4; j++) {
            const int k = tx * 4 + j;
#pragma unroll
            for (int i = 0; i < 8; i++)
                Ps[k * PS_STRIDE + ty * 8 + i] = s[i][j];
        }
        __syncthreads();

#pragma unroll 4
        for (int k = 0; k < 64; k++) {
            float ar[8], bv[4];
            *(float4*)ar       = *(const float4*)(Ps + k * PS_STRIDE + ty * 8);
            *(float4*)(ar + 4) = *(const float4*)(Ps + k * PS_STRIDE + ty * 8 + 4);
            *(float4*)bv       = *(const float4*)(Vs + k * 64 + tx * 4);
#pragma unroll
            for (int i = 0; i < 8; i++)
#pragma unroll
                for (int j = 0; j < 4; j++) o[i][j] = fmaf(ar[i], bv[j], o[i][j]);
        }
    }

#pragma unroll
    for (int i = 0; i < 8; i++) {
        const int q = q0 + ty * 8 + i;
        const float inv = 1.f / l[i];
        float4 ov;
        ov.x = o[i][0] * inv; ov.y = o[i][1] * inv;
        ov.z = o[i][2] * inv; ov.w = o[i][3] * inv;
        *(float4*)(O + ((size_t)((n * HH + h) * TT + q)) * DHD + tx * 4) = ov;
    }
}

// ---------------- residual + LayerNorm ----------------------------------
__global__ void ln_kernel(const float* __restrict__ X, const float* __restrict__ Rsd,
                          const float* __restrict__ g, const float* __restrict__ b,
                          float* __restrict__ out, int mode)
{
    const int r = blockIdx.x;
    const int tid = threadIdx.x;
    size_t rr;
    if (mode == 0) rr = (size_t)r;
    else {
        int n = r >> 9;
        int s = r & (TT - 1);
        rr = (size_t)(n * 16 + (s >> 5));
    }
    const float* xr = X + (size_t)r * DD;
    const float* dr = Rsd + rr * DD;
    const int d = tid * 4;
    float4 xv = *(const float4*)(xr + d);
    float4 dv = *(const float4*)(dr + d);
    float v0 = xv.x + dv.x, v1 = xv.y + dv.y, v2 = xv.z + dv.z, v3 = xv.w + dv.w;

    __shared__ float s1[256], s2[256];
    s1[tid] = v0 + v1 + v2 + v3;
    s2[tid] = v0 * v0 + v1 * v1 + v2 * v2 + v3 * v3;
    __syncthreads();
    for (int st = 128; st > 0; st >>= 1) {
        if (tid < st) { s1[tid] += s1[tid + st]; s2[tid] += s2[tid + st]; }
        __syncthreads();
    }
    const float mean = s1[0] * (1.f / DD);
    const float var = s2[0] * (1.f / DD) - mean * mean;
    const float rstd = rsqrtf(var + 1e-5f);

    float4 ov;
    ov.x = g[d + 0] * (v0 - mean) * rstd + b[d + 0];
    ov.y = g[d + 1] * (v1 - mean) * rstd + b[d + 1];
    ov.z = g[d + 2] * (v2 - mean) * rstd + b[d + 2];
    ov.w = g[d + 3] * (v3 - mean) * rstd + b[d + 3];
    *(float4*)(out + (size_t)r * DD + d) = ov;
}

// ------------- tiled rows for cross-attn out-projection (batched) --------
__global__ void tilefe_kernel(const float* __restrict__ fev, float* __restrict__ A)
{
    const int bx = blockIdx.x;
    const int z = bx >> 8;
    const int rl = bx & 255;
    const int n = rl >> 4;
    const int g = rl & 15;
    const int d = threadIdx.x * 4;
    const float* src = fev + (size_t)z * NB * DD + (size_t)n * DD + g * 64;
    float4 v = *(const float4*)(src + (d & 63));
    *(float4*)(A + (size_t)z * NB * 16 * DD + (size_t)rl * DD + d) = v;
}

// ---------------- launch --------------------------------------------------
extern "C" void kernel_launch(void* const* d_in, const int* in_sizes, int n_in,
                              void* d_out, int out_size)
{
    const float* features = (const float*)d_in[0];
    const int*   captions = (const int*)d_in[1];
    const float* feat_W   = (const float*)d_in[2];
    const float* feat_b   = (const float*)d_in[3];
    const float* cap_emb  = (const float*)d_in[4];
    const float* pos_emb  = (const float*)d_in[5];
    const float* sa_Wq = (const float*)d_in[6];
    const float* sa_Wk = (const float*)d_in[7];
    const float* sa_Wv = (const float*)d_in[8];
    const float* sa_Wo = (const float*)d_in[9];
    const float* sa_bo = (const float*)d_in[10];
    const float* sa_g  = (const float*)d_in[11];
    const float* sa_b  = (const float*)d_in[12];
    const float* ca_Wv = (const float*)d_in[15];
    const float* ca_Wo = (const float*)d_in[16];
    const float* ca_bo = (const float*)d_in[17];
    const float* ca_g  = (const float*)d_in[18];
    const float* ca_b  = (const float*)d_in[19];
    const float* ff_W1 = (const float*)d_in[20];
    const float* ff_b1 = (const float*)d_in[21];
    const float* ff_W2 = (const float*)d_in[22];
    const float* ff_b2 = (const float*)d_in[23];
    const float* ff_g  = (const float*)d_in[24];
    const float* ff_b  = (const float*)d_in[25];
    const float* score_W = (const float*)d_in[26];
    const float* score_b = (const float*)d_in[27];
    float* out = (float*)d_out;

    float *px, *pq, *pk, *pv, *pt, *pattn, *ph, *pfe, *pfev, *pzt, *pz;
    cudaGetSymbolAddress((void**)&px,    g_x);
    cudaGetSymbolAddress((void**)&pq,    g_q);
    cudaGetSymbolAddress((void**)&pk,    g_k);
    cudaGetSymbolAddress((void**)&pv,    g_v);
    cudaGetSymbolAddress((void**)&pt,    g_t);
    cudaGetSymbolAddress((void**)&pattn, g_attn);
    cudaGetSymbolAddress((void**)&ph,    g_h);
    cudaGetSymbolAddress((void**)&pfe,   g_fe);
    cudaGetSymbolAddress((void**)&pfev,  g_fev);
    cudaGetSymbolAddress((void**)&pzt,   g_ztile);
    cudaGetSymbolAddress((void**)&pz,    g_z);

    static bool attr_set = false;
    if (!attr_set) {
        cudaFuncSetAttribute(flash_attn, cudaFuncAttributeMaxDynamicSharedMemorySize, FA_SMEM);
        attr_set = true;
    }

    // features -> fe  (M=16, SIMT path)
    sgemm<false, true><<<dim3(DD / BN, 1), 256>>>(features, feat_W, feat_b, pfe, NB, DD, DIN);

    // embedding
    embed_kernel<<<ROWS, 256>>>(captions, cap_emb, pos_emb, px);

    // cross-attention contributions for all layers
    sgemm_bz<false><<<dim3(DD / BN, 1, LL), 256>>>(pfe, ca_Wv, nullptr, pfev,
                                                   NB, DD, DD,
                                                   0, (size_t)DD * DD, 0, (size_t)NB * DD);
    tilefe_kernel<<<LL * NB * 16, 256>>>(pfev, pzt);
    sgemm_bz<true><<<dim3(DD / BN, 2, LL), 256>>>(pzt, ca_Wo, ca_bo, pz,
                                                  NB * 16, DD, DD,
                                                  (size_t)NB * 16 * DD, (size_t)DD * DD,
                                                  DD, (size_t)NB * 16 * DD);

    const dim3 gP(DD / 128, ROWS / 128);     // 8 x 64
    const dim3 gF(FFD / 128, ROWS / 128);    // 16 x 64

    for (int i = 0; i < LL; i++) {
        const float* Wq = sa_Wq + (size_t)i * DD * DD;
        const float* Wk = sa_Wk + (size_t)i * DD * DD;
        const float* Wv = sa_Wv + (size_t)i * DD * DD;
        const float* Wo = sa_Wo + (size_t)i * DD * DD;

        hgemm<false, false><<<gP, 256>>>(px, Wq, nullptr, pq, ROWS, DD, DD);
        hgemm<false, false><<<gP, 256>>>(px, Wk, nullptr, pk, ROWS, DD, DD);
        hgemm<false, false><<<gP, 256>>>(px, Wv, nullptr, pv, ROWS, DD, DD);
        flash_attn<<<NB * HH * 4, 256, FA_SMEM>>>(pq, pk, pv, pattn);
        hgemm<false, true><<<gP, 256>>>(pattn, Wo, sa_bo + (size_t)i * DD, pt, ROWS, DD, DD);
        ln_kernel<<<ROWS, 256>>>(px, pt, sa_g + (size_t)i * DD, sa_b + (size_t)i * DD, px, 0);

        ln_kernel<<<ROWS, 256>>>(px, pz + (size_t)i * NB * 16 * DD,
                                 ca_g + (size_t)i * DD, ca_b + (size_t)i * DD, px, 1);

        hgemm<true, true><<<gF, 256>>>(px, ff_W1 + (size_t)i * DD * FFD,
                                       ff_b1 + (size_t)i * FFD, ph, ROWS, FFD, DD);
        hgemm<false, true><<<gP, 256>>>(ph, ff_W2 + (size_t)i * FFD * DD,
                                        ff_b2 + (size_t)i * DD, pt, ROWS, DD, FFD);
        ln_kernel<<<ROWS, 256>>>(px, pt, ff_g + (size_t)i * DD, ff_b + (size_t)i * DD, px, 0);
    }

    // final vocab projection
    hgemm<false, true><<<dim3((VV + 127) / 128, ROWS / 128), 256>>>(
        px, score_W, score_b, out, ROWS, VV, DD);
}

// round 7
// speedup vs baseline: 6.8404x; 1.6057x over previous
#include <cuda_runtime.h>
#include <cuda_bf16.h>
#include <cuda_fp16.h>
#include <cstdio>
#include <cstdint>

// Problem constants
#define NB   16
#define TT   512
#define VV   10000
#define DIN  2048
#define DD   1024
#define HH   16
#define LL   4
#define FFD  2048
#define DHD  64
#define ROWS (NB*TT)          // 8192
#define NEGF (-1e8f)

// ---------------- device scratch ----------------
__device__ float g_x[ROWS * DD];
__device__ float g_q[ROWS * DD];
__device__ float g_k[ROWS * DD];
__device__ float g_v[ROWS * DD];
__device__ float g_t[ROWS * DD];
__device__ float g_h[ROWS * FFD];         // (f32 FF hidden no longer used, kept small set)
__device__ float g_fe[NB * DD];
__device__ float g_fev[LL * NB * DD];
__device__ float g_ztile[LL * NB * 16 * DD];
__device__ float g_z[LL * NB * 16 * DD];

// fp16 side
__device__ __half g_xh[ROWS * DD];        // activations (GEMM A)
__device__ __half g_attnh[ROWS * DD];     // attention output (quirk layout)
__device__ __half g_hh[ROWS * FFD];       // FF hidden (fp16)
__device__ __half g_wqh[LL * DD * DD];
__device__ __half g_wkh[LL * DD * DD];
__device__ __half g_wvh[LL * DD * DD];
__device__ __half g_woh[LL * DD * DD];
__device__ __half g_w1h[LL * DD * FFD];
__device__ __half g_w2h[LL * FFD * DD];
__device__ __half g_wsh[DD * VV];

// ---------------- small helpers ----------------
__device__ __forceinline__ unsigned h2_as_u32(__half2 h) {
    return *(unsigned*)&h;
}

// ---------------- f32 -> f16 conversion (n % 4 == 0) ----------------
__global__ void f2h_kernel(const float* __restrict__ src, __half* __restrict__ dst, int n)
{
    int i = (blockIdx.x * blockDim.x + threadIdx.x) * 4;
    if (i < n) {
        float4 v = *(const float4*)(src + i);
        uint2 o;
        o.x = h2_as_u32(__floats2half2_rn(v.x, v.y));
        o.y = h2_as_u32(__floats2half2_rn(v.z, v.w));
        *(uint2*)(dst + i) = o;
    }
}

// ==================== fp16 tensor-core GEMM (mma.sync m16n8k16) ==========
// C = A(MxK) * B(KxN) [+bias] [ReLU]. A,B fp16. M%128==0, K%16==0, Nn%4==0.
// 256 threads = 8 warps (2x4), warp tile 64x32, K-chunk = 16, double buffer.
// smem rows: 16 halves as 8 half2 words; phys word p(w,row)=((w&3)^(row&3))*2+(w>>2)

template<bool RELU, bool BIAS, bool HOUT>
__global__ __launch_bounds__(256) void hgemm(
    const __half* __restrict__ A, const __half* __restrict__ B,
    const float* __restrict__ bias, void* __restrict__ Cv,
    int M, int Nn, int K)
{
    __shared__ unsigned As[2][128 * 8];
    __shared__ unsigned Bs[2][128 * 8];

    const int tid  = threadIdx.x;
    const int lane = tid & 31;
    const int warp = tid >> 5;
    const int row0 = blockIdx.y * 128;
    const int col0 = blockIdx.x * 128;
    const int wm = (warp >> 2) * 64;
    const int wn = (warp & 3) * 32;
    const int g  = lane >> 2;
    const int tq = lane & 3;

    // A producer: row = tid>>1, k-half ah = tid&1 (8 halves = uint4)
    const int arow = tid >> 1;
    const int ah   = tid & 1;
    // B producer: k-pair wk = tid&7, n base = (tid>>3)*4
    const int wk  = tid & 7;
    const int bn0 = (tid >> 3) * 4;

    const __half* aptr  = A + (size_t)(row0 + arow) * K + ah * 8;
    const __half* b0ptr = B + (size_t)(2 * wk) * Nn + col0 + bn0;
    const __half* b1ptr = B + (size_t)(2 * wk + 1) * Nn + col0 + bn0;
    const bool bvalid = (col0 + bn0 + 3) < Nn;   // Nn % 4 == 0 -> no straddle

    float acc[4][4][4];
#pragma unroll
    for (int i = 0; i < 4; i++)
#pragma unroll
        for (int j = 0; j < 4; j++)
#pragma unroll
            for (int c = 0; c < 4; c++) acc[i][j][c] = 0.f;

    const int nk = K >> 4;

    uint4 av;
    uint2 r0, r1;
    // prologue: chunk 0
    av = *(const uint4*)aptr;
    r0 = make_uint2(0u, 0u); r1 = make_uint2(0u, 0u);
    if (bvalid) { r0 = *(const uint2*)b0ptr; r1 = *(const uint2*)b1ptr; }

#define STASH(BUF)                                                              \
    do {                                                                        \
        const int rm = arow & 3;                                                \
        unsigned* ar = &As[BUF][arow * 8];                                      \
        ar[((0 ^ rm) << 1) + ah] = av.x;                                        \
        ar[((1 ^ rm) << 1) + ah] = av.y;                                        \
        ar[((2 ^ rm) << 1) + ah] = av.z;                                        \
        ar[((3 ^ rm) << 1) + ah] = av.w;                                        \
        unsigned wb[4];                                                         \
        wb[0] = __byte_perm(r0.x, r1.x, 0x5410);                                \
        wb[1] = __byte_perm(r0.x, r1.x, 0x7632);                                \
        wb[2] = __byte_perm(r0.y, r1.y, 0x5410);                                \
        wb[3] = __byte_perm(r0.y, r1.y, 0x7632);                                \
        _Pragma("unroll")                                                       \
        for (int e = 0; e < 4; e++) {                                           \
            const int n = bn0 + e;                                              \
            const int p = (((wk ^ n) & 3) << 1) + (wk >> 2);                    \
            Bs[BUF][n * 8 + p] = wb[e];                                         \
        }                                                                       \
    } while (0)

    STASH(0);
    __syncthreads();

    for (int it = 0; it < nk; it++) {
        const int buf = it & 1;
        const bool more = (it + 1) < nk;
        if (more) {
            av = *(const uint4*)(aptr + (size_t)(it + 1) * 16);
            r0 = make_uint2(0u, 0u); r1 = make_uint2(0u, 0u);
            if (bvalid) {
                r0 = *(const uint2*)(b0ptr + (size_t)(it + 1) * 16 * Nn);
                r1 = *(const uint2*)(b1ptr + (size_t)(it + 1) * 16 * Nn);
            }
        }

        unsigned af[4][4], bf[4][2];
#pragma unroll
        for (int i = 0; i < 4; i++) {
            const int ra = wm + i * 16 + g;
            const int rb = ra + 8;
            const uint2 pA = *(const uint2*)&As[buf][ra * 8 + ((tq ^ (ra & 3)) << 1)];
            const uint2 pB = *(const uint2*)&As[buf][rb * 8 + ((tq ^ (rb & 3)) << 1)];
            af[i][0] = pA.x; af[i][2] = pA.y;
            af[i][1] = pB.x; af[i][3] = pB.y;
        }
#pragma unroll
        for (int j = 0; j < 4; j++) {
            const int nr = wn + j * 8 + g;
            const uint2 p = *(const uint2*)&Bs[buf][nr * 8 + ((tq ^ (nr & 3)) << 1)];
            bf[j][0] = p.x; bf[j][1] = p.y;
        }
#pragma unroll
        for (int i = 0; i < 4; i++)
#pragma unroll
            for (int j = 0; j < 4; j++) {
                asm volatile(
                    "mma.sync.aligned.m16n8k16.row.col.f32.f16.f16.f32 "
                    "{%0,%1,%2,%3}, {%4,%5,%6,%7}, {%8,%9}, {%0,%1,%2,%3};"
                    : "+f"(acc[i][j][0]), "+f"(acc[i][j][1]),
                      "+f"(acc[i][j][2]), "+f"(acc[i][j][3])
                    : "r"(af[i][0]), "r"(af[i][1]), "r"(af[i][2]), "r"(af[i][3]),
                      "r"(bf[j][0]), "r"(bf[j][1]));
            }

        if (more) {
            STASH(buf ^ 1);
            __syncthreads();
        }
    }
#undef STASH

    // epilogue
#pragma unroll
    for (int i = 0; i < 4; i++) {
        const int r0r = row0 + wm + i * 16 + g;
#pragma unroll
        for (int j = 0; j < 4; j++) {
            const int col = col0 + wn + j * 8 + tq * 2;
            if (col >= Nn) continue;
            float2 bsv = make_float2(0.f, 0.f);
            if (BIAS) bsv = *(const float2*)(bias + col);
            float2 v0, v1;
            v0.x = acc[i][j][0] + (BIAS ? bsv.x : 0.f);
            v0.y = acc[i][j][1] + (BIAS ? bsv.y : 0.f);
            v1.x = acc[i][j][2] + (BIAS ? bsv.x : 0.f);
            v1.y = acc[i][j][3] + (BIAS ? bsv.y : 0.f);
            if (RELU) {
                v0.x = fmaxf(v0.x, 0.f); v0.y = fmaxf(v0.y, 0.f);
                v1.x = fmaxf(v1.x, 0.f); v1.y = fmaxf(v1.y, 0.f);
            }
            if (HOUT) {
                __half* C = (__half*)Cv;
                *(unsigned*)(C + (size_t)r0r * Nn + col)       = h2_as_u32(__floats2half2_rn(v0.x, v0.y));
                *(unsigned*)(C + (size_t)(r0r + 8) * Nn + col) = h2_as_u32(__floats2half2_rn(v1.x, v1.y));
            } else {
                float* C = (float*)Cv;
                *(float2*)(C + (size_t)r0r * Nn + col) = v0;
                *(float2*)(C + (size_t)(r0r + 8) * Nn + col) = v1;
            }
        }
    }
}

// ---------------- SIMT SGEMM (small M cases only) -------------------------
#define BM 128
#define BN 128
#define BK 8
#define TM 8
#define TN 8

template<bool RELU, bool BIAS>
__global__ void sgemm(const float* __restrict__ A, const float* __restrict__ B,
                      const float* __restrict__ bias, float* __restrict__ C,
                      int M, int Nn, int K)
{
    __shared__ float As[BK][BM];
    __shared__ float Bs[BK][BN];
    const int tid = threadIdx.x;
    const int row0 = blockIdx.y * BM;
    const int col0 = blockIdx.x * BN;
    const int tx = tid % 16;
    const int ty = tid / 16;

    float acc[TM][TN];
#pragma unroll
    for (int i = 0; i < TM; i++)
#pragma unroll
        for (int j = 0; j < TN; j++) acc[i][j] = 0.f;

    const int aRow = tid >> 1;
    const int aCol = (tid & 1) * 4;
    const int bRow = tid >> 5;
    const int bCol = (tid & 31) * 4;

    for (int k0 = 0; k0 < K; k0 += BK) {
        int gr = row0 + aRow;
        float4 av = make_float4(0.f, 0.f, 0.f, 0.f);
        if (gr < M) av = *(const float4*)(A + (size_t)gr * K + k0 + aCol);
        As[aCol + 0][aRow] = av.x;
        As[aCol + 1][aRow] = av.y;
        As[aCol + 2][aRow] = av.z;
        As[aCol + 3][aRow] = av.w;

        int gc = col0 + bCol;
        float4 bv = make_float4(0.f, 0.f, 0.f, 0.f);
        if (gc < Nn) bv = *(const float4*)(B + (size_t)(k0 + bRow) * Nn + gc);
        *(float4*)&Bs[bRow][bCol] = bv;
        __syncthreads();

#pragma unroll
        for (int kk = 0; kk < BK; kk++) {
            float ar[TM], br[TN];
#pragma unroll
            for (int i = 0; i < TM; i++) ar[i] = As[kk][ty * TM + i];
#pragma unroll
            for (int j = 0; j < TN; j++) br[j] = Bs[kk][tx * TN + j];
#pragma unroll
            for (int i = 0; i < TM; i++)
#pragma unroll
                for (int j = 0; j < TN; j++)
                    acc[i][j] = fmaf(ar[i], br[j], acc[i][j]);
        }
        __syncthreads();
    }

#pragma unroll
    for (int i = 0; i < TM; i++) {
        int r = row0 + ty * TM + i;
        if (r >= M) continue;
#pragma unroll
        for (int j = 0; j < TN; j++) {
            int c = col0 + tx * TN + j;
            if (c >= Nn) continue;
            float v = acc[i][j];
            if (BIAS) v += bias[c];
            if (RELU) v = fmaxf(v, 0.f);
            C[(size_t)r * Nn + c] = v;
        }
    }
}

template<bool BIAS>
__global__ void sgemm_bz(const float* __restrict__ A0, const float* __restrict__ B0,
                         const float* __restrict__ bias0, float* __restrict__ C0,
                         int M, int Nn, int K,
                         size_t sA, size_t sB, size_t sBias, size_t sC)
{
    const int z = blockIdx.z;
    const float* A = A0 + sA * z;
    const float* B = B0 + sB * z;
    const float* bias = BIAS ? (bias0 + sBias * z) : nullptr;
    float* C = C0 + sC * z;

    __shared__ float As[BK][BM];
    __shared__ float Bs[BK][BN];
    const int tid = threadIdx.x;
    const int row0 = blockIdx.y * BM;
    const int col0 = blockIdx.x * BN;
    const int tx = tid % 16;
    const int ty = tid / 16;

    float acc[TM][TN];
#pragma unroll
    for (int i = 0; i < TM; i++)
#pragma unroll
        for (int j = 0; j < TN; j++) acc[i][j] = 0.f;

    const int aRow = tid >> 1;
    const int aCol = (tid & 1) * 4;
    const int bRow = tid >> 5;
    const int bCol = (tid & 31) * 4;

    for (int k0 = 0; k0 < K; k0 += BK) {
        int gr = row0 + aRow;
        float4 av = make_float4(0.f, 0.f, 0.f, 0.f);
        if (gr < M) av = *(const float4*)(A + (size_t)gr * K + k0 + aCol);
        As[aCol + 0][aRow] = av.x;
        As[aCol + 1][aRow] = av.y;
        As[aCol + 2][aRow] = av.z;
        As[aCol + 3][aRow] = av.w;

        int gc = col0 + bCol;
        float4 bv = make_float4(0.f, 0.f, 0.f, 0.f);
        if (gc < Nn) bv = *(const float4*)(B + (size_t)(k0 + bRow) * Nn + gc);
        *(float4*)&Bs[bRow][bCol] = bv;
        __syncthreads();

#pragma unroll
        for (int kk = 0; kk < BK; kk++) {
            float ar[TM], br[TN];
#pragma unroll
            for (int i = 0; i < TM; i++) ar[i] = As[kk][ty * TM + i];
#pragma unroll
            for (int j = 0; j < TN; j++) br[j] = Bs[kk][tx * TN + j];
#pragma unroll
            for (int i = 0; i < TM; i++)
#pragma unroll
                for (int j = 0; j < TN; j++)
                    acc[i][j] = fmaf(ar[i], br[j], acc[i][j]);
        }
        __syncthreads();
    }

#pragma unroll
    for (int i = 0; i < TM; i++) {
        int r = row0 + ty * TM + i;
        if (r >= M) continue;
#pragma unroll
        for (int j = 0; j < TN; j++) {
            int c = col0 + tx * TN + j;
            if (c >= Nn) continue;
            float v = acc[i][j];
            if (BIAS) v += bias[c];
            C[(size_t)r * Nn + c] = v;
        }
    }
}

// ---------------- embedding (dual write f32 + f16) ------------
__global__ void embed_kernel(const int* __restrict__ cap, const float* __restrict__ emb,
                             const float* __restrict__ pos, float* __restrict__ X,
                             __half* __restrict__ Xh)
{
    int r = blockIdx.x;
    int t = r & (TT - 1);
    int c = cap[r];
    int d = threadIdx.x * 4;
    float4 e = *(const float4*)(emb + (size_t)c * DD + d);
    float4 p = *(const float4*)(pos + (size_t)t * DD + d);
    e.x += p.x; e.y += p.y; e.z += p.z; e.w += p.w;
    *(float4*)(X + (size_t)r * DD + d) = e;
    uint2 hv;
    hv.x = h2_as_u32(__floats2half2_rn(e.x, e.y));
    hv.y = h2_as_u32(__floats2half2_rn(e.z, e.w));
    *(uint2*)(Xh + (size_t)r * DD + d) = hv;
}

// ---------------- flash attention (fp16 output) ---------------------------
#define QS_STRIDE 132
#define KS_STRIDE 68
#define PS_STRIDE 132
#define FA_SMEM ((64*QS_STRIDE + 64*KS_STRIDE + 64*64 + 64*PS_STRIDE) * sizeof(float))

__global__ __launch_bounds__(256) void flash_attn(
    const float* __restrict__ Q, const float* __restrict__ K,
    const float* __restrict__ V, __half* __restrict__ O)
{
    extern __shared__ float sh[];
    float* Qs = sh;
    float* Ks = Qs + 64 * QS_STRIDE;
    float* Vs = Ks + 64 * KS_STRIDE;
    float* Ps = Vs + 64 * 64;

    const int bid = blockIdx.x;
    const int qt = bid & 3;
    const int h  = (bid >> 2) & 15;
    const int n  = bid >> 6;
    const int q0 = qt * 128;

    const int tid = threadIdx.x;
    const int tx = tid & 15;
    const int ty = tid >> 4;

    {
        const int d4 = (tid & 15) * 4;
        const int r0 = tid >> 4;
#pragma unroll
        for (int rr = 0; rr < 8; rr++) {
            const int r = r0 + rr * 16;
            const float4 v = *(const float4*)(Q + ((size_t)(n * TT + q0 + r)) * DD + h * DHD + d4);
            Qs[(d4 + 0) * QS_STRIDE + r] = v.x;
            Qs[(d4 + 1) * QS_STRIDE + r] = v.y;
            Qs[(d4 + 2) * QS_STRIDE + r] = v.z;
            Qs[(d4 + 3) * QS_STRIDE + r] = v.w;
        }
    }

    float o[8][4];
    float m[8], l[8];
#pragma unroll
    for (int i = 0; i < 8; i++) {
        m[i] = -1e30f; l[i] = 0.f;
#pragma unroll
        for (int j = 0; j < 4; j++) o[i][j] = 0.f;
    }

    const int ntiles = (q0 + 128) / 64;
    for (int t = 0; t < ntiles; t++) {
        const int j0 = t * 64;
        __syncthreads();
        {
            const int d4 = (tid & 15) * 4;
            const int c0 = tid >> 4;
#pragma unroll
            for (int cc = 0; cc < 4; cc++) {
                const int c = c0 + cc * 16;
                const size_t grow = ((size_t)(n * TT + j0 + c)) * DD + h * DHD + d4;
                const float4 kv = *(const float4*)(K + grow);
                Ks[(d4 + 0) * KS_STRIDE + c] = kv.x;
                Ks[(d4 + 1) * KS_STRIDE + c] = kv.y;
                Ks[(d4 + 2) * KS_STRIDE + c] = kv.z;
                Ks[(d4 + 3) * KS_STRIDE + c] = kv.w;
                const float4 vv = *(const float4*)(V + grow);
                *(float4*)(Vs + c * 64 + d4) = vv;
            }
        }
        __syncthreads();

        float s[8][4];
#pragma unroll
        for (int i = 0; i < 8; i++)
#pragma unroll
            for (int j = 0; j < 4; j++) s[i][j] = 0.f;
#pragma unroll 4
        for (int kk = 0; kk < 64; kk++) {
            float ar[8], br[4];
            *(float4*)ar       = *(const float4*)(Qs + kk * QS_STRIDE + ty * 8);
            *(float4*)(ar + 4) = *(const float4*)(Qs + kk * QS_STRIDE + ty * 8 + 4);
            *(float4*)br       = *(const float4*)(Ks + kk * KS_STRIDE + tx * 4);
#pragma unroll
            for (int i = 0; i < 8; i++)
#pragma unroll
                for (int j = 0; j < 4; j++) s[i][j] = fmaf(ar[i], br[j], s[i][j]);
        }

        float tmax[8];
#pragma unroll
        for (int i = 0; i < 8; i++) {
            const int q = q0 + ty * 8 + i;
            tmax[i] = -1e30f;
#pragma unroll
            for (int j = 0; j < 4; j++) {
                const int kidx = j0 + tx * 4 + j;
                float v = (kidx <= q) ? s[i][j] * 0.125f : -1e30f;
                s[i][j] = v;
                tmax[i] = fmaxf(tmax[i], v);
            }
        }
#pragma unroll
        for (int st = 1; st < 16; st <<= 1)
#pragma unroll
            for (int i = 0; i < 8; i++)
                tmax[i] = fmaxf(tmax[i], __shfl_xor_sync(0xffffffffu, tmax[i], st));

        float psum[8];
#pragma unroll
        for (int i = 0; i < 8; i++) {
            const float mn = fmaxf(m[i], tmax[i]);
            const float sc = __expf(m[i] - mn);
            m[i] = mn;
            l[i] *= sc;
#pragma unroll
            for (int j = 0; j < 4; j++) o[i][j] *= sc;
            float ps = 0.f;
#pragma unroll
            for (int j = 0; j < 4; j++) {
                const float p = __expf(s[i][j] - mn);
                s[i][j] = p;
                ps += p;
            }
            psum[i] = ps;
        }
#pragma unroll
        for (int st = 1; st < 16; st <<= 1)
#pragma unroll
            for (int i = 0; i < 8; i++)
                psum[i] += __shfl_xor_sync(0xffffffffu, psum[i], st);
#pragma unroll
        for (int i = 0; i < 8; i++) l[i] += psum[i];

#pragma unroll
        for (int j = 0; j < 4; j++) {
            const int k = tx * 4 + j;
#pragma unroll
            for (int i = 0; i < 8; i++)
                Ps[k * PS_STRIDE + ty * 8 + i] = s[i][j];
        }
        __syncthreads();

#pragma unroll 4
        for (int k = 0; k < 64; k++) {
            float ar[8], bv[4];
            *(float4*)ar       = *(const float4*)(Ps + k * PS_STRIDE + ty * 8);
            *(float4*)(ar + 4) = *(const float4*)(Ps + k * PS_STRIDE + ty * 8 + 4);
            *(float4*)bv       = *(const float4*)(Vs + k * 64 + tx * 4);
#pragma unroll
            for (int i = 0; i < 8; i++)
#pragma unroll
                for (int j = 0; j < 4; j++) o[i][j] = fmaf(ar[i], bv[j], o[i][j]);
        }
    }

#pragma unroll
    for (int i = 0; i < 8; i++) {
        const int q = q0 + ty * 8 + i;
        const float inv = 1.f / l[i];
        uint2 hv;
        hv.x = h2_as_u32(__floats2half2_rn(o[i][0] * inv, o[i][1] * inv));
        hv.y = h2_as_u32(__floats2half2_rn(o[i][2] * inv, o[i][3] * inv));
        *(uint2*)(O + ((size_t)((n * HH + h) * TT + q)) * DHD + tx * 4) = hv;
    }
}

// ---------------- residual + LayerNorm (dual write) ----------------------
__global__ void ln_kernel(const float* __restrict__ X, const float* __restrict__ Rsd,
                          const float* __restrict__ g, const float* __restrict__ b,
                          float* __restrict__ out, __half* __restrict__ outh, int mode)
{
    const int r = blockIdx.x;
    const int tid = threadIdx.x;
    size_t rr;
    if (mode == 0) rr = (size_t)r;
    else {
        int n = r >> 9;
        int s = r & (TT - 1);
        rr = (size_t)(n * 16 + (s >> 5));
    }
    const float* xr = X + (size_t)r * DD;
    const float* dr = Rsd + rr * DD;
    const int d = tid * 4;
    float4 xv = *(const float4*)(xr + d);
    float4 dv = *(const float4*)(dr + d);
    float v0 = xv.x + dv.x, v1 = xv.y + dv.y, v2 = xv.z + dv.z, v3 = xv.w + dv.w;

    __shared__ float s1[256], s2[256];
    s1[tid] = v0 + v1 + v2 + v3;
    s2[tid] = v0 * v0 + v1 * v1 + v2 * v2 + v3 * v3;
    __syncthreads();
    for (int st = 128; st > 0; st >>= 1) {
        if (tid < st) { s1[tid] += s1[tid + st]; s2[tid] += s2[tid + st]; }
        __syncthreads();
    }
    const float mean = s1[0] * (1.f / DD);
    const float var = s2[0] * (1.f / DD) - mean * mean;
    const float rstd = rsqrtf(var + 1e-5f);

    float4 ov;
    ov.x = g[d + 0] * (v0 - mean) * rstd + b[d + 0];
    ov.y = g[d + 1] * (v1 - mean) * rstd + b[d + 1];
    ov.z = g[d + 2] * (v2 - mean) * rstd + b[d + 2];
    ov.w = g[d + 3] * (v3 - mean) * rstd + b[d + 3];
    *(float4*)(out + (size_t)r * DD + d) = ov;
    uint2 hv;
    hv.x = h2_as_u32(__floats2half2_rn(ov.x, ov.y));
    hv.y = h2_as_u32(__floats2half2_rn(ov.z, ov.w));
    *(uint2*)(outh + (size_t)r * DD + d) = hv;
}

// ------------- tiled rows for cross-attn out-projection (batched) --------
__global__ void tilefe_kernel(const float* __restrict__ fev, float* __restrict__ A)
{
    const int bx = blockIdx.x;
    const int z = bx >> 8;
    const int rl = bx & 255;
    const int n = rl >> 4;
    const int g = rl & 15;
    const int d = threadIdx.x * 4;
    const float* src = fev + (size_t)z * NB * DD + (size_t)n * DD + g * 64;
    float4 v = *(const float4*)(src + (d & 63));
    *(float4*)(A + (size_t)z * NB * 16 * DD + (size_t)rl * DD + d) = v;
}

// ---------------- launch --------------------------------------------------
extern "C" void kernel_launch(void* const* d_in, const int* in_sizes, int n_in,
                              void* d_out, int out_size)
{
    const float* features = (const float*)d_in[0];
    const int*   captions = (const int*)d_in[1];
    const float* feat_W   = (const float*)d_in[2];
    const float* feat_b   = (const float*)d_in[3];
    const float* cap_emb  = (const float*)d_in[4];
    const float* pos_emb  = (const float*)d_in[5];
    const float* sa_Wq = (const float*)d_in[6];
    const float* sa_Wk = (const float*)d_in[7];
    const float* sa_Wv = (const float*)d_in[8];
    const float* sa_Wo = (const float*)d_in[9];
    const float* sa_bo = (const float*)d_in[10];
    const float* sa_g  = (const float*)d_in[11];
    const float* sa_b  = (const float*)d_in[12];
    const float* ca_Wv = (const float*)d_in[15];
    const float* ca_Wo = (const float*)d_in[16];
    const float* ca_bo = (const float*)d_in[17];
    const float* ca_g  = (const float*)d_in[18];
    const float* ca_b  = (const float*)d_in[19];
    const float* ff_W1 = (const float*)d_in[20];
    const float* ff_b1 = (const float*)d_in[21];
    const float* ff_W2 = (const float*)d_in[22];
    const float* ff_b2 = (const float*)d_in[23];
    const float* ff_g  = (const float*)d_in[24];
    const float* ff_b  = (const float*)d_in[25];
    const float* score_W = (const float*)d_in[26];
    const float* score_b = (const float*)d_in[27];
    float* out = (float*)d_out;

    float *px, *pq, *pk, *pv, *pt, *pfe, *pfev, *pzt, *pz;
    __half *pxh, *pattnh, *phh, *pwqh, *pwkh, *pwvh, *pwoh, *pw1h, *pw2h, *pwsh;
    cudaGetSymbolAddress((void**)&px,    g_x);
    cudaGetSymbolAddress((void**)&pq,    g_q);
    cudaGetSymbolAddress((void**)&pk,    g_k);
    cudaGetSymbolAddress((void**)&pv,    g_v);
    cudaGetSymbolAddress((void**)&pt,    g_t);
    cudaGetSymbolAddress((void**)&pfe,   g_fe);
    cudaGetSymbolAddress((void**)&pfev,  g_fev);
    cudaGetSymbolAddress((void**)&pzt,   g_ztile);
    cudaGetSymbolAddress((void**)&pz,    g_z);
    cudaGetSymbolAddress((void**)&pxh,    g_xh);
    cudaGetSymbolAddress((void**)&pattnh, g_attnh);
    cudaGetSymbolAddress((void**)&phh,    g_hh);
    cudaGetSymbolAddress((void**)&pwqh,   g_wqh);
    cudaGetSymbolAddress((void**)&pwkh,   g_wkh);
    cudaGetSymbolAddress((void**)&pwvh,   g_wvh);
    cudaGetSymbolAddress((void**)&pwoh,   g_woh);
    cudaGetSymbolAddress((void**)&pw1h,   g_w1h);
    cudaGetSymbolAddress((void**)&pw2h,   g_w2h);
    cudaGetSymbolAddress((void**)&pwsh,   g_wsh);

    static bool attr_set = false;
    if (!attr_set) {
        cudaFuncSetAttribute(flash_attn, cudaFuncAttributeMaxDynamicSharedMemorySize, FA_SMEM);
        attr_set = true;
    }

    // ---- weight conversions (once per launch; deterministic) ----
    {
        const int tb = 256;
        const int nDD = LL * DD * DD;
        f2h_kernel<<<(nDD / 4 + tb - 1) / tb, tb>>>(sa_Wq, pwqh, nDD);
        f2h_kernel<<<(nDD / 4 + tb - 1) / tb, tb>>>(sa_Wk, pwkh, nDD);
        f2h_kernel<<<(nDD / 4 + tb - 1) / tb, tb>>>(sa_Wv, pwvh, nDD);
        f2h_kernel<<<(nDD / 4 + tb - 1) / tb, tb>>>(sa_Wo, pwoh, nDD);
        const int nFF = LL * DD * FFD;
        f2h_kernel<<<(nFF / 4 + tb - 1) / tb, tb>>>(ff_W1, pw1h, nFF);
        f2h_kernel<<<(nFF / 4 + tb - 1) / tb, tb>>>(ff_W2, pw2h, nFF);
        const int nS = DD * VV;
        f2h_kernel<<<(nS / 4 + tb - 1) / tb, tb>>>(score_W, pwsh, nS);
    }

    // features -> fe  (M=16, SIMT path)
    sgemm<false, true><<<dim3(DD / BN, 1), 256>>>(features, feat_W, feat_b, pfe, NB, DD, DIN);

    // embedding (f32 + f16)
    embed_kernel<<<ROWS, 256>>>(captions, cap_emb, pos_emb, px, pxh);

    // cross-attention contributions for all layers (f32 SIMT path)
    sgemm_bz<false><<<dim3(DD / BN, 1, LL), 256>>>(pfe, ca_Wv, nullptr, pfev,
                                                   NB, DD, DD,
                                                   0, (size_t)DD * DD, 0, (size_t)NB * DD);
    tilefe_kernel<<<LL * NB * 16, 256>>>(pfev, pzt);
    sgemm_bz<true><<<dim3(DD / BN, 2, LL), 256>>>(pzt, ca_Wo, ca_bo, pz,
                                                  NB * 16, DD, DD,
                                                  (size_t)NB * 16 * DD, (size_t)DD * DD,
                                                  DD, (size_t)NB * 16 * DD);

    const dim3 gP(DD / 128, ROWS / 128);     // 8 x 64
    const dim3 gF(FFD / 128, ROWS / 128);    // 16 x 64

    for (int i = 0; i < LL; i++) {
        hgemm<false, false, false><<<gP, 256>>>(pxh, pwqh + (size_t)i * DD * DD, nullptr, pq, ROWS, DD, DD);
        hgemm<false, false, false><<<gP, 256>>>(pxh, pwkh + (size_t)i * DD * DD, nullptr, pk, ROWS, DD, DD);
        hgemm<false, false, false><<<gP, 256>>>(pxh, pwvh + (size_t)i * DD * DD, nullptr, pv, ROWS, DD, DD);
        flash_attn<<<NB * HH * 4, 256, FA_SMEM>>>(pq, pk, pv, pattnh);
        hgemm<false, true, false><<<gP, 256>>>(pattnh, pwoh + (size_t)i * DD * DD,
                                               sa_bo + (size_t)i * DD, pt, ROWS, DD, DD);
        ln_kernel<<<ROWS, 256>>>(px, pt, sa_g + (size_t)i * DD, sa_b + (size_t)i * DD, px, pxh, 0);

        ln_kernel<<<ROWS, 256>>>(px, pz + (size_t)i * NB * 16 * DD,
                                 ca_g + (size_t)i * DD, ca_b + (size_t)i * DD, px, pxh, 1);

        hgemm<true, true, true><<<gF, 256>>>(pxh, pw1h + (size_t)i * DD * FFD,
                                             ff_b1 + (size_t)i * FFD, phh, ROWS, FFD, DD);
        hgemm<false, true, false><<<gP, 256>>>(phh, pw2h + (size_t)i * FFD * DD,
                                               ff_b2 + (size_t)i * DD, pt, ROWS, DD, FFD);
        ln_kernel<<<ROWS, 256>>>(px, pt, ff_g + (size_t)i * DD, ff_b + (size_t)i * DD, px, pxh, 0);
    }

    // final vocab projection
    hgemm<false, true, false><<<dim3((VV + 127) / 128, ROWS / 128), 256>>>(
        pxh, pwsh, score_b, out, ROWS, VV, DD);
}

// round 8
// speedup vs baseline: 11.1408x; 1.6287x over previous
#include <cuda_runtime.h>
#include <cuda_bf16.h>
#include <cuda_fp16.h>
#include <cstdio>
#include <cstdint>

// Problem constants
#define NB   16
#define TT   512
#define VV   10000
#define DIN  2048
#define DD   1024
#define HH   16
#define LL   4
#define FFD  2048
#define DHD  64
#define ROWS (NB*TT)          // 8192
#define NEGF (-1e8f)

// ---------------- device scratch ----------------
__device__ float g_x[ROWS * DD];
__device__ float g_q[ROWS * DD];
__device__ float g_k[ROWS * DD];
__device__ float g_v[ROWS * DD];
__device__ float g_t[ROWS * DD];
__device__ float g_fe[NB * DD];
__device__ float g_fev[LL * NB * DD];
__device__ float g_ztile[LL * NB * 16 * DD];
__device__ float g_z[LL * NB * 16 * DD];

// fp16 side
__device__ __half g_xh[ROWS * DD];
__device__ __half g_attnh[ROWS * DD];
__device__ __half g_hh[ROWS * FFD];
__device__ __half g_wqh[LL * DD * DD];
__device__ __half g_wkh[LL * DD * DD];
__device__ __half g_wvh[LL * DD * DD];
__device__ __half g_woh[LL * DD * DD];
__device__ __half g_w1h[LL * DD * FFD];
__device__ __half g_w2h[LL * FFD * DD];
__device__ __half g_wsh[DD * VV];

// ---------------- small helpers ----------------
__device__ __forceinline__ unsigned h2_as_u32(__half2 h) {
    return *(unsigned*)&h;
}
__device__ __forceinline__ uint32_t smem_u32(const void* p) {
    uint32_t a;
    asm("{ .reg .u64 t; cvta.to.shared.u64 t, %1; cvt.u32.u64 %0, t; }"
        : "=r"(a) : "l"(p));
    return a;
}

#define CPA16(dst, src) \
    asm volatile("cp.async.cg.shared.global [%0], [%1], 16;" :: "r"(dst), "l"(src))
#define CPA16Z(dst, src, sz) \
    asm volatile("cp.async.cg.shared.global [%0], [%1], 16, %2;" :: "r"(dst), "l"(src), "r"(sz))
#define CPA_COMMIT() asm volatile("cp.async.commit_group;" ::: "memory")
#define CPA_WAIT1()  asm volatile("cp.async.wait_group 1;" ::: "memory")

#define LDSM4(r0, r1, r2, r3, addr) \
    asm volatile("ldmatrix.sync.aligned.m8n8.x4.shared.b16 {%0,%1,%2,%3}, [%4];" \
                 : "=r"(r0), "=r"(r1), "=r"(r2), "=r"(r3) : "r"(addr))
#define LDSM4T(r0, r1, r2, r3, addr) \
    asm volatile("ldmatrix.sync.aligned.m8n8.x4.trans.shared.b16 {%0,%1,%2,%3}, [%4];" \
                 : "=r"(r0), "=r"(r1), "=r"(r2), "=r"(r3) : "r"(addr))

// ---------------- f32 -> f16 conversion (n % 4 == 0) ----------------
__global__ void f2h_kernel(const float* __restrict__ src, __half* __restrict__ dst, int n)
{
    int i = (blockIdx.x * blockDim.x + threadIdx.x) * 4;
    if (i < n) {
        float4 v = *(const float4*)(src + i);
        uint2 o;
        o.x = h2_as_u32(__floats2half2_rn(v.x, v.y));
        o.y = h2_as_u32(__floats2half2_rn(v.z, v.w));
        *(uint2*)(dst + i) = o;
    }
}

// ==================== fp16 GEMM: cp.async + ldmatrix + mma.m16n8k16 =======
// C = A(MxK)*B(KxN) [+bias][ReLU]. fp16 in. M%128==0, K%32==0, Nn%8==0.
// 128x128 tile, BK=32, 3-stage cp.async pipeline, 256 thr (8 warps, 64x32 each).
// A smem: 128 rows x 4 units(16B); phys unit = r*4 + (u ^ ((r&7)>>1))
// B smem: 32 k-rows x 16 n-units;  phys unit = kr*16 + (nu ^ (kr&7))

template<bool RELU, bool BIAS, bool HOUT>
__global__ __launch_bounds__(256) void hgemm(
    const __half* __restrict__ A, const __half* __restrict__ B,
    const float* __restrict__ bias, void* __restrict__ Cv,
    int M, int Nn, int K)
{
    __shared__ __align__(16) unsigned char sm[3][16384];  // 48KB: per stage A(8KB)+B(8KB)

    const int tid  = threadIdx.x;
    const int lane = tid & 31;
    const int warp = tid >> 5;
    const int row0 = blockIdx.y * 128;
    const int col0 = blockIdx.x * 128;
    const int wm = (warp >> 2) * 64;
    const int wn = (warp & 3) * 32;
    const int g  = lane >> 2;
    const int tq = lane & 3;

    const uint32_t sbase = smem_u32(sm);

    // ---- producer indices (2 A units + 2 B units per thread per chunk) ----
    int aR[2], aU[2], aPhys[2];
    int bKr[2], bNu[2], bPhys[2];
    unsigned bSz[2];
#pragma unroll
    for (int i = 0; i < 2; i++) {
        const int ul = tid + 256 * i;
        aR[i] = ul >> 2; aU[i] = ul & 3;
        aPhys[i] = aR[i] * 4 + (aU[i] ^ ((aR[i] & 7) >> 1));
        bKr[i] = ul >> 4; bNu[i] = ul & 15;
        bPhys[i] = bKr[i] * 16 + (bNu[i] ^ (bKr[i] & 7));
        bSz[i] = (col0 + bNu[i] * 8 + 7 < Nn) ? 16u : 0u;
    }

    // ---- consumer (ldmatrix) lane components ----
    const int g8 = lane >> 3, li = lane & 7;
    // A: row within warp tile
    const int rowa = wm + (g8 & 1) * 8 + li;
    const int sa = (rowa & 7) >> 1;
    const int ub = g8 >> 1;
    const uint32_t aOff0 = (uint32_t)rowa * 64 + ((unsigned)((0 + ub) ^ sa) << 4); // kk=0 (u=ub)
    const uint32_t aOff1 = (uint32_t)rowa * 64 + ((unsigned)((2 + ub) ^ sa) << 4); // kk=1 (u=2+ub)
    // B
    const int krb = (g8 & 1) * 8 + li;            // k row within 16-block
    const int sb = krb & 7;
    const int nub = (wn >> 3) + (g8 >> 1);
    uint32_t bOff[2][2];  // [kk][jpair]
#pragma unroll
    for (int kk = 0; kk < 2; kk++)
#pragma unroll
        for (int jp = 0; jp < 2; jp++)
            bOff[kk][jp] = 8192u + (uint32_t)krb * 256 + (uint32_t)kk * 4096
                         + ((unsigned)((nub + 2 * jp) ^ sb) << 4);

    float acc[4][4][4];
#pragma unroll
    for (int i = 0; i < 4; i++)
#pragma unroll
        for (int j = 0; j < 4; j++)
#pragma unroll
            for (int c = 0; c < 4; c++) acc[i][j][c] = 0.f;

    const int nk = K >> 5;   // 32-K chunks (nk >= 2 for all our shapes)

    // ---- producer lambda ----
    auto issue = [&](int c, int st) {
        const int k0 = c * 32;
        const uint32_t stb = sbase + (uint32_t)st * 16384;
#pragma unroll
        for (int i = 0; i < 2; i++) {
            const __half* src = A + (size_t)(row0 + aR[i]) * K + k0 + aU[i] * 8;
            CPA16(stb + (uint32_t)aPhys[i] * 16, src);
        }
#pragma unroll
        for (int i = 0; i < 2; i++) {
            const int gc = col0 + bNu[i] * 8;
            const __half* src = B + (size_t)(k0 + bKr[i]) * Nn + (bSz[i] ? gc : 0);
            CPA16Z(stb + 8192u + (uint32_t)bPhys[i] * 16, src, bSz[i]);
        }
        CPA_COMMIT();
    };

    issue(0, 0);
    issue(1, 1);

    for (int it = 0; it < nk; it++) {
        const int st = it % 3;
        CPA_WAIT1();
        __syncthreads();
        if (it + 2 < nk) issue(it + 2, (it + 2) % 3);
        else CPA_COMMIT();   // keep group accounting uniform

        const uint32_t stb = sbase + (uint32_t)st * 16384;
#pragma unroll
        for (int kk = 0; kk < 2; kk++) {
            unsigned af[4][4], bf[4][2];
            const uint32_t aO = (kk == 0) ? aOff0 : aOff1;
#pragma unroll
            for (int i = 0; i < 4; i++)
                LDSM4(af[i][0], af[i][1], af[i][2], af[i][3],
                      stb + aO + (uint32_t)i * 1024);
#pragma unroll
            for (int jp = 0; jp < 2; jp++) {
                unsigned t0, t1, t2, t3;
                LDSM4T(t0, t1, t2, t3, stb + bOff[kk][jp]);
                bf[2 * jp][0] = t0; bf[2 * jp][1] = t1;
                bf[2 * jp + 1][0] = t2; bf[2 * jp + 1][1] = t3;
            }
#pragma unroll
            for (int i = 0; i < 4; i++)
#pragma unroll
                for (int j = 0; j < 4; j++) {
                    asm volatile(
                        "mma.sync.aligned.m16n8k16.row.col.f32.f16.f16.f32 "
                        "{%0,%1,%2,%3}, {%4,%5,%6,%7}, {%8,%9}, {%0,%1,%2,%3};"
                        : "+f"(acc[i][j][0]), "+f"(acc[i][j][1]),
                          "+f"(acc[i][j][2]), "+f"(acc[i][j][3])
                        : "r"(af[i][0]), "r"(af[i][1]), "r"(af[i][2]), "r"(af[i][3]),
                          "r"(bf[j][0]), "r"(bf[j][1]));
                }
        }
    }

    // ---- epilogue (acc layout identical to previous rounds) ----
#pragma unroll
    for (int i = 0; i < 4; i++) {
        const int r0r = row0 + wm + i * 16 + g;
#pragma unroll
        for (int j = 0; j < 4; j++) {
            const int col = col0 + wn + j * 8 + tq * 2;
            if (col >= Nn) continue;
            float2 bsv = make_float2(0.f, 0.f);
            if (BIAS) bsv = *(const float2*)(bias + col);
            float2 v0, v1;
            v0.x = acc[i][j][0] + (BIAS ? bsv.x : 0.f);
            v0.y = acc[i][j][1] + (BIAS ? bsv.y : 0.f);
            v1.x = acc[i][j][2] + (BIAS ? bsv.x : 0.f);
            v1.y = acc[i][j][3] + (BIAS ? bsv.y : 0.f);
            if (RELU) {
                v0.x = fmaxf(v0.x, 0.f); v0.y = fmaxf(v0.y, 0.f);
                v1.x = fmaxf(v1.x, 0.f); v1.y = fmaxf(v1.y, 0.f);
            }
            if (HOUT) {
                __half* C = (__half*)Cv;
                *(unsigned*)(C + (size_t)r0r * Nn + col)       = h2_as_u32(__floats2half2_rn(v0.x, v0.y));
                *(unsigned*)(C + (size_t)(r0r + 8) * Nn + col) = h2_as_u32(__floats2half2_rn(v1.x, v1.y));
            } else {
                float* C = (float*)Cv;
                *(float2*)(C + (size_t)r0r * Nn + col) = v0;
                *(float2*)(C + (size_t)(r0r + 8) * Nn + col) = v1;
            }
        }
    }
}

// ---------------- SIMT SGEMM (small M cases only) -------------------------
#define BM 128
#define BN 128
#define BK 8
#define TM 8
#define TN 8

template<bool RELU, bool BIAS>
__global__ void sgemm(const float* __restrict__ A, const float* __restrict__ B,
                      const float* __restrict__ bias, float* __restrict__ C,
                      int M, int Nn, int K)
{
    __shared__ float As[BK][BM];
    __shared__ float Bs[BK][BN];
    const int tid = threadIdx.x;
    const int row0 = blockIdx.y * BM;
    const int col0 = blockIdx.x * BN;
    const int tx = tid % 16;
    const int ty = tid / 16;

    float acc[TM][TN];
#pragma unroll
    for (int i = 0; i < TM; i++)
#pragma unroll
        for (int j = 0; j < TN; j++) acc[i][j] = 0.f;

    const int aRow = tid >> 1;
    const int aCol = (tid & 1) * 4;
    const int bRow = tid >> 5;
    const int bCol = (tid & 31) * 4;

    for (int k0 = 0; k0 < K; k0 += BK) {
        int gr = row0 + aRow;
        float4 av = make_float4(0.f, 0.f, 0.f, 0.f);
        if (gr < M) av = *(const float4*)(A + (size_t)gr * K + k0 + aCol);
        As[aCol + 0][aRow] = av.x;
        As[aCol + 1][aRow] = av.y;
        As[aCol + 2][aRow] = av.z;
        As[aCol + 3][aRow] = av.w;

        int gc = col0 + bCol;
        float4 bv = make_float4(0.f, 0.f, 0.f, 0.f);
        if (gc < Nn) bv = *(const float4*)(B + (size_t)(k0 + bRow) * Nn + gc);
        *(float4*)&Bs[bRow][bCol] = bv;
        __syncthreads();

#pragma unroll
        for (int kk = 0; kk < BK; kk++) {
            float ar[TM], br[TN];
#pragma unroll
            for (int i = 0; i < TM; i++) ar[i] = As[kk][ty * TM + i];
#pragma unroll
            for (int j = 0; j < TN; j++) br[j] = Bs[kk][tx * TN + j];
#pragma unroll
            for (int i = 0; i < TM; i++)
#pragma unroll
                for (int j = 0; j < TN; j++)
                    acc[i][j] = fmaf(ar[i], br[j], acc[i][j]);
        }
        __syncthreads();
    }

#pragma unroll
    for (int i = 0; i < TM; i++) {
        int r = row0 + ty * TM + i;
        if (r >= M) continue;
#pragma unroll
        for (int j = 0; j < TN; j++) {
            int c = col0 + tx * TN + j;
            if (c >= Nn) continue;
            float v = acc[i][j];
            if (BIAS) v += bias[c];
            if (RELU) v = fmaxf(v, 0.f);
            C[(size_t)r * Nn + c] = v;
        }
    }
}

template<bool BIAS>
__global__ void sgemm_bz(const float* __restrict__ A0, const float* __restrict__ B0,
                         const float* __restrict__ bias0, float* __restrict__ C0,
                         int M, int Nn, int K,
                         size_t sA, size_t sB, size_t sBias, size_t sC)
{
    const int z = blockIdx.z;
    const float* A = A0 + sA * z;
    const float* B = B0 + sB * z;
    const float* bias = BIAS ? (bias0 + sBias * z) : nullptr;
    float* C = C0 + sC * z;

    __shared__ float As[BK][BM];
    __shared__ float Bs[BK][BN];
    const int tid = threadIdx.x;
    const int row0 = blockIdx.y * BM;
    const int col0 = blockIdx.x * BN;
    const int tx = tid % 16;
    const int ty = tid / 16;

    float acc[TM][TN];
#pragma unroll
    for (int i = 0; i < TM; i++)
#pragma unroll
        for (int j = 0; j < TN; j++) acc[i][j] = 0.f;

    const int aRow = tid >> 1;
    const int aCol = (tid & 1) * 4;
    const int bRow = tid >> 5;
    const int bCol = (tid & 31) * 4;

    for (int k0 = 0; k0 < K; k0 += BK) {
        int gr = row0 + aRow;
        float4 av = make_float4(0.f, 0.f, 0.f, 0.f);
        if (gr < M) av = *(const float4*)(A + (size_t)gr * K + k0 + aCol);
        As[aCol + 0][aRow] = av.x;
        As[aCol + 1][aRow] = av.y;
        As[aCol + 2][aRow] = av.z;
        As[aCol + 3][aRow] = av.w;

        int gc = col0 + bCol;
        float4 bv = make_float4(0.f, 0.f, 0.f, 0.f);
        if (gc < Nn) bv = *(const float4*)(B + (size_t)(k0 + bRow) * Nn + gc);
        *(float4*)&Bs[bRow][bCol] = bv;
        __syncthreads();

#pragma unroll
        for (int kk = 0; kk < BK; kk++) {
            float ar[TM], br[TN];
#pragma unroll
            for (int i = 0; i < TM; i++) ar[i] = As[kk][ty * TM + i];
#pragma unroll
            for (int j = 0; j < TN; j++) br[j] = Bs[kk][tx * TN + j];
#pragma unroll
            for (int i = 0; i < TM; i++)
#pragma unroll
                for (int j = 0; j < TN; j++)
                    acc[i][j] = fmaf(ar[i], br[j], acc[i][j]);
        }
        __syncthreads();
    }

#pragma unroll
    for (int i = 0; i < TM; i++) {
        int r = row0 + ty * TM + i;
        if (r >= M) continue;
#pragma unroll
        for (int j = 0; j < TN; j++) {
            int c = col0 + tx * TN + j;
            if (c >= Nn) continue;
            float v = acc[i][j];
            if (BIAS) v += bias[c];
            C[(size_t)r * Nn + c] = v;
        }
    }
}

// ---------------- embedding (dual write f32 + f16) ------------
__global__ void embed_kernel(const int* __restrict__ cap, const float* __restrict__ emb,
                             const float* __restrict__ pos, float* __restrict__ X,
                             __half* __restrict__ Xh)
{
    int r = blockIdx.x;
    int t = r & (TT - 1);
    int c = cap[r];
    int d = threadIdx.x * 4;
    float4 e = *(const float4*)(emb + (size_t)c * DD + d);
    float4 p = *(const float4*)(pos + (size_t)t * DD + d);
    e.x += p.x; e.y += p.y; e.z += p.z; e.w += p.w;
    *(float4*)(X + (size_t)r * DD + d) = e;
    uint2 hv;
    hv.x = h2_as_u32(__floats2half2_rn(e.x, e.y));
    hv.y = h2_as_u32(__floats2half2_rn(e.z, e.w));
    *(uint2*)(Xh + (size_t)r * DD + d) = hv;
}

// ---------------- flash attention (fp16 output) ---------------------------
#define QS_STRIDE 132
#define KS_STRIDE 68
#define PS_STRIDE 132
#define FA_SMEM ((64*QS_STRIDE + 64*KS_STRIDE + 64*64 + 64*PS_STRIDE) * sizeof(float))

__global__ __launch_bounds__(256) void flash_attn(
    const float* __restrict__ Q, const float* __restrict__ K,
    const float* __restrict__ V, __half* __restrict__ O)
{
    extern __shared__ float sh[];
    float* Qs = sh;
    float* Ks = Qs + 64 * QS_STRIDE;
    float* Vs = Ks + 64 * KS_STRIDE;
    float* Ps = Vs + 64 * 64;

    const int bid = blockIdx.x;
    const int qt = bid & 3;
    const int h  = (bid >> 2) & 15;
    const int n  = bid >> 6;
    const int q0 = qt * 128;

    const int tid = threadIdx.x;
    const int tx = tid & 15;
    const int ty = tid >> 4;

    {
        const int d4 = (tid & 15) * 4;
        const int r0 = tid >> 4;
#pragma unroll
        for (int rr = 0; rr < 8; rr++) {
            const int r = r0 + rr * 16;
            const float4 v = *(const float4*)(Q + ((size_t)(n * TT + q0 + r)) * DD + h * DHD + d4);
            Qs[(d4 + 0) * QS_STRIDE + r] = v.x;
            Qs[(d4 + 1) * QS_STRIDE + r] = v.y;
            Qs[(d4 + 2) * QS_STRIDE + r] = v.z;
            Qs[(d4 + 3) * QS_STRIDE + r] = v.w;
        }
    }

    float o[8][4];
    float m[8], l[8];
#pragma unroll
    for (int i = 0; i < 8; i++) {
        m[i] = -1e30f; l[i] = 0.f;
#pragma unroll
        for (int j = 0; j < 4; j++) o[i][j] = 0.f;
    }

    const int ntiles = (q0 + 128) / 64;
    for (int t = 0; t < ntiles; t++) {
        const int j0 = t * 64;
        __syncthreads();
        {
            const int d4 = (tid & 15) * 4;
            const int c0 = tid >> 4;
#pragma unroll
            for (int cc = 0; cc < 4; cc++) {
                const int c = c0 + cc * 16;
                const size_t grow = ((size_t)(n * TT + j0 + c)) * DD + h * DHD + d4;
                const float4 kv = *(const float4*)(K + grow);
                Ks[(d4 + 0) * KS_STRIDE + c] = kv.x;
                Ks[(d4 + 1) * KS_STRIDE + c] = kv.y;
                Ks[(d4 + 2) * KS_STRIDE + c] = kv.z;
                Ks[(d4 + 3) * KS_STRIDE + c] = kv.w;
                const float4 vv = *(const float4*)(V + grow);
                *(float4*)(Vs + c * 64 + d4) = vv;
            }
        }
        __syncthreads();

        float s[8][4];
#pragma unroll
        for (int i = 0; i < 8; i++)
#pragma unroll
            for (int j = 0; j < 4; j++) s[i][j] = 0.f;
#pragma unroll 4
        for (int kk = 0; kk < 64; kk++) {
            float ar[8], br[4];
            *(float4*)ar       = *(const float4*)(Qs + kk * QS_STRIDE + ty * 8);
            *(float4*)(ar + 4) = *(const float4*)(Qs + kk * QS_STRIDE + ty * 8 + 4);
            *(float4*)br       = *(const float4*)(Ks + kk * KS_STRIDE + tx * 4);
#pragma unroll
            for (int i = 0; i < 8; i++)
#pragma unroll
                for (int j = 0; j < 4; j++) s[i][j] = fmaf(ar[i], br[j], s[i][j]);
        }

        float tmax[8];
#pragma unroll
        for (int i = 0; i < 8; i++) {
            const int q = q0 + ty * 8 + i;
            tmax[i] = -1e30f;
#pragma unroll
            for (int j = 0; j < 4; j++) {
                const int kidx = j0 + tx * 4 + j;
                float v = (kidx <= q) ? s[i][j] * 0.125f : -1e30f;
                s[i][j] = v;
                tmax[i] = fmaxf(tmax[i], v);
            }
        }
#pragma unroll
        for (int st = 1; st < 16; st <<= 1)
#pragma unroll
            for (int i = 0; i < 8; i++)
                tmax[i] = fmaxf(tmax[i], __shfl_xor_sync(0xffffffffu, tmax[i], st));

        float psum[8];
#pragma unroll
        for (int i = 0; i < 8; i++) {
            const float mn = fmaxf(m[i], tmax[i]);
            const float sc = __expf(m[i] - mn);
            m[i] = mn;
            l[i] *= sc;
#pragma unroll
            for (int j = 0; j < 4; j++) o[i][j] *= sc;
            float ps = 0.f;
#pragma unroll
            for (int j = 0; j < 4; j++) {
                const float p = __expf(s[i][j] - mn);
                s[i][j] = p;
                ps += p;
            }
            psum[i] = ps;
        }
#pragma unroll
        for (int st = 1; st < 16; st <<= 1)
#pragma unroll
            for (int i = 0; i < 8; i++)
                psum[i] += __shfl_xor_sync(0xffffffffu, psum[i], st);
#pragma unroll
        for (int i = 0; i < 8; i++) l[i] += psum[i];

#pragma unroll
        for (int j = 0; j < 4; j++) {
            const int k = tx * 4 + j;
#pragma unroll
            for (int i = 0; i < 8; i++)
                Ps[k * PS_STRIDE + ty * 8 + i] = s[i][j];
        }
        __syncthreads();

#pragma unroll 4
        for (int k = 0; k < 64; k++) {
            float ar[8], bv[4];
            *(float4*)ar       = *(const float4*)(Ps + k * PS_STRIDE + ty * 8);
            *(float4*)(ar + 4) = *(const float4*)(Ps + k * PS_STRIDE + ty * 8 + 4);
            *(float4*)bv       = *(const float4*)(Vs + k * 64 + tx * 4);
#pragma unroll
            for (int i = 0; i < 8; i++)
#pragma unroll
                for (int j = 0; j < 4; j++) o[i][j] = fmaf(ar[i], bv[j], o[i][j]);
        }
    }

#pragma unroll
    for (int i = 0; i < 8; i++) {
        const int q = q0 + ty * 8 + i;
        const float inv = 1.f / l[i];
        uint2 hv;
        hv.x = h2_as_u32(__floats2half2_rn(o[i][0] * inv, o[i][1] * inv));
        hv.y = h2_as_u32(__floats2half2_rn(o[i][2] * inv, o[i][3] * inv));
        *(uint2*)(O + ((size_t)((n * HH + h) * TT + q)) * DHD + tx * 4) = hv;
    }
}

// ---------------- residual + LayerNorm (dual write) ----------------------
__global__ void ln_kernel(const float* __restrict__ X, const float* __restrict__ Rsd,
                          const float* __restrict__ g, const float* __restrict__ b,
                          float* __restrict__ out, __half* __restrict__ outh, int mode)
{
    const int r = blockIdx.x;
    const int tid = threadIdx.x;
    size_t rr;
    if (mode == 0) rr = (size_t)r;
    else {
        int n = r >> 9;
        int s = r & (TT - 1);
        rr = (size_t)(n * 16 + (s >> 5));
    }
    const float* xr = X + (size_t)r * DD;
    const float* dr = Rsd + rr * DD;
    const int d = tid * 4;
    float4 xv = *(const float4*)(xr + d);
    float4 dv = *(const float4*)(dr + d);
    float v0 = xv.x + dv.x, v1 = xv.y + dv.y, v2 = xv.z + dv.z, v3 = xv.w + dv.w;

    __shared__ float s1[256], s2[256];
    s1[tid] = v0 + v1 + v2 + v3;
    s2[tid] = v0 * v0 + v1 * v1 + v2 * v2 + v3 * v3;
    __syncthreads();
    for (int st = 128; st > 0; st >>= 1) {
        if (tid < st) { s1[tid] += s1[tid + st]; s2[tid] += s2[tid + st]; }
        __syncthreads();
    }
    const float mean = s1[0] * (1.f / DD);
    const float var = s2[0] * (1.f / DD) - mean * mean;
    const float rstd = rsqrtf(var + 1e-5f);

    float4 ov;
    ov.x = g[d + 0] * (v0 - mean) * rstd + b[d + 0];
    ov.y = g[d + 1] * (v1 - mean) * rstd + b[d + 1];
    ov.z = g[d + 2] * (v2 - mean) * rstd + b[d + 2];
    ov.w = g[d + 3] * (v3 - mean) * rstd + b[d + 3];
    *(float4*)(out + (size_t)r * DD + d) = ov;
    uint2 hv;
    hv.x = h2_as_u32(__floats2half2_rn(ov.x, ov.y));
    hv.y = h2_as_u32(__floats2half2_rn(ov.z, ov.w));
    *(uint2*)(outh + (size_t)r * DD + d) = hv;
}

// ------------- tiled rows for cross-attn out-projection (batched) --------
__global__ void tilefe_kernel(const float* __restrict__ fev, float* __restrict__ A)
{
    const int bx = blockIdx.x;
    const int z = bx >> 8;
    const int rl = bx & 255;
    const int n = rl >> 4;
    const int g = rl & 15;
    const int d = threadIdx.x * 4;
    const float* src = fev + (size_t)z * NB * DD + (size_t)n * DD + g * 64;
    float4 v = *(const float4*)(src + (d & 63));
    *(float4*)(A + (size_t)z * NB * 16 * DD + (size_t)rl * DD + d) = v;
}

// ---------------- launch --------------------------------------------------
extern "C" void kernel_launch(void* const* d_in, const int* in_sizes, int n_in,
                              void* d_out, int out_size)
{
    const float* features = (const float*)d_in[0];
    const int*   captions = (const int*)d_in[1];
    const float* feat_W   = (const float*)d_in[2];
    const float* feat_b   = (const float*)d_in[3];
    const float* cap_emb  = (const float*)d_in[4];
    const float* pos_emb  = (const float*)d_in[5];
    const float* sa_Wq = (const float*)d_in[6];
    const float* sa_Wk = (const float*)d_in[7];
    const float* sa_Wv = (const float*)d_in[8];
    const float* sa_Wo = (const float*)d_in[9];
    const float* sa_bo = (const float*)d_in[10];
    const float* sa_g  = (const float*)d_in[11];
    const float* sa_b  = (const float*)d_in[12];
    const float* ca_Wv = (const float*)d_in[15];
    const float* ca_Wo = (const float*)d_in[16];
    const float* ca_bo = (const float*)d_in[17];
    const float* ca_g  = (const float*)d_in[18];
    const float* ca_b  = (const float*)d_in[19];
    const float* ff_W1 = (const float*)d_in[20];
    const float* ff_b1 = (const float*)d_in[21];
    const float* ff_W2 = (const float*)d_in[22];
    const float* ff_b2 = (const float*)d_in[23];
    const float* ff_g  = (const float*)d_in[24];
    const float* ff_b  = (const float*)d_in[25];
    const float* score_W = (const float*)d_in[26];
    const float* score_b = (const float*)d_in[27];
    float* out = (float*)d_out;

    float *px, *pq, *pk, *pv, *pt, *pfe, *pfev, *pzt, *pz;
    __half *pxh, *pattnh, *phh, *pwqh, *pwkh, *pwvh, *pwoh, *pw1h, *pw2h, *pwsh;
    cudaGetSymbolAddress((void**)&px,    g_x);
    cudaGetSymbolAddress((void**)&pq,    g_q);
    cudaGetSymbolAddress((void**)&pk,    g_k);
    cudaGetSymbolAddress((void**)&pv,    g_v);
    cudaGetSymbolAddress((void**)&pt,    g_t);
    cudaGetSymbolAddress((void**)&pfe,   g_fe);
    cudaGetSymbolAddress((void**)&pfev,  g_fev);
    cudaGetSymbolAddress((void**)&pzt,   g_ztile);
    cudaGetSymbolAddress((void**)&pz,    g_z);
    cudaGetSymbolAddress((void**)&pxh,    g_xh);
    cudaGetSymbolAddress((void**)&pattnh, g_attnh);
    cudaGetSymbolAddress((void**)&phh,    g_hh);
    cudaGetSymbolAddress((void**)&pwqh,   g_wqh);
    cudaGetSymbolAddress((void**)&pwkh,   g_wkh);
    cudaGetSymbolAddress((void**)&pwvh,   g_wvh);
    cudaGetSymbolAddress((void**)&pwoh,   g_woh);
    cudaGetSymbolAddress((void**)&pw1h,   g_w1h);
    cudaGetSymbolAddress((void**)&pw2h,   g_w2h);
    cudaGetSymbolAddress((void**)&pwsh,   g_wsh);

    static bool attr_set = false;
    if (!attr_set) {
        cudaFuncSetAttribute(flash_attn, cudaFuncAttributeMaxDynamicSharedMemorySize, FA_SMEM);
        attr_set = true;
    }

    const int tb = 256;
    const int nDD = LL * DD * DD;
    const int nFF = LL * DD * FFD;
    const int nS = DD * VV;

    const dim3 gP(DD / 128, ROWS / 128);     // 8 x 64
    const dim3 gF(FFD / 128, ROWS / 128);    // 16 x 64

    // Launch order puts hgemm(Q, layer 0) at launch index 5 so ncu -s 5 -c 1
    // profiles the dominant kernel.
    f2h_kernel<<<(nDD / 4 + tb - 1) / tb, tb>>>(sa_Wq, pwqh, nDD);               // 0
    sgemm<false, true><<<dim3(DD / BN, 1), 256>>>(features, feat_W, feat_b, pfe, NB, DD, DIN); // 1
    embed_kernel<<<ROWS, 256>>>(captions, cap_emb, pos_emb, px, pxh);            // 2
    f2h_kernel<<<(nDD / 4 + tb - 1) / tb, tb>>>(sa_Wk, pwkh, nDD);               // 3
    f2h_kernel<<<(nDD / 4 + tb - 1) / tb, tb>>>(sa_Wv, pwvh, nDD);               // 4
    hgemm<false, false, false><<<gP, 256>>>(pxh, pwqh, nullptr, pq, ROWS, DD, DD); // 5 <- profiled
    hgemm<false, false, false><<<gP, 256>>>(pxh, pwkh, nullptr, pk, ROWS, DD, DD);
    hgemm<false, false, false><<<gP, 256>>>(pxh, pwvh, nullptr, pv, ROWS, DD, DD);

    f2h_kernel<<<(nDD / 4 + tb - 1) / tb, tb>>>(sa_Wo, pwoh, nDD);
    f2h_kernel<<<(nFF / 4 + tb - 1) / tb, tb>>>(ff_W1, pw1h, nFF);
    f2h_kernel<<<(nFF / 4 + tb - 1) / tb, tb>>>(ff_W2, pw2h, nFF);
    f2h_kernel<<<(nS / 4 + tb - 1) / tb, tb>>>(score_W, pwsh, nS);

    // cross-attention contributions for all layers (f32 SIMT path)
    sgemm_bz<false><<<dim3(DD / BN, 1, LL), 256>>>(pfe, ca_Wv, nullptr, pfev,
                                                   NB, DD, DD,
                                                   0, (size_t)DD * DD, 0, (size_t)NB * DD);
    tilefe_kernel<<<LL * NB * 16, 256>>>(pfev, pzt);
    sgemm_bz<true><<<dim3(DD / BN, 2, LL), 256>>>(pzt, ca_Wo, ca_bo, pz,
                                                  NB * 16, DD, DD,
                                                  (size_t)NB * 16 * DD, (size_t)DD * DD,
                                                  DD, (size_t)NB * 16 * DD);

    for (int i = 0; i < LL; i++) {
        if (i > 0) {
            hgemm<false, false, false><<<gP, 256>>>(pxh, pwqh + (size_t)i * DD * DD, nullptr, pq, ROWS, DD, DD);
            hgemm<false, false, false><<<gP, 256>>>(pxh, pwkh + (size_t)i * DD * DD, nullptr, pk, ROWS, DD, DD);
            hgemm<false, false, false><<<gP, 256>>>(pxh, pwvh + (size_t)i * DD * DD, nullptr, pv, ROWS, DD, DD);
        }
        flash_attn<<<NB * HH * 4, 256, FA_SMEM>>>(pq, pk, pv, pattnh);
        hgemm<false, true, false><<<gP, 256>>>(pattnh, pwoh + (size_t)i * DD * DD,
                                               sa_bo + (size_t)i * DD, pt, ROWS, DD, DD);
        ln_kernel<<<ROWS, 256>>>(px, pt, sa_g + (size_t)i * DD, sa_b + (size_t)i * DD, px, pxh, 0);

        ln_kernel<<<ROWS, 256>>>(px, pz + (size_t)i * NB * 16 * DD,
                                 ca_g + (size_t)i * DD, ca_b + (size_t)i * DD, px, pxh, 1);

        hgemm<true, true, true><<<gF, 256>>>(pxh, pw1h + (size_t)i * DD * FFD,
                                             ff_b1 + (size_t)i * FFD, phh, ROWS, FFD, DD);
        hgemm<false, true, false><<<gP, 256>>>(phh, pw2h + (size_t)i * FFD * DD,
                                               ff_b2 + (size_t)i * DD, pt, ROWS, DD, FFD);
        ln_kernel<<<ROWS, 256>>>(px, pt, ff_g + (size_t)i * DD, ff_b + (size_t)i * DD, px, pxh, 0);
    }

    // final vocab projection
    hgemm<false, true, false><<<dim3((VV + 127) / 128, ROWS / 128), 256>>>(
        pxh, pwsh, score_b, out, ROWS, VV, DD);
}

// round 9
// speedup vs baseline: 11.4971x; 1.0320x over previous
#include <cuda_runtime.h>
#include <cuda_bf16.h>
#include <cuda_fp16.h>
#include <cstdio>
#include <cstdint>

// Problem constants
#define NB   16
#define TT   512
#define VV   10000
#define DIN  2048
#define DD   1024
#define HH   16
#define LL   4
#define FFD  2048
#define DHD  64
#define ROWS (NB*TT)          // 8192
#define NEGF (-1e8f)

// ---------------- device scratch ----------------
__device__ float g_x[ROWS * DD];
__device__ float g_q[ROWS * DD];
__device__ float g_k[ROWS * DD];
__device__ float g_v[ROWS * DD];
__device__ float g_t[ROWS * DD];
__device__ float g_fe[NB * DD];
__device__ float g_fev[LL * NB * DD];
__device__ float g_ztile[LL * NB * 16 * DD];
__device__ float g_z[LL * NB * 16 * DD];

// fp16 side
__device__ __half g_xh[ROWS * DD];
__device__ __half g_attnh[ROWS * DD];
__device__ __half g_hh[ROWS * FFD];
__device__ __half g_wqh[LL * DD * DD];
__device__ __half g_wkh[LL * DD * DD];
__device__ __half g_wvh[LL * DD * DD];
__device__ __half g_woh[LL * DD * DD];
__device__ __half g_w1h[LL * DD * FFD];
__device__ __half g_w2h[LL * FFD * DD];
__device__ __half g_wsh[DD * VV];

// ---------------- small helpers ----------------
__device__ __forceinline__ unsigned h2_as_u32(__half2 h) {
    return *(unsigned*)&h;
}
__device__ __forceinline__ uint32_t smem_u32(const void* p) {
    uint32_t a;
    asm("{ .reg .u64 t; cvta.to.shared.u64 t, %1; cvt.u32.u64 %0, t; }"
        : "=r"(a) : "l"(p));
    return a;
}

#define CPA16(dst, src) \
    asm volatile("cp.async.cg.shared.global [%0], [%1], 16;" :: "r"(dst), "l"(src))
#define CPA16Z(dst, src, sz) \
    asm volatile("cp.async.cg.shared.global [%0], [%1], 16, %2;" :: "r"(dst), "l"(src), "r"(sz))
#define CPA_COMMIT() asm volatile("cp.async.commit_group;" ::: "memory")
#define CPA_WAIT1()  asm volatile("cp.async.wait_group 1;" ::: "memory")

#define LDSM4(r0, r1, r2, r3, addr) \
    asm volatile("ldmatrix.sync.aligned.m8n8.x4.shared.b16 {%0,%1,%2,%3}, [%4];" \
                 : "=r"(r0), "=r"(r1), "=r"(r2), "=r"(r3) : "r"(addr))
#define LDSM4T(r0, r1, r2, r3, addr) \
    asm volatile("ldmatrix.sync.aligned.m8n8.x4.trans.shared.b16 {%0,%1,%2,%3}, [%4];" \
                 : "=r"(r0), "=r"(r1), "=r"(r2), "=r"(r3) : "r"(addr))

// ---------------- f32 -> f16 conversion (n % 4 == 0) ----------------
__global__ void f2h_kernel(const float* __restrict__ src, __half* __restrict__ dst, int n)
{
    int i = (blockIdx.x * blockDim.x + threadIdx.x) * 4;
    if (i < n) {
        float4 v = *(const float4*)(src + i);
        uint2 o;
        o.x = h2_as_u32(__floats2half2_rn(v.x, v.y));
        o.y = h2_as_u32(__floats2half2_rn(v.z, v.w));
        *(uint2*)(dst + i) = o;
    }
}

// ==================== fp16 GEMM: cp.async + ldmatrix + mma.m16n8k16 =======
// C = A(MxK)*B(KxN) [+bias][ReLU]. fp16 in. M%128==0, K%32==0, Nn%8==0.
// 128x128 tile, BK=32, 3-stage cp.async pipeline.
// 128 threads = 4 warps (2x2 grid), warp tile 64x64.
// A smem: 128 rows x 4 units(16B); phys unit = r*4 + (u ^ ((r&7)>>1))
// B smem: 32 k-rows x 16 n-units;  phys unit = kr*16 + (nu ^ (kr&7))

template<bool RELU, bool BIAS, bool HOUT>
__global__ __launch_bounds__(128, 2) void hgemm(
    const __half* __restrict__ A, const __half* __restrict__ B,
    const float* __restrict__ bias, void* __restrict__ Cv,
    int M, int Nn, int K)
{
    __shared__ __align__(16) unsigned char sm[3][16384];  // 48KB: per stage A(8KB)+B(8KB)

    const int tid  = threadIdx.x;
    const int lane = tid & 31;
    const int warp = tid >> 5;
    const int row0 = blockIdx.y * 128;
    const int col0 = blockIdx.x * 128;
    const int wm = (warp >> 1) * 64;       // 0 or 64
    const int wn = (warp & 1) * 64;        // 0 or 64
    const int g  = lane >> 2;
    const int tq = lane & 3;

    const uint32_t sbase = smem_u32(sm);

    // ---- producer indices (4 A units + 4 B units per thread per chunk) ----
    int aR[4], aU[4], aPhys[4];
    int bKr[4], bNu[4], bPhys[4];
    unsigned bSz[4];
#pragma unroll
    for (int i = 0; i < 4; i++) {
        const int ul = tid + 128 * i;
        aR[i] = ul >> 2; aU[i] = ul & 3;
        aPhys[i] = aR[i] * 4 + (aU[i] ^ ((aR[i] & 7) >> 1));
        bKr[i] = ul >> 4; bNu[i] = ul & 15;
        bPhys[i] = bKr[i] * 16 + (bNu[i] ^ (bKr[i] & 7));
        bSz[i] = (col0 + bNu[i] * 8 + 7 < Nn) ? 16u : 0u;
    }

    // ---- consumer (ldmatrix) lane components ----
    const int g8 = lane >> 3, li = lane & 7;
    // A
    const int rowa = wm + (g8 & 1) * 8 + li;
    const int sa = (rowa & 7) >> 1;
    const int ub = g8 >> 1;
    const uint32_t aOff0 = (uint32_t)rowa * 64 + ((unsigned)((0 + ub) ^ sa) << 4);
    const uint32_t aOff1 = (uint32_t)rowa * 64 + ((unsigned)((2 + ub) ^ sa) << 4);
    // B
    const int krb = (g8 & 1) * 8 + li;
    const int sb = krb & 7;
    const int nub = (wn >> 3) + (g8 >> 1);
    uint32_t bOff[2][4];  // [kk][jpair]
#pragma unroll
    for (int kk = 0; kk < 2; kk++)
#pragma unroll
        for (int jp = 0; jp < 4; jp++)
            bOff[kk][jp] = 8192u + (uint32_t)krb * 256 + (uint32_t)kk * 4096
                         + ((unsigned)((nub + 2 * jp) ^ sb) << 4);

    float acc[4][8][4];
#pragma unroll
    for (int i = 0; i < 4; i++)
#pragma unroll
        for (int j = 0; j < 8; j++)
#pragma unroll
            for (int c = 0; c < 4; c++) acc[i][j][c] = 0.f;

    const int nk = K >> 5;   // 32-K chunks (nk >= 2 for all our shapes)

    auto issue = [&](int c, int st) {
        const int k0 = c * 32;
        const uint32_t stb = sbase + (uint32_t)st * 16384;
#pragma unroll
        for (int i = 0; i < 4; i++) {
            const __half* src = A + (size_t)(row0 + aR[i]) * K + k0 + aU[i] * 8;
            CPA16(stb + (uint32_t)aPhys[i] * 16, src);
        }
#pragma unroll
        for (int i = 0; i < 4; i++) {
            const int gc = col0 + bNu[i] * 8;
            const __half* src = B + (size_t)(k0 + bKr[i]) * Nn + (bSz[i] ? gc : 0);
            CPA16Z(stb + 8192u + (uint32_t)bPhys[i] * 16, src, bSz[i]);
        }
        CPA_COMMIT();
    };

    issue(0, 0);
    issue(1, 1);

    for (int it = 0; it < nk; it++) {
        const int st = it % 3;
        CPA_WAIT1();
        __syncthreads();
        if (it + 2 < nk) issue(it + 2, (it + 2) % 3);
        else CPA_COMMIT();

        const uint32_t stb = sbase + (uint32_t)st * 16384;
#pragma unroll
        for (int kk = 0; kk < 2; kk++) {
            unsigned af[4][4], bf[8][2];
            const uint32_t aO = (kk == 0) ? aOff0 : aOff1;
#pragma unroll
            for (int i = 0; i < 4; i++)
                LDSM4(af[i][0], af[i][1], af[i][2], af[i][3],
                      stb + aO + (uint32_t)i * 1024);
#pragma unroll
            for (int jp = 0; jp < 4; jp++) {
                unsigned t0, t1, t2, t3;
                LDSM4T(t0, t1, t2, t3, stb + bOff[kk][jp]);
                bf[2 * jp][0] = t0; bf[2 * jp][1] = t1;
                bf[2 * jp + 1][0] = t2; bf[2 * jp + 1][1] = t3;
            }
#pragma unroll
            for (int i = 0; i < 4; i++)
#pragma unroll
                for (int j = 0; j < 8; j++) {
                    asm volatile(
                        "mma.sync.aligned.m16n8k16.row.col.f32.f16.f16.f32 "
                        "{%0,%1,%2,%3}, {%4,%5,%6,%7}, {%8,%9}, {%0,%1,%2,%3};"
                        : "+f"(acc[i][j][0]), "+f"(acc[i][j][1]),
                          "+f"(acc[i][j][2]), "+f"(acc[i][j][3])
                        : "r"(af[i][0]), "r"(af[i][1]), "r"(af[i][2]), "r"(af[i][3]),
                          "r"(bf[j][0]), "r"(bf[j][1]));
                }
        }
    }

    // ---- epilogue ----
#pragma unroll
    for (int i = 0; i < 4; i++) {
        const int r0r = row0 + wm + i * 16 + g;
#pragma unroll
        for (int j = 0; j < 8; j++) {
            const int col = col0 + wn + j * 8 + tq * 2;
            if (col >= Nn) continue;
            float2 bsv = make_float2(0.f, 0.f);
            if (BIAS) bsv = *(const float2*)(bias + col);
            float2 v0, v1;
            v0.x = acc[i][j][0] + (BIAS ? bsv.x : 0.f);
            v0.y = acc[i][j][1] + (BIAS ? bsv.y : 0.f);
            v1.x = acc[i][j][2] + (BIAS ? bsv.x : 0.f);
            v1.y = acc[i][j][3] + (BIAS ? bsv.y : 0.f);
            if (RELU) {
                v0.x = fmaxf(v0.x, 0.f); v0.y = fmaxf(v0.y, 0.f);
                v1.x = fmaxf(v1.x, 0.f); v1.y = fmaxf(v1.y, 0.f);
            }
            if (HOUT) {
                __half* C = (__half*)Cv;
                *(unsigned*)(C + (size_t)r0r * Nn + col)       = h2_as_u32(__floats2half2_rn(v0.x, v0.y));
                *(unsigned*)(C + (size_t)(r0r + 8) * Nn + col) = h2_as_u32(__floats2half2_rn(v1.x, v1.y));
            } else {
                float* C = (float*)Cv;
                *(float2*)(C + (size_t)r0r * Nn + col) = v0;
                *(float2*)(C + (size_t)(r0r + 8) * Nn + col) = v1;
            }
        }
    }
}

// ---------------- SIMT SGEMM (small M cases only) -------------------------
#define BM 128
#define BN 128
#define BK 8
#define TM 8
#define TN 8

template<bool RELU, bool BIAS>
__global__ void sgemm(const float* __restrict__ A, const float* __restrict__ B,
                      const float* __restrict__ bias, float* __restrict__ C,
                      int M, int Nn, int K)
{
    __shared__ float As[BK][BM];
    __shared__ float Bs[BK][BN];
    const int tid = threadIdx.x;
    const int row0 = blockIdx.y * BM;
    const int col0 = blockIdx.x * BN;
    const int tx = tid % 16;
    const int ty = tid / 16;

    float acc[TM][TN];
#pragma unroll
    for (int i = 0; i < TM; i++)
#pragma unroll
        for (int j = 0; j < TN; j++) acc[i][j] = 0.f;

    const int aRow = tid >> 1;
    const int aCol = (tid & 1) * 4;
    const int bRow = tid >> 5;
    const int bCol = (tid & 31) * 4;

    for (int k0 = 0; k0 < K; k0 += BK) {
        int gr = row0 + aRow;
        float4 av = make_float4(0.f, 0.f, 0.f, 0.f);
        if (gr < M) av = *(const float4*)(A + (size_t)gr * K + k0 + aCol);
        As[aCol + 0][aRow] = av.x;
        As[aCol + 1][aRow] = av.y;
        As[aCol + 2][aRow] = av.z;
        As[aCol + 3][aRow] = av.w;

        int gc = col0 + bCol;
        float4 bv = make_float4(0.f, 0.f, 0.f, 0.f);
        if (gc < Nn) bv = *(const float4*)(B + (size_t)(k0 + bRow) * Nn + gc);
        *(float4*)&Bs[bRow][bCol] = bv;
        __syncthreads();

#pragma unroll
        for (int kk = 0; kk < BK; kk++) {
            float ar[TM], br[TN];
#pragma unroll
            for (int i = 0; i < TM; i++) ar[i] = As[kk][ty * TM + i];
#pragma unroll
            for (int j = 0; j < TN; j++) br[j] = Bs[kk][tx * TN + j];
#pragma unroll
            for (int i = 0; i < TM; i++)
#pragma unroll
                for (int j = 0; j < TN; j++)
                    acc[i][j] = fmaf(ar[i], br[j], acc[i][j]);
        }
        __syncthreads();
    }

#pragma unroll
    for (int i = 0; i < TM; i++) {
        int r = row0 + ty * TM + i;
        if (r >= M) continue;
#pragma unroll
        for (int j = 0; j < TN; j++) {
            int c = col0 + tx * TN + j;
            if (c >= Nn) continue;
            float v = acc[i][j];
            if (BIAS) v += bias[c];
            if (RELU) v = fmaxf(v, 0.f);
            C[(size_t)r * Nn + c] = v;
        }
    }
}

template<bool BIAS>
__global__ void sgemm_bz(const float* __restrict__ A0, const float* __restrict__ B0,
                         const float* __restrict__ bias0, float* __restrict__ C0,
                         int M, int Nn, int K,
                         size_t sA, size_t sB, size_t sBias, size_t sC)
{
    const int z = blockIdx.z;
    const float* A = A0 + sA * z;
    const float* B = B0 + sB * z;
    const float* bias = BIAS ? (bias0 + sBias * z) : nullptr;
    float* C = C0 + sC * z;

    __shared__ float As[BK][BM];
    __shared__ float Bs[BK][BN];
    const int tid = threadIdx.x;
    const int row0 = blockIdx.y * BM;
    const int col0 = blockIdx.x * BN;
    const int tx = tid % 16;
    const int ty = tid / 16;

    float acc[TM][TN];
#pragma unroll
    for (int i = 0; i < TM; i++)
#pragma unroll
        for (int j = 0; j < TN; j++) acc[i][j] = 0.f;

    const int aRow = tid >> 1;
    const int aCol = (tid & 1) * 4;
    const int bRow = tid >> 5;
    const int bCol = (tid & 31) * 4;

    for (int k0 = 0; k0 < K; k0 += BK) {
        int gr = row0 + aRow;
        float4 av = make_float4(0.f, 0.f, 0.f, 0.f);
        if (gr < M) av = *(const float4*)(A + (size_t)gr * K + k0 + aCol);
        As[aCol + 0][aRow] = av.x;
        As[aCol + 1][aRow] = av.y;
        As[aCol + 2][aRow] = av.z;
        As[aCol + 3][aRow] = av.w;

        int gc = col0 + bCol;
        float4 bv = make_float4(0.f, 0.f, 0.f, 0.f);
        if (gc < Nn) bv = *(const float4*)(B + (size_t)(k0 + bRow) * Nn + gc);
        *(float4*)&Bs[bRow][bCol] = bv;
        __syncthreads();

#pragma unroll
        for (int kk = 0; kk < BK; kk++) {
            float ar[TM], br[TN];
#pragma unroll
            for (int i = 0; i < TM; i++) ar[i] = As[kk][ty * TM + i];
#pragma unroll
            for (int j = 0; j < TN; j++) br[j] = Bs[kk][tx * TN + j];
#pragma unroll
            for (int i = 0; i < TM; i++)
#pragma unroll
                for (int j = 0; j < TN; j++)
                    acc[i][j] = fmaf(ar[i], br[j], acc[i][j]);
        }
        __syncthreads();
    }

#pragma unroll
    for (int i = 0; i < TM; i++) {
        int r = row0 + ty * TM + i;
        if (r >= M) continue;
#pragma unroll
        for (int j = 0; j < TN; j++) {
            int c = col0 + tx * TN + j;
            if (c >= Nn) continue;
            float v = acc[i][j];
            if (BIAS) v += bias[c];
            C[(size_t)r * Nn + c] = v;
        }
    }
}

// ---------------- embedding (dual write f32 + f16) ------------
__global__ void embed_kernel(const int* __restrict__ cap, const float* __restrict__ emb,
                             const float* __restrict__ pos, float* __restrict__ X,
                             __half* __restrict__ Xh)
{
    int r = blockIdx.x;
    int t = r & (TT - 1);
    int c = cap[r];
    int d = threadIdx.x * 4;
    float4 e = *(const float4*)(emb + (size_t)c * DD + d);
    float4 p = *(const float4*)(pos + (size_t)t * DD + d);
    e.x += p.x; e.y += p.y; e.z += p.z; e.w += p.w;
    *(float4*)(X + (size_t)r * DD + d) = e;
    uint2 hv;
    hv.x = h2_as_u32(__floats2half2_rn(e.x, e.y));
    hv.y = h2_as_u32(__floats2half2_rn(e.z, e.w));
    *(uint2*)(Xh + (size_t)r * DD + d) = hv;
}

// ---------------- flash attention (fp16 output) ---------------------------
#define QS_STRIDE 132
#define KS_STRIDE 68
#define PS_STRIDE 132
#define FA_SMEM ((64*QS_STRIDE + 64*KS_STRIDE + 64*64 + 64*PS_STRIDE) * sizeof(float))

__global__ __launch_bounds__(256) void flash_attn(
    const float* __restrict__ Q, const float* __restrict__ K,
    const float* __restrict__ V, __half* __restrict__ O)
{
    extern __shared__ float sh[];
    float* Qs = sh;
    float* Ks = Qs + 64 * QS_STRIDE;
    float* Vs = Ks + 64 * KS_STRIDE;
    float* Ps = Vs + 64 * 64;

    const int bid = blockIdx.x;
    const int qt = bid & 3;
    const int h  = (bid >> 2) & 15;
    const int n  = bid >> 6;
    const int q0 = qt * 128;

    const int tid = threadIdx.x;
    const int tx = tid & 15;
    const int ty = tid >> 4;

    {
        const int d4 = (tid & 15) * 4;
        const int r0 = tid >> 4;
#pragma unroll
        for (int rr = 0; rr < 8; rr++) {
            const int r = r0 + rr * 16;
            const float4 v = *(const float4*)(Q + ((size_t)(n * TT + q0 + r)) * DD + h * DHD + d4);
            Qs[(d4 + 0) * QS_STRIDE + r] = v.x;
            Qs[(d4 + 1) * QS_STRIDE + r] = v.y;
            Qs[(d4 + 2) * QS_STRIDE + r] = v.z;
            Qs[(d4 + 3) * QS_STRIDE + r] = v.w;
        }
    }

    float o[8][4];
    float m[8], l[8];
#pragma unroll
    for (int i = 0; i < 8; i++) {
        m[i] = -1e30f; l[i] = 0.f;
#pragma unroll
        for (int j = 0; j < 4; j++) o[i][j] = 0.f;
    }

    const int ntiles = (q0 + 128) / 64;
    for (int t = 0; t < ntiles; t++) {
        const int j0 = t * 64;
        __syncthreads();
        {
            const int d4 = (tid & 15) * 4;
            const int c0 = tid >> 4;
#pragma unroll
            for (int cc = 0; cc < 4; cc++) {
                const int c = c0 + cc * 16;
                const size_t grow = ((size_t)(n * TT + j0 + c)) * DD + h * DHD + d4;
                const float4 kv = *(const float4*)(K + grow);
                Ks[(d4 + 0) * KS_STRIDE + c] = kv.x;
                Ks[(d4 + 1) * KS_STRIDE + c] = kv.y;
                Ks[(d4 + 2) * KS_STRIDE + c] = kv.z;
                Ks[(d4 + 3) * KS_STRIDE + c] = kv.w;
                const float4 vv = *(const float4*)(V + grow);
                *(float4*)(Vs + c * 64 + d4) = vv;
            }
        }
        __syncthreads();

        float s[8][4];
#pragma unroll
        for (int i = 0; i < 8; i++)
#pragma unroll
            for (int j = 0; j < 4; j++) s[i][j] = 0.f;
#pragma unroll 4
        for (int kk = 0; kk < 64; kk++) {
            float ar[8], br[4];
            *(float4*)ar       = *(const float4*)(Qs + kk * QS_STRIDE + ty * 8);
            *(float4*)(ar + 4) = *(const float4*)(Qs + kk * QS_STRIDE + ty * 8 + 4);
            *(float4*)br       = *(const float4*)(Ks + kk * KS_STRIDE + tx * 4);
#pragma unroll
            for (int i = 0; i < 8; i++)
#pragma unroll
                for (int j = 0; j < 4; j++) s[i][j] = fmaf(ar[i], br[j], s[i][j]);
        }

        float tmax[8];
#pragma unroll
        for (int i = 0; i < 8; i++) {
            const int q = q0 + ty * 8 + i;
            tmax[i] = -1e30f;
#pragma unroll
            for (int j = 0; j < 4; j++) {
                const int kidx = j0 + tx * 4 + j;
                float v = (kidx <= q) ? s[i][j] * 0.125f : -1e30f;
                s[i][j] = v;
                tmax[i] = fmaxf(tmax[i], v);
            }
        }
#pragma unroll
        for (int st = 1; st < 16; st <<= 1)
#pragma unroll
            for (int i = 0; i < 8; i++)
                tmax[i] = fmaxf(tmax[i], __shfl_xor_sync(0xffffffffu, tmax[i], st));

        float psum[8];
#pragma unroll
        for (int i = 0; i < 8; i++) {
            const float mn = fmaxf(m[i], tmax[i]);
            const float sc = __expf(m[i] - mn);
            m[i] = mn;
            l[i] *= sc;
#pragma unroll
            for (int j = 0; j < 4; j++) o[i][j] *= sc;
            float ps = 0.f;
#pragma unroll
            for (int j = 0; j < 4; j++) {
                const float p = __expf(s[i][j] - mn);
                s[i][j] = p;
                ps += p;
            }
            psum[i] = ps;
        }
#pragma unroll
        for (int st = 1; st < 16; st <<= 1)
#pragma unroll
            for (int i = 0; i < 8; i++)
                psum[i] += __shfl_xor_sync(0xffffffffu, psum[i], st);
#pragma unroll
        for (int i = 0; i < 8; i++) l[i] += psum[i];

#pragma unroll
        for (int j = 0; j < 4; j++) {
            const int k = tx * 4 + j;
#pragma unroll
            for (int i = 0; i < 8; i++)
                Ps[k * PS_STRIDE + ty * 8 + i] = s[i][j];
        }
        __syncthreads();

#pragma unroll 4
        for (int k = 0; k < 64; k++) {
            float ar[8], bv[4];
            *(float4*)ar       = *(const float4*)(Ps + k * PS_STRIDE + ty * 8);
            *(float4*)(ar + 4) = *(const float4*)(Ps + k * PS_STRIDE + ty * 8 + 4);
            *(float4*)bv       = *(const float4*)(Vs + k * 64 + tx * 4);
#pragma unroll
            for (int i = 0; i < 8; i++)
#pragma unroll
                for (int j = 0; j < 4; j++) o[i][j] = fmaf(ar[i], bv[j], o[i][j]);
        }
    }

#pragma unroll
    for (int i = 0; i < 8; i++) {
        const int q = q0 + ty * 8 + i;
        const float inv = 1.f / l[i];
        uint2 hv;
        hv.x = h2_as_u32(__floats2half2_rn(o[i][0] * inv, o[i][1] * inv));
        hv.y = h2_as_u32(__floats2half2_rn(o[i][2] * inv, o[i][3] * inv));
        *(uint2*)(O + ((size_t)((n * HH + h) * TT + q)) * DHD + tx * 4) = hv;
    }
}

// ---------------- residual + LayerNorm (dual write) ----------------------
__global__ void ln_kernel(const float* __restrict__ X, const float* __restrict__ Rsd,
                          const float* __restrict__ g, const float* __restrict__ b,
                          float* __restrict__ out, __half* __restrict__ outh, int mode)
{
    const int r = blockIdx.x;
    const int tid = threadIdx.x;
    size_t rr;
    if (mode == 0) rr = (size_t)r;
    else {
        int n = r >> 9;
        int s = r & (TT - 1);
        rr = (size_t)(n * 16 + (s >> 5));
    }
    const float* xr = X + (size_t)r * DD;
    const float* dr = Rsd + rr * DD;
    const int d = tid * 4;
    float4 xv = *(const float4*)(xr + d);
    float4 dv = *(const float4*)(dr + d);
    float v0 = xv.x + dv.x, v1 = xv.y + dv.y, v2 = xv.z + dv.z, v3 = xv.w + dv.w;

    __shared__ float s1[256], s2[256];
    s1[tid] = v0 + v1 + v2 + v3;
    s2[tid] = v0 * v0 + v1 * v1 + v2 * v2 + v3 * v3;
    __syncthreads();
    for (int st = 128; st > 0; st >>= 1) {
        if (tid < st) { s1[tid] += s1[tid + st]; s2[tid] += s2[tid + st]; }
        __syncthreads();
    }
    const float mean = s1[0] * (1.f / DD);
    const float var = s2[0] * (1.f / DD) - mean * mean;
    const float rstd = rsqrtf(var + 1e-5f);

    float4 ov;
    ov.x = g[d + 0] * (v0 - mean) * rstd + b[d + 0];
    ov.y = g[d + 1] * (v1 - mean) * rstd + b[d + 1];
    ov.z = g[d + 2] * (v2 - mean) * rstd + b[d + 2];
    ov.w = g[d + 3] * (v3 - mean) * rstd + b[d + 3];
    *(float4*)(out + (size_t)r * DD + d) = ov;
    uint2 hv;
    hv.x = h2_as_u32(__floats2half2_rn(ov.x, ov.y));
    hv.y = h2_as_u32(__floats2half2_rn(ov.z, ov.w));
    *(uint2*)(outh + (size_t)r * DD + d) = hv;
}

// ------------- tiled rows for cross-attn out-projection (batched) --------
__global__ void tilefe_kernel(const float* __restrict__ fev, float* __restrict__ A)
{
    const int bx = blockIdx.x;
    const int z = bx >> 8;
    const int rl = bx & 255;
    const int n = rl >> 4;
    const int g = rl & 15;
    const int d = threadIdx.x * 4;
    const float* src = fev + (size_t)z * NB * DD + (size_t)n * DD + g * 64;
    float4 v = *(const float4*)(src + (d & 63));
    *(float4*)(A + (size_t)z * NB * 16 * DD + (size_t)rl * DD + d) = v;
}

// ---------------- launch --------------------------------------------------
extern "C" void kernel_launch(void* const* d_in, const int* in_sizes, int n_in,
                              void* d_out, int out_size)
{
    const float* features = (const float*)d_in[0];
    const int*   captions = (const int*)d_in[1];
    const float* feat_W   = (const float*)d_in[2];
    const float* feat_b   = (const float*)d_in[3];
    const float* cap_emb  = (const float*)d_in[4];
    const float* pos_emb  = (const float*)d_in[5];
    const float* sa_Wq = (const float*)d_in[6];
    const float* sa_Wk = (const float*)d_in[7];
    const float* sa_Wv = (const float*)d_in[8];
    const float* sa_Wo = (const float*)d_in[9];
    const float* sa_bo = (const float*)d_in[10];
    const float* sa_g  = (const float*)d_in[11];
    const float* sa_b  = (const float*)d_in[12];
    const float* ca_Wv = (const float*)d_in[15];
    const float* ca_Wo = (const float*)d_in[16];
    const float* ca_bo = (const float*)d_in[17];
    const float* ca_g  = (const float*)d_in[18];
    const float* ca_b  = (const float*)d_in[19];
    const float* ff_W1 = (const float*)d_in[20];
    const float* ff_b1 = (const float*)d_in[21];
    const float* ff_W2 = (const float*)d_in[22];
    const float* ff_b2 = (const float*)d_in[23];
    const float* ff_g  = (const float*)d_in[24];
    const float* ff_b  = (const float*)d_in[25];
    const float* score_W = (const float*)d_in[26];
    const float* score_b = (const float*)d_in[27];
    float* out = (float*)d_out;

    float *px, *pq, *pk, *pv, *pt, *pfe, *pfev, *pzt, *pz;
    __half *pxh, *pattnh, *phh, *pwqh, *pwkh, *pwvh, *pwoh, *pw1h, *pw2h, *pwsh;
    cudaGetSymbolAddress((void**)&px,    g_x);
    cudaGetSymbolAddress((void**)&pq,    g_q);
    cudaGetSymbolAddress((void**)&pk,    g_k);
    cudaGetSymbolAddress((void**)&pv,    g_v);
    cudaGetSymbolAddress((void**)&pt,    g_t);
    cudaGetSymbolAddress((void**)&pfe,   g_fe);
    cudaGetSymbolAddress((void**)&pfev,  g_fev);
    cudaGetSymbolAddress((void**)&pzt,   g_ztile);
    cudaGetSymbolAddress((void**)&pz,    g_z);
    cudaGetSymbolAddress((void**)&pxh,    g_xh);
    cudaGetSymbolAddress((void**)&pattnh, g_attnh);
    cudaGetSymbolAddress((void**)&phh,    g_hh);
    cudaGetSymbolAddress((void**)&pwqh,   g_wqh);
    cudaGetSymbolAddress((void**)&pwkh,   g_wkh);
    cudaGetSymbolAddress((void**)&pwvh,   g_wvh);
    cudaGetSymbolAddress((void**)&pwoh,   g_woh);
    cudaGetSymbolAddress((void**)&pw1h,   g_w1h);
    cudaGetSymbolAddress((void**)&pw2h,   g_w2h);
    cudaGetSymbolAddress((void**)&pwsh,   g_wsh);

    static bool attr_set = false;
    if (!attr_set) {
        cudaFuncSetAttribute(flash_attn, cudaFuncAttributeMaxDynamicSharedMemorySize, FA_SMEM);
        attr_set = true;
    }

    const int tb = 256;
    const int nDD = LL * DD * DD;
    const int nFF = LL * DD * FFD;
    const int nS = DD * VV;

    const dim3 gP(DD / 128, ROWS / 128);     // 8 x 64
    const dim3 gF(FFD / 128, ROWS / 128);    // 16 x 64

    f2h_kernel<<<(nDD / 4 + tb - 1) / tb, tb>>>(sa_Wq, pwqh, nDD);
    sgemm<false, true><<<dim3(DD / BN, 1), 256>>>(features, feat_W, feat_b, pfe, NB, DD, DIN);
    embed_kernel<<<ROWS, 256>>>(captions, cap_emb, pos_emb, px, pxh);
    f2h_kernel<<<(nDD / 4 + tb - 1) / tb, tb>>>(sa_Wk, pwkh, nDD);
    f2h_kernel<<<(nDD / 4 + tb - 1) / tb, tb>>>(sa_Wv, pwvh, nDD);
    hgemm<false, false, false><<<gP, 128>>>(pxh, pwqh, nullptr, pq, ROWS, DD, DD);
    hgemm<false, false, false><<<gP, 128>>>(pxh, pwkh, nullptr, pk, ROWS, DD, DD);
    hgemm<false, false, false><<<gP, 128>>>(pxh, pwvh, nullptr, pv, ROWS, DD, DD);

    f2h_kernel<<<(nDD / 4 + tb - 1) / tb, tb>>>(sa_Wo, pwoh, nDD);
    f2h_kernel<<<(nFF / 4 + tb - 1) / tb, tb>>>(ff_W1, pw1h, nFF);
    f2h_kernel<<<(nFF / 4 + tb - 1) / tb, tb>>>(ff_W2, pw2h, nFF);
    f2h_kernel<<<(nS / 4 + tb - 1) / tb, tb>>>(score_W, pwsh, nS);

    // cross-attention contributions for all layers (f32 SIMT path)
    sgemm_bz<false><<<dim3(DD / BN, 1, LL), 256>>>(pfe, ca_Wv, nullptr, pfev,
                                                   NB, DD, DD,
                                                   0, (size_t)DD * DD, 0, (size_t)NB * DD);
    tilefe_kernel<<<LL * NB * 16, 256>>>(pfev, pzt);
    sgemm_bz<true><<<dim3(DD / BN, 2, LL), 256>>>(pzt, ca_Wo, ca_bo, pz,
                                                  NB * 16, DD, DD,
                                                  (size_t)NB * 16 * DD, (size_t)DD * DD,
                                                  DD, (size_t)NB * 16 * DD);

    for (int i = 0; i < LL; i++) {
        if (i > 0) {
            hgemm<false, false, false><<<gP, 128>>>(pxh, pwqh + (size_t)i * DD * DD, nullptr, pq, ROWS, DD, DD);
            hgemm<false, false, false><<<gP, 128>>>(pxh, pwkh + (size_t)i * DD * DD, nullptr, pk, ROWS, DD, DD);
            hgemm<false, false, false><<<gP, 128>>>(pxh, pwvh + (size_t)i * DD * DD, nullptr, pv, ROWS, DD, DD);
        }
        flash_attn<<<NB * HH * 4, 256, FA_SMEM>>>(pq, pk, pv, pattnh);
        hgemm<false, true, false><<<gP, 128>>>(pattnh, pwoh + (size_t)i * DD * DD,
                                               sa_bo + (size_t)i * DD, pt, ROWS, DD, DD);
        ln_kernel<<<ROWS, 256>>>(px, pt, sa_g + (size_t)i * DD, sa_b + (size_t)i * DD, px, pxh, 0);

        ln_kernel<<<ROWS, 256>>>(px, pz + (size_t)i * NB * 16 * DD,
                                 ca_g + (size_t)i * DD, ca_b + (size_t)i * DD, px, pxh, 1);

        hgemm<true, true, true><<<gF, 128>>>(pxh, pw1h + (size_t)i * DD * FFD,
                                             ff_b1 + (size_t)i * FFD, phh, ROWS, FFD, DD);
        hgemm<false, true, false><<<gP, 128>>>(phh, pw2h + (size_t)i * FFD * DD,
                                               ff_b2 + (size_t)i * DD, pt, ROWS, DD, FFD);
        ln_kernel<<<ROWS, 256>>>(px, pt, ff_g + (size_t)i * DD, ff_b + (size_t)i * DD, px, pxh, 0);
    }

    // final vocab projection
    hgemm<false, true, false><<<dim3((VV + 127) / 128, ROWS / 128), 128>>>(
        pxh, pwsh, score_b, out, ROWS, VV, DD);
}

// round 10
// speedup vs baseline: 15.3993x; 1.3394x over previous
#include <cuda_runtime.h>
#include <cuda_bf16.h>
#include <cuda_fp16.h>
#include <cstdio>
#include <cstdint>

// Problem constants
#define NB   16
#define TT   512
#define VV   10000
#define DIN  2048
#define DD   1024
#define HH   16
#define LL   4
#define FFD  2048
#define DHD  64
#define ROWS (NB*TT)          // 8192
#define NEGF (-1e8f)

// ---------------- device scratch ----------------
__device__ float g_x[ROWS * DD];
__device__ float g_t[ROWS * DD];
__device__ float g_fe[NB * DD];
__device__ float g_fev[LL * NB * DD];
__device__ float g_ztile[LL * NB * 16 * DD];
__device__ float g_z[LL * NB * 16 * DD];

// fp16 side
__device__ __half g_xh[ROWS * DD];
__device__ __half g_qh[ROWS * DD];
__device__ __half g_kh[ROWS * DD];
__device__ __half g_vh[ROWS * DD];
__device__ __half g_attnh[ROWS * DD];
__device__ __half g_hh[ROWS * FFD];
__device__ __half g_wqh[LL * DD * DD];
__device__ __half g_wkh[LL * DD * DD];
__device__ __half g_wvh[LL * DD * DD];
__device__ __half g_woh[LL * DD * DD];
__device__ __half g_w1h[LL * DD * FFD];
__device__ __half g_w2h[LL * FFD * DD];
__device__ __half g_wsh[DD * VV];

// ---------------- small helpers ----------------
__device__ __forceinline__ unsigned h2_as_u32(__half2 h) {
    return *(unsigned*)&h;
}
__device__ __forceinline__ uint32_t smem_u32(const void* p) {
    uint32_t a;
    asm("{ .reg .u64 t; cvta.to.shared.u64 t, %1; cvt.u32.u64 %0, t; }"
        : "=r"(a) : "l"(p));
    return a;
}

#define CPA16(dst, src) \
    asm volatile("cp.async.cg.shared.global [%0], [%1], 16;" :: "r"(dst), "l"(src))
#define CPA16Z(dst, src, sz) \
    asm volatile("cp.async.cg.shared.global [%0], [%1], 16, %2;" :: "r"(dst), "l"(src), "r"(sz))
#define CPA_COMMIT() asm volatile("cp.async.commit_group;" ::: "memory")
#define CPA_WAIT1()  asm volatile("cp.async.wait_group 1;" ::: "memory")

#define LDSM4(r0, r1, r2, r3, addr) \
    asm volatile("ldmatrix.sync.aligned.m8n8.x4.shared.b16 {%0,%1,%2,%3}, [%4];" \
                 : "=r"(r0), "=r"(r1), "=r"(r2), "=r"(r3) : "r"(addr))
#define LDSM4T(r0, r1, r2, r3, addr) \
    asm volatile("ldmatrix.sync.aligned.m8n8.x4.trans.shared.b16 {%0,%1,%2,%3}, [%4];" \
                 : "=r"(r0), "=r"(r1), "=r"(r2), "=r"(r3) : "r"(addr))

#define MMA16816(acc, a0, a1, a2, a3, b0, b1) \
    asm volatile( \
        "mma.sync.aligned.m16n8k16.row.col.f32.f16.f16.f32 " \
        "{%0,%1,%2,%3}, {%4,%5,%6,%7}, {%8,%9}, {%0,%1,%2,%3};" \
        : "+f"((acc)[0]), "+f"((acc)[1]), "+f"((acc)[2]), "+f"((acc)[3]) \
        : "r"(a0), "r"(a1), "r"(a2), "r"(a3), "r"(b0), "r"(b1))

// ---------------- f32 -> f16 conversion (n % 4 == 0) ----------------
__global__ void f2h_kernel(const float* __restrict__ src, __half* __restrict__ dst, int n)
{
    int i = (blockIdx.x * blockDim.x + threadIdx.x) * 4;
    if (i < n) {
        float4 v = *(const float4*)(src + i);
        uint2 o;
        o.x = h2_as_u32(__floats2half2_rn(v.x, v.y));
        o.y = h2_as_u32(__floats2half2_rn(v.z, v.w));
        *(uint2*)(dst + i) = o;
    }
}

// ==================== fp16 GEMM: cp.async + ldmatrix + mma.m16n8k16 =======
template<bool RELU, bool BIAS, bool HOUT>
__global__ __launch_bounds__(128, 2) void hgemm(
    const __half* __restrict__ A, const __half* __restrict__ B,
    const float* __restrict__ bias, void* __restrict__ Cv,
    int M, int Nn, int K)
{
    __shared__ __align__(16) unsigned char sm[3][16384];

    const int tid  = threadIdx.x;
    const int lane = tid & 31;
    const int warp = tid >> 5;
    const int row0 = blockIdx.y * 128;
    const int col0 = blockIdx.x * 128;
    const int wm = (warp >> 1) * 64;
    const int wn = (warp & 1) * 64;
    const int g  = lane >> 2;
    const int tq = lane & 3;

    const uint32_t sbase = smem_u32(sm);

    int aR[4], aU[4], aPhys[4];
    int bKr[4], bNu[4], bPhys[4];
    unsigned bSz[4];
#pragma unroll
    for (int i = 0; i < 4; i++) {
        const int ul = tid + 128 * i;
        aR[i] = ul >> 2; aU[i] = ul & 3;
        aPhys[i] = aR[i] * 4 + (aU[i] ^ ((aR[i] & 7) >> 1));
        bKr[i] = ul >> 4; bNu[i] = ul & 15;
        bPhys[i] = bKr[i] * 16 + (bNu[i] ^ (bKr[i] & 7));
        bSz[i] = (col0 + bNu[i] * 8 + 7 < Nn) ? 16u : 0u;
    }

    const int g8 = lane >> 3, li = lane & 7;
    const int rowa = wm + (g8 & 1) * 8 + li;
    const int sa = (rowa & 7) >> 1;
    const int ub = g8 >> 1;
    const uint32_t aOff0 = (uint32_t)rowa * 64 + ((unsigned)((0 + ub) ^ sa) << 4);
    const uint32_t aOff1 = (uint32_t)rowa * 64 + ((unsigned)((2 + ub) ^ sa) << 4);
    const int krb = (g8 & 1) * 8 + li;
    const int sb = krb & 7;
    const int nub = (wn >> 3) + (g8 >> 1);
    uint32_t bOff[2][4];
#pragma unroll
    for (int kk = 0; kk < 2; kk++)
#pragma unroll
        for (int jp = 0; jp < 4; jp++)
            bOff[kk][jp] = 8192u + (uint32_t)krb * 256 + (uint32_t)kk * 4096
                         + ((unsigned)((nub + 2 * jp) ^ sb) << 4);

    float acc[4][8][4];
#pragma unroll
    for (int i = 0; i < 4; i++)
#pragma unroll
        for (int j = 0; j < 8; j++)
#pragma unroll
            for (int c = 0; c < 4; c++) acc[i][j][c] = 0.f;

    const int nk = K >> 5;

    auto issue = [&](int c, int st) {
        const int k0 = c * 32;
        const uint32_t stb = sbase + (uint32_t)st * 16384;
#pragma unroll
        for (int i = 0; i < 4; i++) {
            const __half* src = A + (size_t)(row0 + aR[i]) * K + k0 + aU[i] * 8;
            CPA16(stb + (uint32_t)aPhys[i] * 16, src);
        }
#pragma unroll
        for (int i = 0; i < 4; i++) {
            const int gc = col0 + bNu[i] * 8;
            const __half* src = B + (size_t)(k0 + bKr[i]) * Nn + (bSz[i] ? gc : 0);
            CPA16Z(stb + 8192u + (uint32_t)bPhys[i] * 16, src, bSz[i]);
        }
        CPA_COMMIT();
    };

    issue(0, 0);
    issue(1, 1);

    for (int it = 0; it < nk; it++) {
        const int st = it % 3;
        CPA_WAIT1();
        __syncthreads();
        if (it + 2 < nk) issue(it + 2, (it + 2) % 3);
        else CPA_COMMIT();

        const uint32_t stb = sbase + (uint32_t)st * 16384;
#pragma unroll
        for (int kk = 0; kk < 2; kk++) {
            unsigned af[4][4], bf[8][2];
            const uint32_t aO = (kk == 0) ? aOff0 : aOff1;
#pragma unroll
            for (int i = 0; i < 4; i++)
                LDSM4(af[i][0], af[i][1], af[i][2], af[i][3],
                      stb + aO + (uint32_t)i * 1024);
#pragma unroll
            for (int jp = 0; jp < 4; jp++) {
                unsigned t0, t1, t2, t3;
                LDSM4T(t0, t1, t2, t3, stb + bOff[kk][jp]);
                bf[2 * jp][0] = t0; bf[2 * jp][1] = t1;
                bf[2 * jp + 1][0] = t2; bf[2 * jp + 1][1] = t3;
            }
#pragma unroll
            for (int i = 0; i < 4; i++)
#pragma unroll
                for (int j = 0; j < 8; j++)
                    MMA16816(acc[i][j], af[i][0], af[i][1], af[i][2], af[i][3],
                             bf[j][0], bf[j][1]);
        }
    }

#pragma unroll
    for (int i = 0; i < 4; i++) {
        const int r0r = row0 + wm + i * 16 + g;
#pragma unroll
        for (int j = 0; j < 8; j++) {
            const int col = col0 + wn + j * 8 + tq * 2;
            if (col >= Nn) continue;
            float2 bsv = make_float2(0.f, 0.f);
            if (BIAS) bsv = *(const float2*)(bias + col);
            float2 v0, v1;
            v0.x = acc[i][j][0] + (BIAS ? bsv.x : 0.f);
            v0.y = acc[i][j][1] + (BIAS ? bsv.y : 0.f);
            v1.x = acc[i][j][2] + (BIAS ? bsv.x : 0.f);
            v1.y = acc[i][j][3] + (BIAS ? bsv.y : 0.f);
            if (RELU) {
                v0.x = fmaxf(v0.x, 0.f); v0.y = fmaxf(v0.y, 0.f);
                v1.x = fmaxf(v1.x, 0.f); v1.y = fmaxf(v1.y, 0.f);
            }
            if (HOUT) {
                __half* C = (__half*)Cv;
                *(unsigned*)(C + (size_t)r0r * Nn + col)       = h2_as_u32(__floats2half2_rn(v0.x, v0.y));
                *(unsigned*)(C + (size_t)(r0r + 8) * Nn + col) = h2_as_u32(__floats2half2_rn(v1.x, v1.y));
            } else {
                float* C = (float*)Cv;
                *(float2*)(C + (size_t)r0r * Nn + col) = v0;
                *(float2*)(C + (size_t)(r0r + 8) * Nn + col) = v1;
            }
        }
    }
}

// ---------------- SIMT SGEMM (small M cases only) -------------------------
#define BM 128
#define BN 128
#define BK 8
#define TM 8
#define TN 8

template<bool RELU, bool BIAS>
__global__ void sgemm(const float* __restrict__ A, const float* __restrict__ B,
                      const float* __restrict__ bias, float* __restrict__ C,
                      int M, int Nn, int K)
{
    __shared__ float As[BK][BM];
    __shared__ float Bs[BK][BN];
    const int tid = threadIdx.x;
    const int row0 = blockIdx.y * BM;
    const int col0 = blockIdx.x * BN;
    const int tx = tid % 16;
    const int ty = tid / 16;

    float acc[TM][TN];
#pragma unroll
    for (int i = 0; i < TM; i++)
#pragma unroll
        for (int j = 0; j < TN; j++) acc[i][j] = 0.f;

    const int aRow = tid >> 1;
    const int aCol = (tid & 1) * 4;
    const int bRow = tid >> 5;
    const int bCol = (tid & 31) * 4;

    for (int k0 = 0; k0 < K; k0 += BK) {
        int gr = row0 + aRow;
        float4 av = make_float4(0.f, 0.f, 0.f, 0.f);
        if (gr < M) av = *(const float4*)(A + (size_t)gr * K + k0 + aCol);
        As[aCol + 0][aRow] = av.x;
        As[aCol + 1][aRow] = av.y;
        As[aCol + 2][aRow] = av.z;
        As[aCol + 3][aRow] = av.w;

        int gc = col0 + bCol;
        float4 bv = make_float4(0.f, 0.f, 0.f, 0.f);
        if (gc < Nn) bv = *(const float4*)(B + (size_t)(k0 + bRow) * Nn + gc);
        *(float4*)&Bs[bRow][bCol] = bv;
        __syncthreads();

#pragma unroll
        for (int kk = 0; kk < BK; kk++) {
            float ar[TM], br[TN];
#pragma unroll
            for (int i = 0; i < TM; i++) ar[i] = As[kk][ty * TM + i];
#pragma unroll
            for (int j = 0; j < TN; j++) br[j] = Bs[kk][tx * TN + j];
#pragma unroll
            for (int i = 0; i < TM; i++)
#pragma unroll
                for (int j = 0; j < TN; j++)
                    acc[i][j] = fmaf(ar[i], br[j], acc[i][j]);
        }
        __syncthreads();
    }

#pragma unroll
    for (int i = 0; i < TM; i++) {
        int r = row0 + ty * TM + i;
        if (r >= M) continue;
#pragma unroll
        for (int j = 0; j < TN; j++) {
            int c = col0 + tx * TN + j;
            if (c >= Nn) continue;
            float v = acc[i][j];
            if (BIAS) v += bias[c];
            if (RELU) v = fmaxf(v, 0.f);
            C[(size_t)r * Nn + c] = v;
        }
    }
}

template<bool BIAS>
__global__ void sgemm_bz(const float* __restrict__ A0, const float* __restrict__ B0,
                         const float* __restrict__ bias0, float* __restrict__ C0,
                         int M, int Nn, int K,
                         size_t sA, size_t sB, size_t sBias, size_t sC)
{
    const int z = blockIdx.z;
    const float* A = A0 + sA * z;
    const float* B = B0 + sB * z;
    const float* bias = BIAS ? (bias0 + sBias * z) : nullptr;
    float* C = C0 + sC * z;

    __shared__ float As[BK][BM];
    __shared__ float Bs[BK][BN];
    const int tid = threadIdx.x;
    const int row0 = blockIdx.y * BM;
    const int col0 = blockIdx.x * BN;
    const int tx = tid % 16;
    const int ty = tid / 16;

    float acc[TM][TN];
#pragma unroll
    for (int i = 0; i < TM; i++)
#pragma unroll
        for (int j = 0; j < TN; j++) acc[i][j] = 0.f;

    const int aRow = tid >> 1;
    const int aCol = (tid & 1) * 4;
    const int bRow = tid >> 5;
    const int bCol = (tid & 31) * 4;

    for (int k0 = 0; k0 < K; k0 += BK) {
        int gr = row0 + aRow;
        float4 av = make_float4(0.f, 0.f, 0.f, 0.f);
        if (gr < M) av = *(const float4*)(A + (size_t)gr * K + k0 + aCol);
        As[aCol + 0][aRow] = av.x;
        As[aCol + 1][aRow] = av.y;
        As[aCol + 2][aRow] = av.z;
        As[aCol + 3][aRow] = av.w;

        int gc = col0 + bCol;
        float4 bv = make_float4(0.f, 0.f, 0.f, 0.f);
        if (gc < Nn) bv = *(const float4*)(B + (size_t)(k0 + bRow) * Nn + gc);
        *(float4*)&Bs[bRow][bCol] = bv;
        __syncthreads();

#pragma unroll
        for (int kk = 0; kk < BK; kk++) {
            float ar[TM], br[TN];
#pragma unroll
            for (int i = 0; i < TM; i++) ar[i] = As[kk][ty * TM + i];
#pragma unroll
            for (int j = 0; j < TN; j++) br[j] = Bs[kk][tx * TN + j];
#pragma unroll
            for (int i = 0; i < TM; i++)
#pragma unroll
                for (int j = 0; j < TN; j++)
                    acc[i][j] = fmaf(ar[i], br[j], acc[i][j]);
        }
        __syncthreads();
    }

#pragma unroll
    for (int i = 0; i < TM; i++) {
        int r = row0 + ty * TM + i;
        if (r >= M) continue;
#pragma unroll
        for (int j = 0; j < TN; j++) {
            int c = col0 + tx * TN + j;
            if (c >= Nn) continue;
            float v = acc[i][j];
            if (BIAS) v += bias[c];
            C[(size_t)r * Nn + c] = v;
        }
    }
}

// ---------------- embedding (dual write f32 + f16) ------------
__global__ void embed_kernel(const int* __restrict__ cap, const float* __restrict__ emb,
                             const float* __restrict__ pos, float* __restrict__ X,
                             __half* __restrict__ Xh)
{
    int r = blockIdx.x;
    int t = r & (TT - 1);
    int c = cap[r];
    int d = threadIdx.x * 4;
    float4 e = *(const float4*)(emb + (size_t)c * DD + d);
    float4 p = *(const float4*)(pos + (size_t)t * DD + d);
    e.x += p.x; e.y += p.y; e.z += p.z; e.w += p.w;
    *(float4*)(X + (size_t)r * DD + d) = e;
    uint2 hv;
    hv.x = h2_as_u32(__floats2half2_rn(e.x, e.y));
    hv.y = h2_as_u32(__floats2half2_rn(e.z, e.w));
    *(uint2*)(Xh + (size_t)r * DD + d) = hv;
}

// ============ tensor-core flash attention (fp16 in/out, f32 softmax) ======
// Block: 64 q-rows of one (n,h). 128 threads = 4 warps, warp owns 16 q-rows.
// KV tiles of 64, double-buffered cp.async. Causal.
// smem: Q 8KB; KV[2] each K(8KB)+V(8KB).
// All tiles row-major [row][64 halves], unit swizzle: phys = u ^ (r&7).
__global__ __launch_bounds__(128) void flash_attn2(
    const __half* __restrict__ Q, const __half* __restrict__ K,
    const __half* __restrict__ V, __half* __restrict__ O)
{
    __shared__ __align__(16) unsigned char sQ[8192];
    __shared__ __align__(16) unsigned char sKV[2][16384];

    const int bid = blockIdx.x;
    const int qt = bid & 7;
    const int h  = (bid >> 3) & 15;
    const int n  = bid >> 7;
    const int q0 = qt * 64;

    const int tid = threadIdx.x;
    const int lane = tid & 31;
    const int warp = tid >> 5;
    const int g8 = lane >> 3, li = lane & 7;
    const int g = lane >> 2, tq = lane & 3;

    const uint32_t sQb = smem_u32(sQ);
    const uint32_t sKVb = smem_u32(sKV);

    // load Q tile (group 0)
#pragma unroll
    for (int i = 0; i < 4; i++) {
        const int ui = tid + 128 * i;
        const int r = ui >> 3, u = ui & 7;
        const int phys = r * 8 + (u ^ (r & 7));
        CPA16(sQb + phys * 16,
              Q + ((size_t)(n * TT + q0 + r)) * DD + h * DHD + u * 8);
    }
    CPA_COMMIT();

    auto load_kv = [&](int t, int buf) {
        const int j0 = t * 64;
        const uint32_t base = sKVb + (uint32_t)buf * 16384;
#pragma unroll
        for (int i = 0; i < 4; i++) {
            const int ui = tid + 128 * i;
            const int r = ui >> 3, u = ui & 7;
            const int phys = r * 8 + (u ^ (r & 7));
            const size_t go = ((size_t)(n * TT + j0 + r)) * DD + h * DHD + u * 8;
            CPA16(base + phys * 16, K + go);
            CPA16(base + 8192u + phys * 16, V + go);
        }
        CPA_COMMIT();
    };

    load_kv(0, 0);     // group 1
    CPA_WAIT1();       // Q done
    __syncthreads();

    // Q fragments (persist in regs)
    unsigned qa[4][4];
    {
        const int qrow = 16 * warp + (g8 & 1) * 8 + li;
#pragma unroll
        for (int kc = 0; kc < 4; kc++) {
            const int u = 2 * kc + (g8 >> 1);
            LDSM4(qa[kc][0], qa[kc][1], qa[kc][2], qa[kc][3],
                  sQb + (uint32_t)(qrow * 8 + (u ^ (qrow & 7))) * 16);
        }
    }

    float o[8][4];
#pragma unroll
    for (int j = 0; j < 8; j++)
#pragma unroll
        for (int c = 0; c < 4; c++) o[j][c] = 0.f;
    float m0 = -1e30f, m1 = -1e30f, l0 = 0.f, l1 = 0.f;

    const int r0q = q0 + 16 * warp + g;       // lane's row (also +8)
    const int nt = qt + 1;

    // ldmatrix lane addr components
    const int kbrow = (g8 >> 1) * 8 + li;     // S b-frags (non-trans on K)
    const int vrow  = (g8 & 1) * 8 + li;      // PV b-frags (trans on V)

    for (int t = 0; t < nt; t++) {
        const int buf = t & 1;
        __syncthreads();
        if (t + 1 < nt) load_kv(t + 1, buf ^ 1);
        else CPA_COMMIT();
        CPA_WAIT1();
        __syncthreads();

        const uint32_t kb = sKVb + (uint32_t)buf * 16384;
        const uint32_t vb = kb + 8192u;

        // ---- S = Q K^T ----
        float s[8][4];
#pragma unroll
        for (int j = 0; j < 8; j++)
#pragma unroll
            for (int c = 0; c < 4; c++) s[j][c] = 0.f;

#pragma unroll
        for (int kc = 0; kc < 4; kc++) {
            const int ku = 2 * kc + (g8 & 1);
#pragma unroll
            for (int jp = 0; jp < 4; jp++) {
                const int row = 16 * jp + kbrow;
                unsigned t0, t1, t2, t3;
                LDSM4(t0, t1, t2, t3,
                      kb + (uint32_t)(row * 8 + (ku ^ (row & 7))) * 16);
                MMA16816(s[2 * jp],     qa[kc][0], qa[kc][1], qa[kc][2], qa[kc][3], t0, t1);
                MMA16816(s[2 * jp + 1], qa[kc][0], qa[kc][1], qa[kc][2], qa[kc][3], t2, t3);
            }
        }

        // ---- scale + mask + online softmax ----
        const int j0 = t * 64;
        float mx0 = -1e30f, mx1 = -1e30f;
        if (t == qt) {
#pragma unroll
            for (int j = 0; j < 8; j++) {
                const int col = j0 + 8 * j + 2 * tq;
                s[j][0] = (col     <= r0q)     ? s[j][0] * 0.125f : -1e30f;
                s[j][1] = (col + 1 <= r0q)     ? s[j][1] * 0.125f : -1e30f;
                s[j][2] = (col     <= r0q + 8) ? s[j][2] * 0.125f : -1e30f;
                s[j][3] = (col + 1 <= r0q + 8) ? s[j][3] * 0.125f : -1e30f;
                mx0 = fmaxf(mx0, fmaxf(s[j][0], s[j][1]));
                mx1 = fmaxf(mx1, fmaxf(s[j][2], s[j][3]));
            }
        } else {
#pragma unroll
            for (int j = 0; j < 8; j++) {
                s[j][0] *= 0.125f; s[j][1] *= 0.125f;
                s[j][2] *= 0.125f; s[j][3] *= 0.125f;
                mx0 = fmaxf(mx0, fmaxf(s[j][0], s[j][1]));
                mx1 = fmaxf(mx1, fmaxf(s[j][2], s[j][3]));
            }
        }
        mx0 = fmaxf(mx0, __shfl_xor_sync(0xffffffffu, mx0, 1));
        mx0 = fmaxf(mx0, __shfl_xor_sync(0xffffffffu, mx0, 2));
        mx1 = fmaxf(mx1, __shfl_xor_sync(0xffffffffu, mx1, 1));
        mx1 = fmaxf(mx1, __shfl_xor_sync(0xffffffffu, mx1, 2));

        const float mn0 = fmaxf(m0, mx0);
        const float mn1 = fmaxf(m1, mx1);
        const float sc0 = __expf(m0 - mn0);
        const float sc1 = __expf(m1 - mn1);
        m0 = mn0; m1 = mn1;
        l0 *= sc0; l1 *= sc1;
#pragma unroll
        for (int j = 0; j < 8; j++) {
            o[j][0] *= sc0; o[j][1] *= sc0;
            o[j][2] *= sc1; o[j][3] *= sc1;
        }

        unsigned pa[8], pb[8];
#pragma unroll
        for (int j = 0; j < 8; j++) {
            const float p0 = __expf(s[j][0] - mn0);
            const float p1 = __expf(s[j][1] - mn0);
            const float p2 = __expf(s[j][2] - mn1);
            const float p3 = __expf(s[j][3] - mn1);
            l0 += p0 + p1; l1 += p2 + p3;
            pa[j] = h2_as_u32(__floats2half2_rn(p0, p1));
            pb[j] = h2_as_u32(__floats2half2_rn(p2, p3));
        }

        // ---- O += P V ----
#pragma unroll
        for (int kc = 0; kc < 4; kc++) {
#pragma unroll
            for (int jp = 0; jp < 4; jp++) {
                const int row = 16 * kc + vrow;
                const int u = 2 * jp + (g8 >> 1);
                unsigned t0, t1, t2, t3;
                LDSM4T(t0, t1, t2, t3,
                       vb + (uint32_t)(row * 8 + (u ^ (row & 7))) * 16);
                MMA16816(o[2 * jp],     pa[2 * kc], pb[2 * kc], pa[2 * kc + 1], pb[2 * kc + 1], t0, t1);
                MMA16816(o[2 * jp + 1], pa[2 * kc], pb[2 * kc], pa[2 * kc + 1], pb[2 * kc + 1], t2, t3);
            }
        }
    }

    // ---- finalize ----
    l0 += __shfl_xor_sync(0xffffffffu, l0, 1);
    l0 += __shfl_xor_sync(0xffffffffu, l0, 2);
    l1 += __shfl_xor_sync(0xffffffffu, l1, 1);
    l1 += __shfl_xor_sync(0xffffffffu, l1, 2);
    const float inv0 = 1.f / l0;
    const float inv1 = 1.f / l1;

    // quirk layout: O[(n*H + h)*T + q][dh]
    const size_t obase = ((size_t)((n * HH + h) * TT + q0 + 16 * warp)) * DHD;
#pragma unroll
    for (int j = 0; j < 8; j++) {
        const int col = 8 * j + 2 * tq;
        *(unsigned*)(O + obase + (size_t)g * DHD + col) =
            h2_as_u32(__floats2half2_rn(o[j][0] * inv0, o[j][1] * inv0));
        *(unsigned*)(O + obase + (size_t)(g + 8) * DHD + col) =
            h2_as_u32(__floats2half2_rn(o[j][2] * inv1, o[j][3] * inv1));
    }
}

// ---------------- residual + LayerNorm (dual write) ----------------------
__global__ void ln_kernel(const float* __restrict__ X, const float* __restrict__ Rsd,
                          const float* __restrict__ g, const float* __restrict__ b,
                          float* __restrict__ out, __half* __restrict__ outh, int mode)
{
    const int r = blockIdx.x;
    const int tid = threadIdx.x;
    size_t rr;
    if (mode == 0) rr = (size_t)r;
    else {
        int n = r >> 9;
        int s = r & (TT - 1);
        rr = (size_t)(n * 16 + (s >> 5));
    }
    const float* xr = X + (size_t)r * DD;
    const float* dr = Rsd + rr * DD;
    const int d = tid * 4;
    float4 xv = *(const float4*)(xr + d);
    float4 dv = *(const float4*)(dr + d);
    float v0 = xv.x + dv.x, v1 = xv.y + dv.y, v2 = xv.z + dv.z, v3 = xv.w + dv.w;

    __shared__ float s1[256], s2[256];
    s1[tid] = v0 + v1 + v2 + v3;
    s2[tid] = v0 * v0 + v1 * v1 + v2 * v2 + v3 * v3;
    __syncthreads();
    for (int st = 128; st > 0; st >>= 1) {
        if (tid < st) { s1[tid] += s1[tid + st]; s2[tid] += s2[tid + st]; }
        __syncthreads();
    }
    const float mean = s1[0] * (1.f / DD);
    const float var = s2[0] * (1.f / DD) - mean * mean;
    const float rstd = rsqrtf(var + 1e-5f);

    float4 ov;
    ov.x = g[d + 0] * (v0 - mean) * rstd + b[d + 0];
    ov.y = g[d + 1] * (v1 - mean) * rstd + b[d + 1];
    ov.z = g[d + 2] * (v2 - mean) * rstd + b[d + 2];
    ov.w = g[d + 3] * (v3 - mean) * rstd + b[d + 3];
    *(float4*)(out + (size_t)r * DD + d) = ov;
    uint2 hv;
    hv.x = h2_as_u32(__floats2half2_rn(ov.x, ov.y));
    hv.y = h2_as_u32(__floats2half2_rn(ov.z, ov.w));
    *(uint2*)(outh + (size_t)r * DD + d) = hv;
}

// ------------- tiled rows for cross-attn out-projection (batched) --------
__global__ void tilefe_kernel(const float* __restrict__ fev, float* __restrict__ A)
{
    const int bx = blockIdx.x;
    const int z = bx >> 8;
    const int rl = bx & 255;
    const int n = rl >> 4;
    const int g = rl & 15;
    const int d = threadIdx.x * 4;
    const float* src = fev + (size_t)z * NB * DD + (size_t)n * DD + g * 64;
    float4 v = *(const float4*)(src + (d & 63));
    *(float4*)(A + (size_t)z * NB * 16 * DD + (size_t)rl * DD + d) = v;
}

// ---------------- launch --------------------------------------------------
extern "C" void kernel_launch(void* const* d_in, const int* in_sizes, int n_in,
                              void* d_out, int out_size)
{
    const float* features = (const float*)d_in[0];
    const int*   captions = (const int*)d_in[1];
    const float* feat_W   = (const float*)d_in[2];
    const float* feat_b   = (const float*)d_in[3];
    const float* cap_emb  = (const float*)d_in[4];
    const float* pos_emb  = (const float*)d_in[5];
    const float* sa_Wq = (const float*)d_in[6];
    const float* sa_Wk = (const float*)d_in[7];
    const float* sa_Wv = (const float*)d_in[8];
    const float* sa_Wo = (const float*)d_in[9];
    const float* sa_bo = (const float*)d_in[10];
    const float* sa_g  = (const float*)d_in[11];
    const float* sa_b  = (const float*)d_in[12];
    const float* ca_Wv = (const float*)d_in[15];
    const float* ca_Wo = (const float*)d_in[16];
    const float* ca_bo = (const float*)d_in[17];
    const float* ca_g  = (const float*)d_in[18];
    const float* ca_b  = (const float*)d_in[19];
    const float* ff_W1 = (const float*)d_in[20];
    const float* ff_b1 = (const float*)d_in[21];
    const float* ff_W2 = (const float*)d_in[22];
    const float* ff_b2 = (const float*)d_in[23];
    const float* ff_g  = (const float*)d_in[24];
    const float* ff_b  = (const float*)d_in[25];
    const float* score_W = (const float*)d_in[26];
    const float* score_b = (const float*)d_in[27];
    float* out = (float*)d_out;

    float *px, *pt, *pfe, *pfev, *pzt, *pz;
    __half *pxh, *pqh, *pkh, *pvh, *pattnh, *phh;
    __half *pwqh, *pwkh, *pwvh, *pwoh, *pw1h, *pw2h, *pwsh;
    cudaGetSymbolAddress((void**)&px,    g_x);
    cudaGetSymbolAddress((void**)&pt,    g_t);
    cudaGetSymbolAddress((void**)&pfe,   g_fe);
    cudaGetSymbolAddress((void**)&pfev,  g_fev);
    cudaGetSymbolAddress((void**)&pzt,   g_ztile);
    cudaGetSymbolAddress((void**)&pz,    g_z);
    cudaGetSymbolAddress((void**)&pxh,    g_xh);
    cudaGetSymbolAddress((void**)&pqh,    g_qh);
    cudaGetSymbolAddress((void**)&pkh,    g_kh);
    cudaGetSymbolAddress((void**)&pvh,    g_vh);
    cudaGetSymbolAddress((void**)&pattnh, g_attnh);
    cudaGetSymbolAddress((void**)&phh,    g_hh);
    cudaGetSymbolAddress((void**)&pwqh,   g_wqh);
    cudaGetSymbolAddress((void**)&pwkh,   g_wkh);
    cudaGetSymbolAddress((void**)&pwvh,   g_wvh);
    cudaGetSymbolAddress((void**)&pwoh,   g_woh);
    cudaGetSymbolAddress((void**)&pw1h,   g_w1h);
    cudaGetSymbolAddress((void**)&pw2h,   g_w2h);
    cudaGetSymbolAddress((void**)&pwsh,   g_wsh);

    const int tb = 256;
    const int nDD = LL * DD * DD;
    const int nFF = LL * DD * FFD;
    const int nS = DD * VV;

    const dim3 gP(DD / 128, ROWS / 128);     // 8 x 64
    const dim3 gF(FFD / 128, ROWS / 128);    // 16 x 64

    f2h_kernel<<<(nDD / 4 + tb - 1) / tb, tb>>>(sa_Wq, pwqh, nDD);
    sgemm<false, true><<<dim3(DD / BN, 1), 256>>>(features, feat_W, feat_b, pfe, NB, DD, DIN);
    embed_kernel<<<ROWS, 256>>>(captions, cap_emb, pos_emb, px, pxh);
    f2h_kernel<<<(nDD / 4 + tb - 1) / tb, tb>>>(sa_Wk, pwkh, nDD);
    f2h_kernel<<<(nDD / 4 + tb - 1) / tb, tb>>>(sa_Wv, pwvh, nDD);
    hgemm<false, false, true><<<gP, 128>>>(pxh, pwqh, nullptr, pqh, ROWS, DD, DD);
    hgemm<false, false, true><<<gP, 128>>>(pxh, pwkh, nullptr, pkh, ROWS, DD, DD);
    hgemm<false, false, true><<<gP, 128>>>(pxh, pwvh, nullptr, pvh, ROWS, DD, DD);

    f2h_kernel<<<(nDD / 4 + tb - 1) / tb, tb>>>(sa_Wo, pwoh, nDD);
    f2h_kernel<<<(nFF / 4 + tb - 1) / tb, tb>>>(ff_W1, pw1h, nFF);
    f2h_kernel<<<(nFF / 4 + tb - 1) / tb, tb>>>(ff_W2, pw2h, nFF);
    f2h_kernel<<<(nS / 4 + tb - 1) / tb, tb>>>(score_W, pwsh, nS);

    // cross-attention contributions for all layers (f32 SIMT path)
    sgemm_bz<false><<<dim3(DD / BN, 1, LL), 256>>>(pfe, ca_Wv, nullptr, pfev,
                                                   NB, DD, DD,
                                                   0, (size_t)DD * DD, 0, (size_t)NB * DD);
    tilefe_kernel<<<LL * NB * 16, 256>>>(pfev, pzt);
    sgemm_bz<true><<<dim3(DD / BN, 2, LL), 256>>>(pzt, ca_Wo, ca_bo, pz,
                                                  NB * 16, DD, DD,
                                                  (size_t)NB * 16 * DD, (size_t)DD * DD,
                                                  DD, (size_t)NB * 16 * DD);

    for (int i = 0; i < LL; i++) {
        if (i > 0) {
            hgemm<false, false, true><<<gP, 128>>>(pxh, pwqh + (size_t)i * DD * DD, nullptr, pqh, ROWS, DD, DD);
            hgemm<false, false, true><<<gP, 128>>>(pxh, pwkh + (size_t)i * DD * DD, nullptr, pkh, ROWS, DD, DD);
            hgemm<false, false, true><<<gP, 128>>>(pxh, pwvh + (size_t)i * DD * DD, nullptr, pvh, ROWS, DD, DD);
        }
        flash_attn2<<<NB * HH * 8, 128>>>(pqh, pkh, pvh, pattnh);
        hgemm<false, true, false><<<gP, 128>>>(pattnh, pwoh + (size_t)i * DD * DD,
                                               sa_bo + (size_t)i * DD, pt, ROWS, DD, DD);
        ln_kernel<<<ROWS, 256>>>(px, pt, sa_g + (size_t)i * DD, sa_b + (size_t)i * DD, px, pxh, 0);

        ln_kernel<<<ROWS, 256>>>(px, pz + (size_t)i * NB * 16 * DD,
                                 ca_g + (size_t)i * DD, ca_b + (size_t)i * DD, px, pxh, 1);

        hgemm<true, true, true><<<gF, 128>>>(pxh, pw1h + (size_t)i * DD * FFD,
                                             ff_b1 + (size_t)i * FFD, phh, ROWS, FFD, DD);
        hgemm<false, true, false><<<gP, 128>>>(phh, pw2h + (size_t)i * FFD * DD,
                                               ff_b2 + (size_t)i * DD, pt, ROWS, DD, FFD);
        ln_kernel<<<ROWS, 256>>>(px, pt, ff_g + (size_t)i * DD, ff_b + (size_t)i * DD, px, pxh, 0);
    }

    // final vocab projection
    hgemm<false, true, false><<<dim3((VV + 127) / 128, ROWS / 128), 128>>>(
        pxh, pwsh, score_b, out, ROWS, VV, DD);
}

// round 11
// speedup vs baseline: 15.8019x; 1.0261x over previous
#include <cuda_runtime.h>
#include <cuda_bf16.h>
#include <cuda_fp16.h>
#include <cstdio>
#include <cstdint>

// Problem constants
#define NB   16
#define TT   512
#define VV   10000
#define DIN  2048
#define DD   1024
#define HH   16
#define LL   4
#define FFD  2048
#define DHD  64
#define ROWS (NB*TT)          // 8192
#define QKVLD (3*DD)          // 3072

// ---------------- device scratch ----------------
__device__ float g_x[ROWS * DD];
__device__ float g_fe[NB * DD];
__device__ float g_fev[LL * NB * DD];
__device__ float g_ztile[LL * NB * 16 * DD];
__device__ float g_z[LL * NB * 16 * DD];

// fp16 side
__device__ __half g_xh[ROWS * DD];
__device__ __half g_qkvh[ROWS * QKVLD];     // packed Q|K|V per row
__device__ __half g_attnh[ROWS * DD];
__device__ __half g_th[ROWS * DD];          // fp16 GEMM deltas (Wo, FF2)
__device__ __half g_hh[ROWS * FFD];
__device__ __half g_wqkvh[LL * DD * QKVLD]; // packed [k][Q|K|V]
__device__ __half g_woh[LL * DD * DD];
__device__ __half g_w1h[LL * DD * FFD];
__device__ __half g_w2h[LL * FFD * DD];
__device__ __half g_wsh[DD * VV];

// ---------------- small helpers ----------------
__device__ __forceinline__ unsigned h2_as_u32(__half2 h) {
    return *(unsigned*)&h;
}
__device__ __forceinline__ uint32_t smem_u32(const void* p) {
    uint32_t a;
    asm("{ .reg .u64 t; cvta.to.shared.u64 t, %1; cvt.u32.u64 %0, t; }"
        : "=r"(a) : "l"(p));
    return a;
}

#define CPA16(dst, src) \
    asm volatile("cp.async.cg.shared.global [%0], [%1], 16;" :: "r"(dst), "l"(src))
#define CPA16Z(dst, src, sz) \
    asm volatile("cp.async.cg.shared.global [%0], [%1], 16, %2;" :: "r"(dst), "l"(src), "r"(sz))
#define CPA_COMMIT() asm volatile("cp.async.commit_group;" ::: "memory")
#define CPA_WAIT1()  asm volatile("cp.async.wait_group 1;" ::: "memory")

#define LDSM4(r0, r1, r2, r3, addr) \
    asm volatile("ldmatrix.sync.aligned.m8n8.x4.shared.b16 {%0,%1,%2,%3}, [%4];" \
                 : "=r"(r0), "=r"(r1), "=r"(r2), "=r"(r3) : "r"(addr))
#define LDSM4T(r0, r1, r2, r3, addr) \
    asm volatile("ldmatrix.sync.aligned.m8n8.x4.trans.shared.b16 {%0,%1,%2,%3}, [%4];" \
                 : "=r"(r0), "=r"(r1), "=r"(r2), "=r"(r3) : "r"(addr))

#define MMA16816(acc, a0, a1, a2, a3, b0, b1) \
    asm volatile( \
        "mma.sync.aligned.m16n8k16.row.col.f32.f16.f16.f32 " \
        "{%0,%1,%2,%3}, {%4,%5,%6,%7}, {%8,%9}, {%0,%1,%2,%3};" \
        : "+f"((acc)[0]), "+f"((acc)[1]), "+f"((acc)[2]), "+f"((acc)[3]) \
        : "r"(a0), "r"(a1), "r"(a2), "r"(a3), "r"(b0), "r"(b1))

// ---------------- f32 -> f16 conversion (n % 4 == 0) ----------------
__global__ void f2h_kernel(const float* __restrict__ src, __half* __restrict__ dst, int n)
{
    int i = (blockIdx.x * blockDim.x + threadIdx.x) * 4;
    if (i < n) {
        float4 v = *(const float4*)(src + i);
        uint2 o;
        o.x = h2_as_u32(__floats2half2_rn(v.x, v.y));
        o.y = h2_as_u32(__floats2half2_rn(v.z, v.w));
        *(uint2*)(dst + i) = o;
    }
}

// pack Wq|Wk|Wv -> [l][k][3*DD] fp16.  blockIdx.y = which source.
__global__ void f2h3_kernel(const float* __restrict__ wq, const float* __restrict__ wk,
                            const float* __restrict__ wv, __half* __restrict__ dst)
{
    const int sel = blockIdx.y;
    const float* src = (sel == 0) ? wq : (sel == 1) ? wk : wv;
    int i = (blockIdx.x * blockDim.x + threadIdx.x) * 4;   // over LL*DD*DD
    if (i < LL * DD * DD) {
        float4 v = *(const float4*)(src + i);
        const int lk = i >> 10;          // l*DD + k
        const int j  = i & (DD - 1);
        __half* d = dst + (size_t)lk * QKVLD + sel * DD + j;
        uint2 o;
        o.x = h2_as_u32(__floats2half2_rn(v.x, v.y));
        o.y = h2_as_u32(__floats2half2_rn(v.z, v.w));
        *(uint2*)d = o;
    }
}

// ==================== fp16 GEMM: cp.async + ldmatrix + mma.m16n8k16 =======
template<bool RELU, bool BIAS, bool HOUT>
__global__ __launch_bounds__(128, 2) void hgemm(
    const __half* __restrict__ A, const __half* __restrict__ B,
    const float* __restrict__ bias, void* __restrict__ Cv,
    int M, int Nn, int K)
{
    __shared__ __align__(16) unsigned char sm[3][16384];

    const int tid  = threadIdx.x;
    const int lane = tid & 31;
    const int warp = tid >> 5;
    const int row0 = blockIdx.y * 128;
    const int col0 = blockIdx.x * 128;
    const int wm = (warp >> 1) * 64;
    const int wn = (warp & 1) * 64;
    const int g  = lane >> 2;
    const int tq = lane & 3;

    const uint32_t sbase = smem_u32(sm);

    int aR[4], aU[4], aPhys[4];
    int bKr[4], bNu[4], bPhys[4];
    unsigned bSz[4];
#pragma unroll
    for (int i = 0; i < 4; i++) {
        const int ul = tid + 128 * i;
        aR[i] = ul >> 2; aU[i] = ul & 3;
        aPhys[i] = aR[i] * 4 + (aU[i] ^ ((aR[i] & 7) >> 1));
        bKr[i] = ul >> 4; bNu[i] = ul & 15;
        bPhys[i] = bKr[i] * 16 + (bNu[i] ^ (bKr[i] & 7));
        bSz[i] = (col0 + bNu[i] * 8 + 7 < Nn) ? 16u : 0u;
    }

    const int g8 = lane >> 3, li = lane & 7;
    const int rowa = wm + (g8 & 1) * 8 + li;
    const int sa = (rowa & 7) >> 1;
    const int ub = g8 >> 1;
    const uint32_t aOff0 = (uint32_t)rowa * 64 + ((unsigned)((0 + ub) ^ sa) << 4);
    const uint32_t aOff1 = (uint32_t)rowa * 64 + ((unsigned)((2 + ub) ^ sa) << 4);
    const int krb = (g8 & 1) * 8 + li;
    const int sb = krb & 7;
    const int nub = (wn >> 3) + (g8 >> 1);
    uint32_t bOff[2][4];
#pragma unroll
    for (int kk = 0; kk < 2; kk++)
#pragma unroll
        for (int jp = 0; jp < 4; jp++)
            bOff[kk][jp] = 8192u + (uint32_t)krb * 256 + (uint32_t)kk * 4096
                         + ((unsigned)((nub + 2 * jp) ^ sb) << 4);

    float acc[4][8][4];
#pragma unroll
    for (int i = 0; i < 4; i++)
#pragma unroll
        for (int j = 0; j < 8; j++)
#pragma unroll
            for (int c = 0; c < 4; c++) acc[i][j][c] = 0.f;

    const int nk = K >> 5;

    auto issue = [&](int c, int st) {
        const int k0 = c * 32;
        const uint32_t stb = sbase + (uint32_t)st * 16384;
#pragma unroll
        for (int i = 0; i < 4; i++) {
            const __half* src = A + (size_t)(row0 + aR[i]) * K + k0 + aU[i] * 8;
            CPA16(stb + (uint32_t)aPhys[i] * 16, src);
        }
#pragma unroll
        for (int i = 0; i < 4; i++) {
            const int gc = col0 + bNu[i] * 8;
            const __half* src = B + (size_t)(k0 + bKr[i]) * Nn + (bSz[i] ? gc : 0);
            CPA16Z(stb + 8192u + (uint32_t)bPhys[i] * 16, src, bSz[i]);
        }
        CPA_COMMIT();
    };

    issue(0, 0);
    issue(1, 1);

    for (int it = 0; it < nk; it++) {
        const int st = it % 3;
        CPA_WAIT1();
        __syncthreads();
        if (it + 2 < nk) issue(it + 2, (it + 2) % 3);
        else CPA_COMMIT();

        const uint32_t stb = sbase + (uint32_t)st * 16384;
#pragma unroll
        for (int kk = 0; kk < 2; kk++) {
            unsigned af[4][4], bf[8][2];
            const uint32_t aO = (kk == 0) ? aOff0 : aOff1;
#pragma unroll
            for (int i = 0; i < 4; i++)
                LDSM4(af[i][0], af[i][1], af[i][2], af[i][3],
                      stb + aO + (uint32_t)i * 1024);
#pragma unroll
            for (int jp = 0; jp < 4; jp++) {
                unsigned t0, t1, t2, t3;
                LDSM4T(t0, t1, t2, t3, stb + bOff[kk][jp]);
                bf[2 * jp][0] = t0; bf[2 * jp][1] = t1;
                bf[2 * jp + 1][0] = t2; bf[2 * jp + 1][1] = t3;
            }
#pragma unroll
            for (int i = 0; i < 4; i++)
#pragma unroll
                for (int j = 0; j < 8; j++)
                    MMA16816(acc[i][j], af[i][0], af[i][1], af[i][2], af[i][3],
                             bf[j][0], bf[j][1]);
        }
    }

#pragma unroll
    for (int i = 0; i < 4; i++) {
        const int r0r = row0 + wm + i * 16 + g;
#pragma unroll
        for (int j = 0; j < 8; j++) {
            const int col = col0 + wn + j * 8 + tq * 2;
            if (col >= Nn) continue;
            float2 bsv = make_float2(0.f, 0.f);
            if (BIAS) bsv = *(const float2*)(bias + col);
            float2 v0, v1;
            v0.x = acc[i][j][0] + (BIAS ? bsv.x : 0.f);
            v0.y = acc[i][j][1] + (BIAS ? bsv.y : 0.f);
            v1.x = acc[i][j][2] + (BIAS ? bsv.x : 0.f);
            v1.y = acc[i][j][3] + (BIAS ? bsv.y : 0.f);
            if (RELU) {
                v0.x = fmaxf(v0.x, 0.f); v0.y = fmaxf(v0.y, 0.f);
                v1.x = fmaxf(v1.x, 0.f); v1.y = fmaxf(v1.y, 0.f);
            }
            if (HOUT) {
                __half* C = (__half*)Cv;
                *(unsigned*)(C + (size_t)r0r * Nn + col)       = h2_as_u32(__floats2half2_rn(v0.x, v0.y));
                *(unsigned*)(C + (size_t)(r0r + 8) * Nn + col) = h2_as_u32(__floats2half2_rn(v1.x, v1.y));
            } else {
                float* C = (float*)Cv;
                *(float2*)(C + (size_t)r0r * Nn + col) = v0;
                *(float2*)(C + (size_t)(r0r + 8) * Nn + col) = v1;
            }
        }
    }
}

// ---------------- SIMT SGEMM (small M cases only) -------------------------
#define BM 128
#define BN 128
#define BK 8
#define TM 8
#define TN 8

template<bool RELU, bool BIAS>
__global__ void sgemm(const float* __restrict__ A, const float* __restrict__ B,
                      const float* __restrict__ bias, float* __restrict__ C,
                      int M, int Nn, int K)
{
    __shared__ float As[BK][BM];
    __shared__ float Bs[BK][BN];
    const int tid = threadIdx.x;
    const int row0 = blockIdx.y * BM;
    const int col0 = blockIdx.x * BN;
    const int tx = tid % 16;
    const int ty = tid / 16;

    float acc[TM][TN];
#pragma unroll
    for (int i = 0; i < TM; i++)
#pragma unroll
        for (int j = 0; j < TN; j++) acc[i][j] = 0.f;

    const int aRow = tid >> 1;
    const int aCol = (tid & 1) * 4;
    const int bRow = tid >> 5;
    const int bCol = (tid & 31) * 4;

    for (int k0 = 0; k0 < K; k0 += BK) {
        int gr = row0 + aRow;
        float4 av = make_float4(0.f, 0.f, 0.f, 0.f);
        if (gr < M) av = *(const float4*)(A + (size_t)gr * K + k0 + aCol);
        As[aCol + 0][aRow] = av.x;
        As[aCol + 1][aRow] = av.y;
        As[aCol + 2][aRow] = av.z;
        As[aCol + 3][aRow] = av.w;

        int gc = col0 + bCol;
        float4 bv = make_float4(0.f, 0.f, 0.f, 0.f);
        if (gc < Nn) bv = *(const float4*)(B + (size_t)(k0 + bRow) * Nn + gc);
        *(float4*)&Bs[bRow][bCol] = bv;
        __syncthreads();

#pragma unroll
        for (int kk = 0; kk < BK; kk++) {
            float ar[TM], br[TN];
#pragma unroll
            for (int i = 0; i < TM; i++) ar[i] = As[kk][ty * TM + i];
#pragma unroll
            for (int j = 0; j < TN; j++) br[j] = Bs[kk][tx * TN + j];
#pragma unroll
            for (int i = 0; i < TM; i++)
#pragma unroll
                for (int j = 0; j < TN; j++)
                    acc[i][j] = fmaf(ar[i], br[j], acc[i][j]);
        }
        __syncthreads();
    }

#pragma unroll
    for (int i = 0; i < TM; i++) {
        int r = row0 + ty * TM + i;
        if (r >= M) continue;
#pragma unroll
        for (int j = 0; j < TN; j++) {
            int c = col0 + tx * TN + j;
            if (c >= Nn) continue;
            float v = acc[i][j];
            if (BIAS) v += bias[c];
            if (RELU) v = fmaxf(v, 0.f);
            C[(size_t)r * Nn + c] = v;
        }
    }
}

template<bool BIAS>
__global__ void sgemm_bz(const float* __restrict__ A0, const float* __restrict__ B0,
                         const float* __restrict__ bias0, float* __restrict__ C0,
                         int M, int Nn, int K,
                         size_t sA, size_t sB, size_t sBias, size_t sC)
{
    const int z = blockIdx.z;
    const float* A = A0 + sA * z;
    const float* B = B0 + sB * z;
    const float* bias = BIAS ? (bias0 + sBias * z) : nullptr;
    float* C = C0 + sC * z;

    __shared__ float As[BK][BM];
    __shared__ float Bs[BK][BN];
    const int tid = threadIdx.x;
    const int row0 = blockIdx.y * BM;
    const int col0 = blockIdx.x * BN;
    const int tx = tid % 16;
    const int ty = tid / 16;

    float acc[TM][TN];
#pragma unroll
    for (int i = 0; i < TM; i++)
#pragma unroll
        for (int j = 0; j < TN; j++) acc[i][j] = 0.f;

    const int aRow = tid >> 1;
    const int aCol = (tid & 1) * 4;
    const int bRow = tid >> 5;
    const int bCol = (tid & 31) * 4;

    for (int k0 = 0; k0 < K; k0 += BK) {
        int gr = row0 + aRow;
        float4 av = make_float4(0.f, 0.f, 0.f, 0.f);
        if (gr < M) av = *(const float4*)(A + (size_t)gr * K + k0 + aCol);
        As[aCol + 0][aRow] = av.x;
        As[aCol + 1][aRow] = av.y;
        As[aCol + 2][aRow] = av.z;
        As[aCol + 3][aRow] = av.w;

        int gc = col0 + bCol;
        float4 bv = make_float4(0.f, 0.f, 0.f, 0.f);
        if (gc < Nn) bv = *(const float4*)(B + (size_t)(k0 + bRow) * Nn + gc);
        *(float4*)&Bs[bRow][bCol] = bv;
        __syncthreads();

#pragma unroll
        for (int kk = 0; kk < BK; kk++) {
            float ar[TM], br[TN];
#pragma unroll
            for (int i = 0; i < TM; i++) ar[i] = As[kk][ty * TM + i];
#pragma unroll
            for (int j = 0; j < TN; j++) br[j] = Bs[kk][tx * TN + j];
#pragma unroll
            for (int i = 0; i < TM; i++)
#pragma unroll
                for (int j = 0; j < TN; j++)
                    acc[i][j] = fmaf(ar[i], br[j], acc[i][j]);
        }
        __syncthreads();
    }

#pragma unroll
    for (int i = 0; i < TM; i++) {
        int r = row0 + ty * TM + i;
        if (r >= M) continue;
#pragma unroll
        for (int j = 0; j < TN; j++) {
            int c = col0 + tx * TN + j;
            if (c >= Nn) continue;
            float v = acc[i][j];
            if (BIAS) v += bias[c];
            C[(size_t)r * Nn + c] = v;
        }
    }
}

// ---------------- embedding (dual write f32 + f16) ------------
__global__ void embed_kernel(const int* __restrict__ cap, const float* __restrict__ emb,
                             const float* __restrict__ pos, float* __restrict__ X,
                             __half* __restrict__ Xh)
{
    int r = blockIdx.x;
    int t = r & (TT - 1);
    int c = cap[r];
    int d = threadIdx.x * 4;
    float4 e = *(const float4*)(emb + (size_t)c * DD + d);
    float4 p = *(const float4*)(pos + (size_t)t * DD + d);
    e.x += p.x; e.y += p.y; e.z += p.z; e.w += p.w;
    *(float4*)(X + (size_t)r * DD + d) = e;
    uint2 hv;
    hv.x = h2_as_u32(__floats2half2_rn(e.x, e.y));
    hv.y = h2_as_u32(__floats2half2_rn(e.z, e.w));
    *(uint2*)(Xh + (size_t)r * DD + d) = hv;
}

// ============ tensor-core flash attention (packed QKV input) ==============
// Q,K,V pointers into g_qkvh with row stride QKVLD.
__global__ __launch_bounds__(128) void flash_attn2(
    const __half* __restrict__ Q, const __half* __restrict__ K,
    const __half* __restrict__ V, __half* __restrict__ O)
{
    __shared__ __align__(16) unsigned char sQ[8192];
    __shared__ __align__(16) unsigned char sKV[2][16384];

    const int bid = blockIdx.x;
    const int qt = bid & 7;
    const int h  = (bid >> 3) & 15;
    const int n  = bid >> 7;
    const int q0 = qt * 64;

    const int tid = threadIdx.x;
    const int lane = tid & 31;
    const int warp = tid >> 5;
    const int g8 = lane >> 3, li = lane & 7;
    const int g = lane >> 2, tq = lane & 3;

    const uint32_t sQb = smem_u32(sQ);
    const uint32_t sKVb = smem_u32(sKV);

#pragma unroll
    for (int i = 0; i < 4; i++) {
        const int ui = tid + 128 * i;
        const int r = ui >> 3, u = ui & 7;
        const int phys = r * 8 + (u ^ (r & 7));
        CPA16(sQb + phys * 16,
              Q + ((size_t)(n * TT + q0 + r)) * QKVLD + h * DHD + u * 8);
    }
    CPA_COMMIT();

    auto load_kv = [&](int t, int buf) {
        const int j0 = t * 64;
        const uint32_t base = sKVb + (uint32_t)buf * 16384;
#pragma unroll
        for (int i = 0; i < 4; i++) {
            const int ui = tid + 128 * i;
            const int r = ui >> 3, u = ui & 7;
            const int phys = r * 8 + (u ^ (r & 7));
            const size_t go = ((size_t)(n * TT + j0 + r)) * QKVLD + h * DHD + u * 8;
            CPA16(base + phys * 16, K + go);
            CPA16(base + 8192u + phys * 16, V + go);
        }
        CPA_COMMIT();
    };

    load_kv(0, 0);
    CPA_WAIT1();
    __syncthreads();

    unsigned qa[4][4];
    {
        const int qrow = 16 * warp + (g8 & 1) * 8 + li;
#pragma unroll
        for (int kc = 0; kc < 4; kc++) {
            const int u = 2 * kc + (g8 >> 1);
            LDSM4(qa[kc][0], qa[kc][1], qa[kc][2], qa[kc][3],
                  sQb + (uint32_t)(qrow * 8 + (u ^ (qrow & 7))) * 16);
        }
    }

    float o[8][4];
#pragma unroll
    for (int j = 0; j < 8; j++)
#pragma unroll
        for (int c = 0; c < 4; c++) o[j][c] = 0.f;
    float m0 = -1e30f, m1 = -1e30f, l0 = 0.f, l1 = 0.f;

    const int r0q = q0 + 16 * warp + g;
    const int nt = qt + 1;

    const int kbrow = (g8 >> 1) * 8 + li;
    const int vrow  = (g8 & 1) * 8 + li;

    for (int t = 0; t < nt; t++) {
        const int buf = t & 1;
        __syncthreads();
        if (t + 1 < nt) load_kv(t + 1, buf ^ 1);
        else CPA_COMMIT();
        CPA_WAIT1();
        __syncthreads();

        const uint32_t kb = sKVb + (uint32_t)buf * 16384;
        const uint32_t vb = kb + 8192u;

        float s[8][4];
#pragma unroll
        for (int j = 0; j < 8; j++)
#pragma unroll
            for (int c = 0; c < 4; c++) s[j][c] = 0.f;

#pragma unroll
        for (int kc = 0; kc < 4; kc++) {
            const int ku = 2 * kc + (g8 & 1);
#pragma unroll
            for (int jp = 0; jp < 4; jp++) {
                const int row = 16 * jp + kbrow;
                unsigned t0, t1, t2, t3;
                LDSM4(t0, t1, t2, t3,
                      kb + (uint32_t)(row * 8 + (ku ^ (row & 7))) * 16);
                MMA16816(s[2 * jp],     qa[kc][0], qa[kc][1], qa[kc][2], qa[kc][3], t0, t1);
                MMA16816(s[2 * jp + 1], qa[kc][0], qa[kc][1], qa[kc][2], qa[kc][3], t2, t3);
            }
        }

        const int j0 = t * 64;
        float mx0 = -1e30f, mx1 = -1e30f;
        if (t == qt) {
#pragma unroll
            for (int j = 0; j < 8; j++) {
                const int col = j0 + 8 * j + 2 * tq;
                s[j][0] = (col     <= r0q)     ? s[j][0] * 0.125f : -1e30f;
                s[j][1] = (col + 1 <= r0q)     ? s[j][1] * 0.125f : -1e30f;
                s[j][2] = (col     <= r0q + 8) ? s[j][2] * 0.125f : -1e30f;
                s[j][3] = (col + 1 <= r0q + 8) ? s[j][3] * 0.125f : -1e30f;
                mx0 = fmaxf(mx0, fmaxf(s[j][0], s[j][1]));
                mx1 = fmaxf(mx1, fmaxf(s[j][2], s[j][3]));
            }
        } else {
#pragma unroll
            for (int j = 0; j < 8; j++) {
                s[j][0] *= 0.125f; s[j][1] *= 0.125f;
                s[j][2] *= 0.125f; s[j][3] *= 0.125f;
                mx0 = fmaxf(mx0, fmaxf(s[j][0], s[j][1]));
                mx1 = fmaxf(mx1, fmaxf(s[j][2], s[j][3]));
            }
        }
        mx0 = fmaxf(mx0, __shfl_xor_sync(0xffffffffu, mx0, 1));
        mx0 = fmaxf(mx0, __shfl_xor_sync(0xffffffffu, mx0, 2));
        mx1 = fmaxf(mx1, __shfl_xor_sync(0xffffffffu, mx1, 1));
        mx1 = fmaxf(mx1, __shfl_xor_sync(0xffffffffu, mx1, 2));

        const float mn0 = fmaxf(m0, mx0);
        const float mn1 = fmaxf(m1, mx1);
        const float sc0 = __expf(m0 - mn0);
        const float sc1 = __expf(m1 - mn1);
        m0 = mn0; m1 = mn1;
        l0 *= sc0; l1 *= sc1;
#pragma unroll
        for (int j = 0; j < 8; j++) {
            o[j][0] *= sc0; o[j][1] *= sc0;
            o[j][2] *= sc1; o[j][3] *= sc1;
        }

        unsigned pa[8], pb[8];
#pragma unroll
        for (int j = 0; j < 8; j++) {
            const float p0 = __expf(s[j][0] - mn0);
            const float p1 = __expf(s[j][1] - mn0);
            const float p2 = __expf(s[j][2] - mn1);
            const float p3 = __expf(s[j][3] - mn1);
            l0 += p0 + p1; l1 += p2 + p3;
            pa[j] = h2_as_u32(__floats2half2_rn(p0, p1));
            pb[j] = h2_as_u32(__floats2half2_rn(p2, p3));
        }

#pragma unroll
        for (int kc = 0; kc < 4; kc++) {
#pragma unroll
            for (int jp = 0; jp < 4; jp++) {
                const int row = 16 * kc + vrow;
                const int u = 2 * jp + (g8 >> 1);
                unsigned t0, t1, t2, t3;
                LDSM4T(t0, t1, t2, t3,
                       vb + (uint32_t)(row * 8 + (u ^ (row & 7))) * 16);
                MMA16816(o[2 * jp],     pa[2 * kc], pb[2 * kc], pa[2 * kc + 1], pb[2 * kc + 1], t0, t1);
                MMA16816(o[2 * jp + 1], pa[2 * kc], pb[2 * kc], pa[2 * kc + 1], pb[2 * kc + 1], t2, t3);
            }
        }
    }

    l0 += __shfl_xor_sync(0xffffffffu, l0, 1);
    l0 += __shfl_xor_sync(0xffffffffu, l0, 2);
    l1 += __shfl_xor_sync(0xffffffffu, l1, 1);
    l1 += __shfl_xor_sync(0xffffffffu, l1, 2);
    const float inv0 = 1.f / l0;
    const float inv1 = 1.f / l1;

    const size_t obase = ((size_t)((n * HH + h) * TT + q0 + 16 * warp)) * DHD;
#pragma unroll
    for (int j = 0; j < 8; j++) {
        const int col = 8 * j + 2 * tq;
        *(unsigned*)(O + obase + (size_t)g * DHD + col) =
            h2_as_u32(__floats2half2_rn(o[j][0] * inv0, o[j][1] * inv0));
        *(unsigned*)(O + obase + (size_t)(g + 8) * DHD + col) =
            h2_as_u32(__floats2half2_rn(o[j][2] * inv1, o[j][3] * inv1));
    }
}

// ---------------- residual + LayerNorm (fp16 delta, dual write) ----------
__global__ void ln_kernel(const float* __restrict__ X, const __half* __restrict__ Dd,
                          const float* __restrict__ g, const float* __restrict__ b,
                          float* __restrict__ out, __half* __restrict__ outh)
{
    const int r = blockIdx.x;
    const int tid = threadIdx.x;
    const float* xr = X + (size_t)r * DD;
    const __half* dr = Dd + (size_t)r * DD;
    const int d = tid * 4;
    float4 xv = *(const float4*)(xr + d);
    uint2 du = *(const uint2*)(dr + d);
    float2 d0 = __half22float2(*(__half2*)&du.x);
    float2 d1 = __half22float2(*(__half2*)&du.y);
    float v0 = xv.x + d0.x, v1 = xv.y + d0.y, v2 = xv.z + d1.x, v3 = xv.w + d1.y;

    __shared__ float s1[256], s2[256];
    s1[tid] = v0 + v1 + v2 + v3;
    s2[tid] = v0 * v0 + v1 * v1 + v2 * v2 + v3 * v3;
    __syncthreads();
    for (int st = 128; st > 0; st >>= 1) {
        if (tid < st) { s1[tid] += s1[tid + st]; s2[tid] += s2[tid + st]; }
        __syncthreads();
    }
    const float mean = s1[0] * (1.f / DD);
    const float var = s2[0] * (1.f / DD) - mean * mean;
    const float rstd = rsqrtf(var + 1e-5f);

    float4 ov;
    ov.x = g[d + 0] * (v0 - mean) * rstd + b[d + 0];
    ov.y = g[d + 1] * (v1 - mean) * rstd + b[d + 1];
    ov.z = g[d + 2] * (v2 - mean) * rstd + b[d + 2];
    ov.w = g[d + 3] * (v3 - mean) * rstd + b[d + 3];
    *(float4*)(out + (size_t)r * DD + d) = ov;
    uint2 hv;
    hv.x = h2_as_u32(__floats2half2_rn(ov.x, ov.y));
    hv.y = h2_as_u32(__floats2half2_rn(ov.z, ov.w));
    *(uint2*)(outh + (size_t)r * DD + d) = hv;
}

// ---- fused: LN(x + attn_delta) then LN(o1 + z_broadcast) ----------------
__global__ void ln_fused2(const float* __restrict__ X, const __half* __restrict__ Dd,
                          const float* __restrict__ g1, const float* __restrict__ b1,
                          const float* __restrict__ Z,
                          const float* __restrict__ g2, const float* __restrict__ b2,
                          float* __restrict__ out, __half* __restrict__ outh)
{
    const int r = blockIdx.x;
    const int tid = threadIdx.x;
    const int d = tid * 4;
    __shared__ float s1[256], s2[256];

    float4 xv = *(const float4*)(X + (size_t)r * DD + d);
    uint2 du = *(const uint2*)(Dd + (size_t)r * DD + d);
    float2 d0 = __half22float2(*(__half2*)&du.x);
    float2 d1 = __half22float2(*(__half2*)&du.y);
    float v0 = xv.x + d0.x, v1 = xv.y + d0.y, v2 = xv.z + d1.x, v3 = xv.w + d1.y;

    s1[tid] = v0 + v1 + v2 + v3;
    s2[tid] = v0 * v0 + v1 * v1 + v2 * v2 + v3 * v3;
    __syncthreads();
    for (int st = 128; st > 0; st >>= 1) {
        if (tid < st) { s1[tid] += s1[tid + st]; s2[tid] += s2[tid + st]; }
        __syncthreads();
    }
    float mean = s1[0] * (1.f / DD);
    float var = s2[0] * (1.f / DD) - mean * mean;
    float rstd = rsqrtf(var + 1e-5f);

    // o1 = LN1(v)
    float o0 = g1[d + 0] * (v0 - mean) * rstd + b1[d + 0];
    float o1_ = g1[d + 1] * (v1 - mean) * rstd + b1[d + 1];
    float o2_ = g1[d + 2] * (v2 - mean) * rstd + b1[d + 2];
    float o3 = g1[d + 3] * (v3 - mean) * rstd + b1[d + 3];

    // add broadcast cross-attn z
    const int n = r >> 9;
    const int s = r & (TT - 1);
    const size_t zr = (size_t)(n * 16 + (s >> 5));
    float4 zv = *(const float4*)(Z + zr * DD + d);
    v0 = o0 + zv.x; v1 = o1_ + zv.y; v2 = o2_ + zv.z; v3 = o3 + zv.w;

    __syncthreads();   // protect s1/s2 reuse
    s1[tid] = v0 + v1 + v2 + v3;
    s2[tid] = v0 * v0 + v1 * v1 + v2 * v2 + v3 * v3;
    __syncthreads();
    for (int st = 128; st > 0; st >>= 1) {
        if (tid < st) { s1[tid] += s1[tid + st]; s2[tid] += s2[tid + st]; }
        __syncthreads();
    }
    mean = s1[0] * (1.f / DD);
    var = s2[0] * (1.f / DD) - mean * mean;
    rstd = rsqrtf(var + 1e-5f);

    float4 ov;
    ov.x = g2[d + 0] * (v0 - mean) * rstd + b2[d + 0];
    ov.y = g2[d + 1] * (v1 - mean) * rstd + b2[d + 1];
    ov.z = g2[d + 2] * (v2 - mean) * rstd + b2[d + 2];
    ov.w = g2[d + 3] * (v3 - mean) * rstd + b2[d + 3];
    *(float4*)(out + (size_t)r * DD + d) = ov;
    uint2 hv;
    hv.x = h2_as_u32(__floats2half2_rn(ov.x, ov.y));
    hv.y = h2_as_u32(__floats2half2_rn(ov.z, ov.w));
    *(uint2*)(outh + (size_t)r * DD + d) = hv;
}

// ------------- tiled rows for cross-attn out-projection (batched) --------
__global__ void tilefe_kernel(const float* __restrict__ fev, float* __restrict__ A)
{
    const int bx = blockIdx.x;
    const int z = bx >> 8;
    const int rl = bx & 255;
    const int n = rl >> 4;
    const int g = rl & 15;
    const int d = threadIdx.x * 4;
    const float* src = fev + (size_t)z * NB * DD + (size_t)n * DD + g * 64;
    float4 v = *(const float4*)(src + (d & 63));
    *(float4*)(A + (size_t)z * NB * 16 * DD + (size_t)rl * DD + d) = v;
}

// ---------------- launch --------------------------------------------------
extern "C" void kernel_launch(void* const* d_in, const int* in_sizes, int n_in,
                              void* d_out, int out_size)
{
    const float* features = (const float*)d_in[0];
    const int*   captions = (const int*)d_in[1];
    const float* feat_W   = (const float*)d_in[2];
    const float* feat_b   = (const float*)d_in[3];
    const float* cap_emb  = (const float*)d_in[4];
    const float* pos_emb  = (const float*)d_in[5];
    const float* sa_Wq = (const float*)d_in[6];
    const float* sa_Wk = (const float*)d_in[7];
    const float* sa_Wv = (const float*)d_in[8];
    const float* sa_Wo = (const float*)d_in[9];
    const float* sa_bo = (const float*)d_in[10];
    const float* sa_g  = (const float*)d_in[11];
    const float* sa_b  = (const float*)d_in[12];
    const float* ca_Wv = (const float*)d_in[15];
    const float* ca_Wo = (const float*)d_in[16];
    const float* ca_bo = (const float*)d_in[17];
    const float* ca_g  = (const float*)d_in[18];
    const float* ca_b  = (const float*)d_in[19];
    const float* ff_W1 = (const float*)d_in[20];
    const float* ff_b1 = (const float*)d_in[21];
    const float* ff_W2 = (const float*)d_in[22];
    const float* ff_b2 = (const float*)d_in[23];
    const float* ff_g  = (const float*)d_in[24];
    const float* ff_b  = (const float*)d_in[25];
    const float* score_W = (const float*)d_in[26];
    const float* score_b = (const float*)d_in[27];
    float* out = (float*)d_out;

    float *px, *pfe, *pfev, *pzt, *pz;
    __half *pxh, *pqkvh, *pattnh, *pth, *phh;
    __half *pwqkvh, *pwoh, *pw1h, *pw2h, *pwsh;
    cudaGetSymbolAddress((void**)&px,    g_x);
    cudaGetSymbolAddress((void**)&pfe,   g_fe);
    cudaGetSymbolAddress((void**)&pfev,  g_fev);
    cudaGetSymbolAddress((void**)&pzt,   g_ztile);
    cudaGetSymbolAddress((void**)&pz,    g_z);
    cudaGetSymbolAddress((void**)&pxh,    g_xh);
    cudaGetSymbolAddress((void**)&pqkvh,  g_qkvh);
    cudaGetSymbolAddress((void**)&pattnh, g_attnh);
    cudaGetSymbolAddress((void**)&pth,    g_th);
    cudaGetSymbolAddress((void**)&phh,    g_hh);
    cudaGetSymbolAddress((void**)&pwqkvh, g_wqkvh);
    cudaGetSymbolAddress((void**)&pwoh,   g_woh);
    cudaGetSymbolAddress((void**)&pw1h,   g_w1h);
    cudaGetSymbolAddress((void**)&pw2h,   g_w2h);
    cudaGetSymbolAddress((void**)&pwsh,   g_wsh);

    const int tb = 256;
    const int nDD = LL * DD * DD;
    const int nFF = LL * DD * FFD;
    const int nS = DD * VV;

    const dim3 gP(DD / 128, ROWS / 128);        // 8 x 64
    const dim3 gQKV(QKVLD / 128, ROWS / 128);   // 24 x 64
    const dim3 gF(FFD / 128, ROWS / 128);       // 16 x 64

    // weight conversions
    f2h3_kernel<<<dim3(nDD / 4 / tb, 3), tb>>>(sa_Wq, sa_Wk, sa_Wv, pwqkvh);
    f2h_kernel<<<(nDD / 4 + tb - 1) / tb, tb>>>(sa_Wo, pwoh, nDD);
    f2h_kernel<<<(nFF / 4 + tb - 1) / tb, tb>>>(ff_W1, pw1h, nFF);
    f2h_kernel<<<(nFF / 4 + tb - 1) / tb, tb>>>(ff_W2, pw2h, nFF);
    f2h_kernel<<<(nS / 4 + tb - 1) / tb, tb>>>(score_W, pwsh, nS);

    // features -> fe  (M=16, SIMT path)
    sgemm<false, true><<<dim3(DD / BN, 1), 256>>>(features, feat_W, feat_b, pfe, NB, DD, DIN);

    // embedding (f32 + f16)
    embed_kernel<<<ROWS, 256>>>(captions, cap_emb, pos_emb, px, pxh);

    // cross-attention contributions for all layers (f32 SIMT path)
    sgemm_bz<false><<<dim3(DD / BN, 1, LL), 256>>>(pfe, ca_Wv, nullptr, pfev,
                                                   NB, DD, DD,
                                                   0, (size_t)DD * DD, 0, (size_t)NB * DD);
    tilefe_kernel<<<LL * NB * 16, 256>>>(pfev, pzt);
    sgemm_bz<true><<<dim3(DD / BN, 2, LL), 256>>>(pzt, ca_Wo, ca_bo, pz,
                                                  NB * 16, DD, DD,
                                                  (size_t)NB * 16 * DD, (size_t)DD * DD,
                                                  DD, (size_t)NB * 16 * DD);

    for (int i = 0; i < LL; i++) {
        // packed QKV projection: [8192,1024] @ [1024,3072]
        hgemm<false, false, true><<<gQKV, 128>>>(pxh, pwqkvh + (size_t)i * DD * QKVLD,
                                                 nullptr, pqkvh, ROWS, QKVLD, DD);
        flash_attn2<<<NB * HH * 8, 128>>>(pqkvh, pqkvh + DD, pqkvh + 2 * DD, pattnh);
        hgemm<false, true, true><<<gP, 128>>>(pattnh, pwoh + (size_t)i * DD * DD,
                                              sa_bo + (size_t)i * DD, pth, ROWS, DD, DD);
        ln_fused2<<<ROWS, 256>>>(px, pth, sa_g + (size_t)i * DD, sa_b + (size_t)i * DD,
                                 pz + (size_t)i * NB * 16 * DD,
                                 ca_g + (size_t)i * DD, ca_b + (size_t)i * DD, px, pxh);

        hgemm<true, true, true><<<gF, 128>>>(pxh, pw1h + (size_t)i * DD * FFD,
                                             ff_b1 + (size_t)i * FFD, phh, ROWS, FFD, DD);
        hgemm<false, true, true><<<gP, 128>>>(phh, pw2h + (size_t)i * FFD * DD,
                                              ff_b2 + (size_t)i * DD, pth, ROWS, DD, FFD);
        ln_kernel<<<ROWS, 256>>>(px, pth, ff_g + (size_t)i * DD, ff_b + (size_t)i * DD, px, pxh);
    }

    // final vocab projection
    hgemm<false, true, false><<<dim3((VV + 127) / 128, ROWS / 128), 128>>>(
        pxh, pwsh, score_b, out, ROWS, VV, DD);
}